// round 2
// baseline (speedup 1.0000x reference)
#include <cuda_runtime.h>
#include <cstdint>
#include <cstddef>

#define SEQ 2048
#define DMODEL 2048
#define NH 32
#define DH 64

// Scratch (device globals: allocation-free rule)
__device__ float g_q[SEQ * DMODEL];
__device__ float g_k[SEQ * DMODEL];
__device__ float g_v[SEQ * DMODEL];
__device__ float g_attn[SEQ * DMODEL];
__device__ int g_mask_mode;  // 0=uint8, 1=int32, 2=float32

// ---------------------------------------------------------------------------
// Detect how the boolean mask was serialized. Deterministic function of input.
//   uint8 bool:  bytes in {0,1}, non-word-aligned bytes frequently 1
//   int32:       bytes at (i&3)!=0 are all 0, aligned bytes in {0,1}
//   float32:     1.0f has bytes {0,0,0x80,0x3F} -> max byte > 1
// ---------------------------------------------------------------------------
__global__ void detect_mask_kernel(const unsigned char* __restrict__ m) {
    if (threadIdx.x == 0) {
        int mx = 0, off = 0;
        for (int i = 0; i < 256; i++) {
            int b = m[i];
            if (b > mx) mx = b;
            if ((i & 3) && b) off = 1;
        }
        g_mask_mode = (mx > 1) ? 2 : (off ? 0 : 1);
    }
}

// ---------------------------------------------------------------------------
// C[M,N] = A[M,K] @ B[N,K]^T + bias[N]   (both operands K-contiguous, "NT")
// 128x128 block, 8x8 per thread, BK=16, smem stored transposed with pad 132.
// ---------------------------------------------------------------------------
#define BM 128
#define BN 128
#define BK 16
#define LDP 132

__global__ __launch_bounds__(256) void gemm_nt_bias(
    const float* __restrict__ A, const float* __restrict__ B,
    const float* __restrict__ bias, float* __restrict__ C,
    int M, int N, int K)
{
    __shared__ float As[BK * LDP];
    __shared__ float Bs[BK * LDP];

    const int t  = threadIdx.x;
    const int tx = t & 15;
    const int ty = t >> 4;
    const int bm = blockIdx.y * BM;
    const int bn = blockIdx.x * BN;

    float acc[8][8];
#pragma unroll
    for (int i = 0; i < 8; i++)
#pragma unroll
        for (int j = 0; j < 8; j++) acc[i][j] = 0.0f;

    for (int kt = 0; kt < K; kt += BK) {
#pragma unroll
        for (int l = 0; l < 2; l++) {
            int idx = t + l * 256;          // 0..511
            int row = idx >> 2;             // 0..127
            int c4  = idx & 3;              // 0..3
            float4 va = *(const float4*)&A[(size_t)(bm + row) * K + kt + c4 * 4];
            float4 vb = *(const float4*)&B[(size_t)(bn + row) * K + kt + c4 * 4];
            As[(c4 * 4 + 0) * LDP + row] = va.x;
            As[(c4 * 4 + 1) * LDP + row] = va.y;
            As[(c4 * 4 + 2) * LDP + row] = va.z;
            As[(c4 * 4 + 3) * LDP + row] = va.w;
            Bs[(c4 * 4 + 0) * LDP + row] = vb.x;
            Bs[(c4 * 4 + 1) * LDP + row] = vb.y;
            Bs[(c4 * 4 + 2) * LDP + row] = vb.z;
            Bs[(c4 * 4 + 3) * LDP + row] = vb.w;
        }
        __syncthreads();

#pragma unroll
        for (int kk = 0; kk < BK; kk++) {
            float4 a0 = *(const float4*)&As[kk * LDP + ty * 8];
            float4 a1 = *(const float4*)&As[kk * LDP + ty * 8 + 4];
            float4 b0 = *(const float4*)&Bs[kk * LDP + tx * 4];
            float4 b1 = *(const float4*)&Bs[kk * LDP + 64 + tx * 4];
            float a[8] = {a0.x, a0.y, a0.z, a0.w, a1.x, a1.y, a1.z, a1.w};
            float b[8] = {b0.x, b0.y, b0.z, b0.w, b1.x, b1.y, b1.z, b1.w};
#pragma unroll
            for (int i = 0; i < 8; i++)
#pragma unroll
                for (int j = 0; j < 8; j++)
                    acc[i][j] = fmaf(a[i], b[j], acc[i][j]);
        }
        __syncthreads();
    }

    float4 bb0 = *(const float4*)&bias[bn + tx * 4];
    float4 bb1 = *(const float4*)&bias[bn + 64 + tx * 4];
#pragma unroll
    for (int i = 0; i < 8; i++) {
        size_t row = (size_t)(bm + ty * 8 + i);
        float4 o0 = make_float4(acc[i][0] + bb0.x, acc[i][1] + bb0.y,
                                acc[i][2] + bb0.z, acc[i][3] + bb0.w);
        float4 o1 = make_float4(acc[i][4] + bb1.x, acc[i][5] + bb1.y,
                                acc[i][6] + bb1.z, acc[i][7] + bb1.w);
        *(float4*)&C[row * N + bn + tx * 4]      = o0;
        *(float4*)&C[row * N + bn + 64 + tx * 4] = o1;
    }
}

// ---------------------------------------------------------------------------
// Flash attention, fp32. Grid: (SEQ/64 q-tiles, NH heads). 256 threads.
// Thread (ty,tx): ty,tx in [0,16). Rows r=ty*4+i, S-cols / O-dims d=tx*4+j.
// smem: Qs[64][64], Ks[64][65] (pad for conflict-free column reads),
//       Vs[64][64], Ps[64][64]  -> 65792 bytes dynamic.
// ---------------------------------------------------------------------------
#define BQ 64
#define BKV 64
#define ATTN_SMEM ((64 * 64 * 3 + 64 * 65) * 4)

__global__ __launch_bounds__(256) void attn_kernel(
    const void* __restrict__ mask_raw, const float* __restrict__ pb)
{
    extern __shared__ float sm[];
    float* Qs = sm;                 // stride 64
    float* Ks = sm + 64 * 64;       // stride 65
    float* Vs = Ks + 64 * 65;       // stride 64
    float* Ps = Vs + 64 * 64;       // stride 64

    const int t  = threadIdx.x;
    const int tx = t & 15;
    const int ty = t >> 4;
    const int qbase = blockIdx.x * BQ;
    const int h     = blockIdx.y;
    const int hoff  = h * DH;
    const int mode  = g_mask_mode;

    const unsigned char* m8 = (const unsigned char*)mask_raw;
    const int*   m32 = (const int*)mask_raw;
    const float* mf  = (const float*)mask_raw;

    // Load Q tile (64 x 64)
#pragma unroll
    for (int l = 0; l < 4; l++) {
        int idx = t + l * 256;
        int r = idx >> 4, c4 = idx & 15;
        *(float4*)&Qs[r * 64 + c4 * 4] =
            *(const float4*)&g_q[(size_t)(qbase + r) * DMODEL + hoff + c4 * 4];
    }

    float m_i[4], l_i[4], O[4][4];
#pragma unroll
    for (int i = 0; i < 4; i++) {
        m_i[i] = -1e30f; l_i[i] = 0.0f;
#pragma unroll
        for (int j = 0; j < 4; j++) O[i][j] = 0.0f;
    }

    for (int kt = 0; kt < SEQ; kt += BKV) {
        __syncthreads();  // previous iteration done with Ks/Vs/Ps
#pragma unroll
        for (int l = 0; l < 4; l++) {
            int idx = t + l * 256;
            int r = idx >> 4, c4 = idx & 15;
            float4 kv = *(const float4*)&g_k[(size_t)(kt + r) * DMODEL + hoff + c4 * 4];
            Ks[r * 65 + c4 * 4 + 0] = kv.x;
            Ks[r * 65 + c4 * 4 + 1] = kv.y;
            Ks[r * 65 + c4 * 4 + 2] = kv.z;
            Ks[r * 65 + c4 * 4 + 3] = kv.w;
            *(float4*)&Vs[r * 64 + c4 * 4] =
                *(const float4*)&g_v[(size_t)(kt + r) * DMODEL + hoff + c4 * 4];
        }
        __syncthreads();

        // S = Q K^T
        float s[4][4];
#pragma unroll
        for (int i = 0; i < 4; i++)
#pragma unroll
            for (int j = 0; j < 4; j++) s[i][j] = 0.0f;

#pragma unroll
        for (int kk4 = 0; kk4 < 16; kk4++) {
            float4 q[4];
#pragma unroll
            for (int i = 0; i < 4; i++)
                q[i] = *(const float4*)&Qs[(ty * 4 + i) * 64 + kk4 * 4];
#pragma unroll
            for (int j = 0; j < 4; j++) {
                float k0 = Ks[(tx * 4 + j) * 65 + kk4 * 4 + 0];
                float k1 = Ks[(tx * 4 + j) * 65 + kk4 * 4 + 1];
                float k2 = Ks[(tx * 4 + j) * 65 + kk4 * 4 + 2];
                float k3 = Ks[(tx * 4 + j) * 65 + kk4 * 4 + 3];
#pragma unroll
                for (int i = 0; i < 4; i++) {
                    s[i][j] = fmaf(q[i].x, k0, s[i][j]);
                    s[i][j] = fmaf(q[i].y, k1, s[i][j]);
                    s[i][j] = fmaf(q[i].z, k2, s[i][j]);
                    s[i][j] = fmaf(q[i].w, k3, s[i][j]);
                }
            }
        }

        // scale + bias + mask, then online softmax update
#pragma unroll
        for (int i = 0; i < 4; i++) {
            int qg = qbase + ty * 4 + i;
            size_t boff = ((size_t)h * SEQ + qg) * SEQ + kt + tx * 4;
            float4 bv = *(const float4*)&pb[boff];
            size_t moff = (size_t)qg * SEQ + kt + tx * 4;
            int ok0, ok1, ok2, ok3;
            if (mode == 0) {
                uchar4 mv = *(const uchar4*)&m8[moff];
                ok0 = mv.x; ok1 = mv.y; ok2 = mv.z; ok3 = mv.w;
            } else if (mode == 1) {
                int4 mv = *(const int4*)&m32[moff];
                ok0 = mv.x; ok1 = mv.y; ok2 = mv.z; ok3 = mv.w;
            } else {
                float4 mv = *(const float4*)&mf[moff];
                ok0 = mv.x != 0.0f; ok1 = mv.y != 0.0f;
                ok2 = mv.z != 0.0f; ok3 = mv.w != 0.0f;
            }
            s[i][0] = ok0 ? fmaf(s[i][0], 0.125f, bv.x) : -1e30f;
            s[i][1] = ok1 ? fmaf(s[i][1], 0.125f, bv.y) : -1e30f;
            s[i][2] = ok2 ? fmaf(s[i][2], 0.125f, bv.z) : -1e30f;
            s[i][3] = ok3 ? fmaf(s[i][3], 0.125f, bv.w) : -1e30f;

            float mx = fmaxf(fmaxf(s[i][0], s[i][1]), fmaxf(s[i][2], s[i][3]));
#pragma unroll
            for (int o = 1; o < 16; o <<= 1)
                mx = fmaxf(mx, __shfl_xor_sync(0xffffffffu, mx, o));
            float mnew = fmaxf(m_i[i], mx);
            float corr = __expf(m_i[i] - mnew);
            float rsum = 0.0f;
#pragma unroll
            for (int j = 0; j < 4; j++) {
                float p = (s[i][j] > -1e29f) ? __expf(s[i][j] - mnew) : 0.0f;
                s[i][j] = p;
                rsum += p;
            }
#pragma unroll
            for (int o = 1; o < 16; o <<= 1)
                rsum += __shfl_xor_sync(0xffffffffu, rsum, o);
            l_i[i] = l_i[i] * corr + rsum;
            m_i[i] = mnew;
#pragma unroll
            for (int j = 0; j < 4; j++) O[i][j] *= corr;
            *(float4*)&Ps[(ty * 4 + i) * 64 + tx * 4] =
                make_float4(s[i][0], s[i][1], s[i][2], s[i][3]);
        }
        __syncthreads();

        // O += P @ V
#pragma unroll 8
        for (int kk = 0; kk < BKV; kk++) {
            float4 v = *(const float4*)&Vs[kk * 64 + tx * 4];
#pragma unroll
            for (int i = 0; i < 4; i++) {
                float p = Ps[(ty * 4 + i) * 64 + kk];
                O[i][0] = fmaf(p, v.x, O[i][0]);
                O[i][1] = fmaf(p, v.y, O[i][1]);
                O[i][2] = fmaf(p, v.z, O[i][2]);
                O[i][3] = fmaf(p, v.w, O[i][3]);
            }
        }
    }

#pragma unroll
    for (int i = 0; i < 4; i++) {
        float inv = 1.0f / l_i[i];
        size_t r = (size_t)(qbase + ty * 4 + i);
        float4 o = make_float4(O[i][0] * inv, O[i][1] * inv,
                               O[i][2] * inv, O[i][3] * inv);
        *(float4*)&g_attn[r * DMODEL + hoff + tx * 4] = o;
    }
}

// ---------------------------------------------------------------------------
extern "C" void kernel_launch(void* const* d_in, const int* in_sizes, int n_in,
                              void* d_out, int out_size)
{
    const float* hq   = (const float*)d_in[0];
    const float* hkv  = (const float*)d_in[1];
    const void*  mask = d_in[2];
    const float* pb   = (const float*)d_in[3];
    const float* wq   = (const float*)d_in[4];
    const float* bq   = (const float*)d_in[5];
    const float* wk   = (const float*)d_in[6];
    const float* bk   = (const float*)d_in[7];
    const float* wv   = (const float*)d_in[8];
    const float* bv   = (const float*)d_in[9];
    const float* wo   = (const float*)d_in[10];
    const float* bo   = (const float*)d_in[11];
    float* out = (float*)d_out;

    float *qp = nullptr, *kp = nullptr, *vp = nullptr, *ap = nullptr;
    cudaGetSymbolAddress((void**)&qp, g_q);
    cudaGetSymbolAddress((void**)&kp, g_k);
    cudaGetSymbolAddress((void**)&vp, g_v);
    cudaGetSymbolAddress((void**)&ap, g_attn);

    detect_mask_kernel<<<1, 32>>>((const unsigned char*)mask);

    dim3 gg(DMODEL / BN, SEQ / BM);
    gemm_nt_bias<<<gg, 256>>>(hq,  wq, bq, qp, SEQ, DMODEL, DMODEL);
    gemm_nt_bias<<<gg, 256>>>(hkv, wk, bk, kp, SEQ, DMODEL, DMODEL);
    gemm_nt_bias<<<gg, 256>>>(hkv, wv, bv, vp, SEQ, DMODEL, DMODEL);

    // Idempotent; errors ignored (attr persists from the correctness run).
    cudaFuncSetAttribute(attn_kernel,
                         cudaFuncAttributeMaxDynamicSharedMemorySize, ATTN_SMEM);
    attn_kernel<<<dim3(SEQ / BQ, NH), 256, ATTN_SMEM>>>(mask, pb);

    gemm_nt_bias<<<gg, 256>>>(ap, wo, bo, out, SEQ, DMODEL, DMODEL);
}

// round 5
// speedup vs baseline: 1.4726x; 1.4726x over previous
#include <cuda_runtime.h>
#include <cuda_bf16.h>
#include <cstdint>
#include <cstddef>

#define SEQ 2048
#define DMODEL 2048
#define NH 32
#define DH 64

// ---------------------------------------------------------------------------
// Scratch (device globals: allocation-free rule)
// ---------------------------------------------------------------------------
__device__ float g_q[SEQ * DMODEL];
__device__ float g_k[SEQ * DMODEL];
__device__ float g_v[SEQ * DMODEL];
__device__ float g_attn[SEQ * DMODEL];
__device__ __nv_bfloat16 g_xh[SEQ * DMODEL];   // activation hi
__device__ __nv_bfloat16 g_xl[SEQ * DMODEL];   // activation lo
__device__ __nv_bfloat16 g_wh[SEQ * DMODEL];   // weight hi
__device__ __nv_bfloat16 g_wl[SEQ * DMODEL];   // weight lo
__device__ int g_mask_mode;  // 0=uint8, 1=int32, 2=float32

// ---------------------------------------------------------------------------
// Mask dtype detection (deterministic function of input bytes)
// ---------------------------------------------------------------------------
__global__ void detect_mask_kernel(const unsigned char* __restrict__ m) {
    if (threadIdx.x == 0) {
        int mx = 0, off = 0;
        for (int i = 0; i < 256; i++) {
            int b = m[i];
            if (b > mx) mx = b;
            if ((i & 3) && b) off = 1;
        }
        g_mask_mode = (mx > 1) ? 2 : (off ? 0 : 1);
    }
}

// ---------------------------------------------------------------------------
// fp32 -> bf16 hi/lo split.  hi = rn(x), lo = rn(x - hi).
// ---------------------------------------------------------------------------
__global__ __launch_bounds__(256) void split_bf16(
    const float* __restrict__ x,
    __nv_bfloat16* __restrict__ hi, __nv_bfloat16* __restrict__ lo)
{
    size_t base = ((size_t)blockIdx.x * 256 + threadIdx.x) * 8;
    float4 a = *(const float4*)(x + base);
    float4 b = *(const float4*)(x + base + 4);
    float v[8] = {a.x, a.y, a.z, a.w, b.x, b.y, b.z, b.w};
    __nv_bfloat162 h2[4], l2[4];
#pragma unroll
    for (int i = 0; i < 4; i++) {
        __nv_bfloat16 h0 = __float2bfloat16_rn(v[2 * i]);
        __nv_bfloat16 h1 = __float2bfloat16_rn(v[2 * i + 1]);
        __nv_bfloat16 l0 = __float2bfloat16_rn(v[2 * i] - __bfloat162float(h0));
        __nv_bfloat16 l1 = __float2bfloat16_rn(v[2 * i + 1] - __bfloat162float(h1));
        h2[i] = __nv_bfloat162(h0, h1);
        l2[i] = __nv_bfloat162(l0, l1);
    }
    *(uint4*)(hi + base) = *(uint4*)h2;
    *(uint4*)(lo + base) = *(uint4*)l2;
}

// ---------------------------------------------------------------------------
// mma.sync helpers (portable sm_80+ path; tcgen05 is unavailable because the
// harness PTX targets sm_103 without the 'a' feature suffix)
// ---------------------------------------------------------------------------
__device__ __forceinline__ uint32_t smem_u32(const void* p) {
    uint32_t a;
    asm("{ .reg .u64 t; cvta.to.shared.u64 t, %1; cvt.u32.u64 %0, t; }"
        : "=r"(a) : "l"(p));
    return a;
}

// Byte offset inside one [128 rows][32 bf16] tile (8 KB). Row = 64 B = 4
// chunks of 16 B. Swizzle: chunk ^= (row>>1)&3  -> cp.async stores and
// ldmatrix reads are conflict-free per 8-lane phase.
__device__ __forceinline__ uint32_t sw_off(int r, int c) {
    return (uint32_t)(r * 64 + ((c ^ ((r >> 1) & 3)) * 16));
}

__device__ __forceinline__ void ldsm4(uint32_t addr, uint32_t* r) {
    asm volatile("ldmatrix.sync.aligned.m8n8.x4.shared.b16 {%0,%1,%2,%3}, [%4];"
        : "=r"(r[0]), "=r"(r[1]), "=r"(r[2]), "=r"(r[3]) : "r"(addr));
}

__device__ __forceinline__ void mma16816(float* d, const uint32_t* a,
                                         uint32_t b0, uint32_t b1) {
    asm volatile(
        "mma.sync.aligned.m16n8k16.row.col.f32.bf16.bf16.f32 "
        "{%0,%1,%2,%3}, {%4,%5,%6,%7}, {%8,%9}, {%0,%1,%2,%3};"
        : "+f"(d[0]), "+f"(d[1]), "+f"(d[2]), "+f"(d[3])
        : "r"(a[0]), "r"(a[1]), "r"(a[2]), "r"(a[3]), "r"(b0), "r"(b1));
}

// ---------------------------------------------------------------------------
// HMMA GEMM:  C[M,N] = (Ah+Al)[M,K] @ (Bh+Bl)[N,K]^T + bias[N]
// 128x128 tile/CTA, BK=32, double-buffered cp.async, 3-pass bf16 split.
// smem/stage: Ah|Al|Bh|Bl 8KB each = 32KB; 2 stages = 64KB.
// ---------------------------------------------------------------------------
#define GEMM_SMEM 65536

__global__ __launch_bounds__(256, 2) void gemm_mma(
    const __nv_bfloat16* __restrict__ Ah, const __nv_bfloat16* __restrict__ Al,
    const __nv_bfloat16* __restrict__ Bh, const __nv_bfloat16* __restrict__ Bl,
    const float* __restrict__ bias, float* __restrict__ C)
{
    extern __shared__ __align__(1024) char sm[];
    const int t    = threadIdx.x;
    const int bm   = blockIdx.y * 128;
    const int bn   = blockIdx.x * 128;
    const int lane = t & 31;
    const int w    = t >> 5;
    const int wm   = (w & 1) * 64;     // warp M offset (2 warps in M)
    const int wn   = (w >> 1) * 32;    // warp N offset (4 warps in N)
    const int lr   = lane & 15;        // ldmatrix row-within-16
    const int kc   = lane >> 4;        // ldmatrix k-chunk select
    const uint32_t smb = smem_u32(sm);

    float d[4][4][4];
#pragma unroll
    for (int i = 0; i < 4; i++)
#pragma unroll
        for (int j = 0; j < 4; j++)
#pragma unroll
            for (int r = 0; r < 4; r++) d[i][j][r] = 0.0f;

    // gmem->smem: each thread cp.asyncs chunks t and t+256 of each array.
    const int r0 = t >> 2, c0 = t & 3;
    const int r1 = (t + 256) >> 2;     // (t+256)&3 == c0

    const __nv_bfloat16* srcs[4] = {Ah, Al, Bh, Bl};

    auto issue_stage = [&](int st, int kt) {
#pragma unroll
        for (int arr = 0; arr < 4; arr++) {
            const __nv_bfloat16* s = srcs[arr];
            const int rb = (arr < 2) ? bm : bn;
            uint32_t s0 = smb + st * 32768 + arr * 8192 + sw_off(r0, c0);
            uint32_t s1 = smb + st * 32768 + arr * 8192 + sw_off(r1, c0);
            const void* g0 = s + (size_t)(rb + r0) * DMODEL + kt * 32 + c0 * 8;
            const void* g1 = s + (size_t)(rb + r1) * DMODEL + kt * 32 + c0 * 8;
            asm volatile("cp.async.cg.shared.global [%0], [%1], 16;"
                         :: "r"(s0), "l"(g0));
            asm volatile("cp.async.cg.shared.global [%0], [%1], 16;"
                         :: "r"(s1), "l"(g1));
        }
        asm volatile("cp.async.commit_group;");
    };

    issue_stage(0, 0);

#pragma unroll 1
    for (int kt = 0; kt < 64; kt++) {
        if (kt < 63) {
            issue_stage((kt + 1) & 1, kt + 1);
            asm volatile("cp.async.wait_group 1;");
        } else {
            asm volatile("cp.async.wait_group 0;");
        }
        __syncthreads();

        const uint32_t sb = smb + (kt & 1) * 32768;
#pragma unroll
        for (int kk = 0; kk < 2; kk++) {
            const int c = kk * 2 + kc;
            uint32_t af[4][4], bf[2][4];

            // pass 1: Ah * Bh
#pragma unroll
            for (int i = 0; i < 4; i++)
                ldsm4(sb + 0 * 8192 + sw_off(wm + i * 16 + lr, c), af[i]);
#pragma unroll
            for (int p = 0; p < 2; p++)
                ldsm4(sb + 2 * 8192 + sw_off(wn + p * 16 + lr, c), bf[p]);
#pragma unroll
            for (int i = 0; i < 4; i++)
#pragma unroll
                for (int j = 0; j < 4; j++)
                    mma16816(d[i][j], af[i], bf[j >> 1][j & 1], bf[j >> 1][(j & 1) + 2]);

            // pass 2: Al * Bh  (Bh frags still live)
#pragma unroll
            for (int i = 0; i < 4; i++)
                ldsm4(sb + 1 * 8192 + sw_off(wm + i * 16 + lr, c), af[i]);
#pragma unroll
            for (int i = 0; i < 4; i++)
#pragma unroll
                for (int j = 0; j < 4; j++)
                    mma16816(d[i][j], af[i], bf[j >> 1][j & 1], bf[j >> 1][(j & 1) + 2]);

            // pass 3: Ah * Bl
#pragma unroll
            for (int i = 0; i < 4; i++)
                ldsm4(sb + 0 * 8192 + sw_off(wm + i * 16 + lr, c), af[i]);
#pragma unroll
            for (int p = 0; p < 2; p++)
                ldsm4(sb + 3 * 8192 + sw_off(wn + p * 16 + lr, c), bf[p]);
#pragma unroll
            for (int i = 0; i < 4; i++)
#pragma unroll
                for (int j = 0; j < 4; j++)
                    mma16816(d[i][j], af[i], bf[j >> 1][j & 1], bf[j >> 1][(j & 1) + 2]);
        }
        __syncthreads();
    }

    // Epilogue: c-frag mapping (group = lane>>2 -> row, (lane&3)*2 -> col)
    const int tg = lane >> 2, t4 = lane & 3;
#pragma unroll
    for (int i = 0; i < 4; i++) {
        const int row = bm + wm + i * 16 + tg;
#pragma unroll
        for (int j = 0; j < 4; j++) {
            const int col = bn + wn + j * 8 + t4 * 2;
            const float b0 = bias[col], b1 = bias[col + 1];
            *(float2*)&C[(size_t)row * DMODEL + col] =
                make_float2(d[i][j][0] + b0, d[i][j][1] + b1);
            *(float2*)&C[(size_t)(row + 8) * DMODEL + col] =
                make_float2(d[i][j][2] + b0, d[i][j][3] + b1);
        }
    }
}

// ---------------------------------------------------------------------------
// Flash attention, fp32 (round-5 target; unchanged).
// ---------------------------------------------------------------------------
#define BQ 64
#define BKV 64
#define ATTN_SMEM ((64 * 64 * 3 + 64 * 65) * 4)

__global__ __launch_bounds__(256) void attn_kernel(
    const void* __restrict__ mask_raw, const float* __restrict__ pb)
{
    extern __shared__ float smf[];
    float* Qs = smf;
    float* Ks = smf + 64 * 64;
    float* Vs = Ks + 64 * 65;
    float* Ps = Vs + 64 * 64;

    const int t  = threadIdx.x;
    const int tx = t & 15;
    const int ty = t >> 4;
    const int qbase = blockIdx.x * BQ;
    const int h     = blockIdx.y;
    const int hoff  = h * DH;
    const int mode  = g_mask_mode;

    const unsigned char* m8 = (const unsigned char*)mask_raw;
    const int*   m32 = (const int*)mask_raw;
    const float* mf  = (const float*)mask_raw;

#pragma unroll
    for (int l = 0; l < 4; l++) {
        int idx = t + l * 256;
        int r = idx >> 4, c4 = idx & 15;
        *(float4*)&Qs[r * 64 + c4 * 4] =
            *(const float4*)&g_q[(size_t)(qbase + r) * DMODEL + hoff + c4 * 4];
    }

    float m_i[4], l_i[4], O[4][4];
#pragma unroll
    for (int i = 0; i < 4; i++) {
        m_i[i] = -1e30f; l_i[i] = 0.0f;
#pragma unroll
        for (int j = 0; j < 4; j++) O[i][j] = 0.0f;
    }

    for (int kt = 0; kt < SEQ; kt += BKV) {
        __syncthreads();
#pragma unroll
        for (int l = 0; l < 4; l++) {
            int idx = t + l * 256;
            int r = idx >> 4, c4 = idx & 15;
            float4 kv = *(const float4*)&g_k[(size_t)(kt + r) * DMODEL + hoff + c4 * 4];
            Ks[r * 65 + c4 * 4 + 0] = kv.x;
            Ks[r * 65 + c4 * 4 + 1] = kv.y;
            Ks[r * 65 + c4 * 4 + 2] = kv.z;
            Ks[r * 65 + c4 * 4 + 3] = kv.w;
            *(float4*)&Vs[r * 64 + c4 * 4] =
                *(const float4*)&g_v[(size_t)(kt + r) * DMODEL + hoff + c4 * 4];
        }
        __syncthreads();

        float s[4][4];
#pragma unroll
        for (int i = 0; i < 4; i++)
#pragma unroll
            for (int j = 0; j < 4; j++) s[i][j] = 0.0f;

#pragma unroll
        for (int kk4 = 0; kk4 < 16; kk4++) {
            float4 q[4];
#pragma unroll
            for (int i = 0; i < 4; i++)
                q[i] = *(const float4*)&Qs[(ty * 4 + i) * 64 + kk4 * 4];
#pragma unroll
            for (int j = 0; j < 4; j++) {
                float k0 = Ks[(tx * 4 + j) * 65 + kk4 * 4 + 0];
                float k1 = Ks[(tx * 4 + j) * 65 + kk4 * 4 + 1];
                float k2 = Ks[(tx * 4 + j) * 65 + kk4 * 4 + 2];
                float k3 = Ks[(tx * 4 + j) * 65 + kk4 * 4 + 3];
#pragma unroll
                for (int i = 0; i < 4; i++) {
                    s[i][j] = fmaf(q[i].x, k0, s[i][j]);
                    s[i][j] = fmaf(q[i].y, k1, s[i][j]);
                    s[i][j] = fmaf(q[i].z, k2, s[i][j]);
                    s[i][j] = fmaf(q[i].w, k3, s[i][j]);
                }
            }
        }

#pragma unroll
        for (int i = 0; i < 4; i++) {
            int qg = qbase + ty * 4 + i;
            size_t boff = ((size_t)h * SEQ + qg) * SEQ + kt + tx * 4;
            float4 bv = *(const float4*)&pb[boff];
            size_t moff = (size_t)qg * SEQ + kt + tx * 4;
            int ok0, ok1, ok2, ok3;
            if (mode == 0) {
                uchar4 mv = *(const uchar4*)&m8[moff];
                ok0 = mv.x; ok1 = mv.y; ok2 = mv.z; ok3 = mv.w;
            } else if (mode == 1) {
                int4 mv = *(const int4*)&m32[moff];
                ok0 = mv.x; ok1 = mv.y; ok2 = mv.z; ok3 = mv.w;
            } else {
                float4 mv = *(const float4*)&mf[moff];
                ok0 = mv.x != 0.0f; ok1 = mv.y != 0.0f;
                ok2 = mv.z != 0.0f; ok3 = mv.w != 0.0f;
            }
            s[i][0] = ok0 ? fmaf(s[i][0], 0.125f, bv.x) : -1e30f;
            s[i][1] = ok1 ? fmaf(s[i][1], 0.125f, bv.y) : -1e30f;
            s[i][2] = ok2 ? fmaf(s[i][2], 0.125f, bv.z) : -1e30f;
            s[i][3] = ok3 ? fmaf(s[i][3], 0.125f, bv.w) : -1e30f;

            float mx = fmaxf(fmaxf(s[i][0], s[i][1]), fmaxf(s[i][2], s[i][3]));
#pragma unroll
            for (int o = 1; o < 16; o <<= 1)
                mx = fmaxf(mx, __shfl_xor_sync(0xffffffffu, mx, o));
            float mnew = fmaxf(m_i[i], mx);
            float corr = __expf(m_i[i] - mnew);
            float rsum = 0.0f;
#pragma unroll
            for (int j = 0; j < 4; j++) {
                float p = (s[i][j] > -1e29f) ? __expf(s[i][j] - mnew) : 0.0f;
                s[i][j] = p;
                rsum += p;
            }
#pragma unroll
            for (int o = 1; o < 16; o <<= 1)
                rsum += __shfl_xor_sync(0xffffffffu, rsum, o);
            l_i[i] = l_i[i] * corr + rsum;
            m_i[i] = mnew;
#pragma unroll
            for (int j = 0; j < 4; j++) O[i][j] *= corr;
            *(float4*)&Ps[(ty * 4 + i) * 64 + tx * 4] =
                make_float4(s[i][0], s[i][1], s[i][2], s[i][3]);
        }
        __syncthreads();

#pragma unroll 8
        for (int kk = 0; kk < BKV; kk++) {
            float4 v = *(const float4*)&Vs[kk * 64 + tx * 4];
#pragma unroll
            for (int i = 0; i < 4; i++) {
                float p = Ps[(ty * 4 + i) * 64 + kk];
                O[i][0] = fmaf(p, v.x, O[i][0]);
                O[i][1] = fmaf(p, v.y, O[i][1]);
                O[i][2] = fmaf(p, v.z, O[i][2]);
                O[i][3] = fmaf(p, v.w, O[i][3]);
            }
        }
    }

#pragma unroll
    for (int i = 0; i < 4; i++) {
        float inv = 1.0f / l_i[i];
        size_t r = (size_t)(qbase + ty * 4 + i);
        float4 o = make_float4(O[i][0] * inv, O[i][1] * inv,
                               O[i][2] * inv, O[i][3] * inv);
        *(float4*)&g_attn[r * DMODEL + hoff + tx * 4] = o;
    }
}

// ---------------------------------------------------------------------------
extern "C" void kernel_launch(void* const* d_in, const int* in_sizes, int n_in,
                              void* d_out, int out_size)
{
    const float* hq   = (const float*)d_in[0];
    const float* hkv  = (const float*)d_in[1];
    const void*  mask = d_in[2];
    const float* pb   = (const float*)d_in[3];
    const float* wq   = (const float*)d_in[4];
    const float* bq   = (const float*)d_in[5];
    const float* wk   = (const float*)d_in[6];
    const float* bk   = (const float*)d_in[7];
    const float* wv   = (const float*)d_in[8];
    const float* bv   = (const float*)d_in[9];
    const float* wo   = (const float*)d_in[10];
    const float* bo   = (const float*)d_in[11];
    float* out = (float*)d_out;

    float *qp = nullptr, *kp = nullptr, *vp = nullptr, *ap = nullptr;
    __nv_bfloat16 *xh, *xl, *wh, *wl;
    cudaGetSymbolAddress((void**)&qp, g_q);
    cudaGetSymbolAddress((void**)&kp, g_k);
    cudaGetSymbolAddress((void**)&vp, g_v);
    cudaGetSymbolAddress((void**)&ap, g_attn);
    cudaGetSymbolAddress((void**)&xh, g_xh);
    cudaGetSymbolAddress((void**)&xl, g_xl);
    cudaGetSymbolAddress((void**)&wh, g_wh);
    cudaGetSymbolAddress((void**)&wl, g_wl);

    cudaFuncSetAttribute(gemm_mma,
                         cudaFuncAttributeMaxDynamicSharedMemorySize, GEMM_SMEM);
    cudaFuncSetAttribute(attn_kernel,
                         cudaFuncAttributeMaxDynamicSharedMemorySize, ATTN_SMEM);

    detect_mask_kernel<<<1, 32>>>((const unsigned char*)mask);

    dim3 gg(DMODEL / 128, SEQ / 128);

    // Q = hq @ wq^T + bq
    split_bf16<<<2048, 256>>>(hq, xh, xl);
    split_bf16<<<2048, 256>>>(wq, wh, wl);
    gemm_mma<<<gg, 256, GEMM_SMEM>>>(xh, xl, wh, wl, bq, qp);

    // K = hkv @ wk^T + bk ; V = hkv @ wv^T + bv
    split_bf16<<<2048, 256>>>(hkv, xh, xl);
    split_bf16<<<2048, 256>>>(wk, wh, wl);
    gemm_mma<<<gg, 256, GEMM_SMEM>>>(xh, xl, wh, wl, bk, kp);
    split_bf16<<<2048, 256>>>(wv, wh, wl);
    gemm_mma<<<gg, 256, GEMM_SMEM>>>(xh, xl, wh, wl, bv, vp);

    // attention (fp32)
    attn_kernel<<<dim3(SEQ / BQ, NH), 256, ATTN_SMEM>>>(mask, pb);

    // out = attn @ wo^T + bo
    split_bf16<<<2048, 256>>>(ap, xh, xl);
    split_bf16<<<2048, 256>>>(wo, wh, wl);
    gemm_mma<<<gg, 256, GEMM_SMEM>>>(xh, xl, wh, wl, bo, out);
}

// round 6
// speedup vs baseline: 2.2143x; 1.5037x over previous
#include <cuda_runtime.h>
#include <cuda_bf16.h>
#include <cstdint>
#include <cstddef>

#define SEQ 2048
#define DMODEL 2048
#define NH 32
#define DH 64

// ---------------------------------------------------------------------------
// Scratch (device globals: allocation-free rule)
// ---------------------------------------------------------------------------
__device__ __nv_bfloat16 g_xh[SEQ * DMODEL];   // gemm activation hi
__device__ __nv_bfloat16 g_xl[SEQ * DMODEL];   // gemm activation lo
__device__ __nv_bfloat16 g_wh[SEQ * DMODEL];   // gemm weight hi
__device__ __nv_bfloat16 g_wl[SEQ * DMODEL];   // gemm weight lo
__device__ __nv_bfloat16 g_qh[SEQ * DMODEL];   // Q (pre-scaled by 0.125) hi/lo
__device__ __nv_bfloat16 g_ql[SEQ * DMODEL];
__device__ __nv_bfloat16 g_kh[SEQ * DMODEL];
__device__ __nv_bfloat16 g_kl[SEQ * DMODEL];
__device__ __nv_bfloat16 g_vh[SEQ * DMODEL];
__device__ __nv_bfloat16 g_vl[SEQ * DMODEL];
__device__ __nv_bfloat16 g_ah[SEQ * DMODEL];   // attention output hi/lo
__device__ __nv_bfloat16 g_al[SEQ * DMODEL];
__device__ int g_mask_mode;  // 0=uint8, 1=int32, 2=float32

// ---------------------------------------------------------------------------
// Mask dtype detection (deterministic function of input bytes)
// ---------------------------------------------------------------------------
__global__ void detect_mask_kernel(const unsigned char* __restrict__ m) {
    if (threadIdx.x == 0) {
        int mx = 0, off = 0;
        for (int i = 0; i < 256; i++) {
            int b = m[i];
            if (b > mx) mx = b;
            if ((i & 3) && b) off = 1;
        }
        g_mask_mode = (mx > 1) ? 2 : (off ? 0 : 1);
    }
}

// ---------------------------------------------------------------------------
// fp32 -> bf16 hi/lo split.
// ---------------------------------------------------------------------------
__global__ __launch_bounds__(256) void split_bf16(
    const float* __restrict__ x,
    __nv_bfloat16* __restrict__ hi, __nv_bfloat16* __restrict__ lo)
{
    size_t base = ((size_t)blockIdx.x * 256 + threadIdx.x) * 8;
    float4 a = *(const float4*)(x + base);
    float4 b = *(const float4*)(x + base + 4);
    float v[8] = {a.x, a.y, a.z, a.w, b.x, b.y, b.z, b.w};
    __nv_bfloat162 h2[4], l2[4];
#pragma unroll
    for (int i = 0; i < 4; i++) {
        __nv_bfloat16 h0 = __float2bfloat16_rn(v[2 * i]);
        __nv_bfloat16 h1 = __float2bfloat16_rn(v[2 * i + 1]);
        __nv_bfloat16 l0 = __float2bfloat16_rn(v[2 * i] - __bfloat162float(h0));
        __nv_bfloat16 l1 = __float2bfloat16_rn(v[2 * i + 1] - __bfloat162float(h1));
        h2[i] = __nv_bfloat162(h0, h1);
        l2[i] = __nv_bfloat162(l0, l1);
    }
    *(uint4*)(hi + base) = *(uint4*)h2;
    *(uint4*)(lo + base) = *(uint4*)l2;
}

// ---------------------------------------------------------------------------
// mma.sync helpers
// ---------------------------------------------------------------------------
__device__ __forceinline__ uint32_t smem_u32(const void* p) {
    uint32_t a;
    asm("{ .reg .u64 t; cvta.to.shared.u64 t, %1; cvt.u32.u64 %0, t; }"
        : "=r"(a) : "l"(p));
    return a;
}

__device__ __forceinline__ void ldsm4(uint32_t addr, uint32_t* r) {
    asm volatile("ldmatrix.sync.aligned.m8n8.x4.shared.b16 {%0,%1,%2,%3}, [%4];"
        : "=r"(r[0]), "=r"(r[1]), "=r"(r[2]), "=r"(r[3]) : "r"(addr));
}
__device__ __forceinline__ void ldsm4t(uint32_t addr, uint32_t* r) {
    asm volatile("ldmatrix.sync.aligned.m8n8.x4.trans.shared.b16 {%0,%1,%2,%3}, [%4];"
        : "=r"(r[0]), "=r"(r[1]), "=r"(r[2]), "=r"(r[3]) : "r"(addr));
}
__device__ __forceinline__ void mma16816(float* d, const uint32_t* a,
                                         uint32_t b0, uint32_t b1) {
    asm volatile(
        "mma.sync.aligned.m16n8k16.row.col.f32.bf16.bf16.f32 "
        "{%0,%1,%2,%3}, {%4,%5,%6,%7}, {%8,%9}, {%0,%1,%2,%3};"
        : "+f"(d[0]), "+f"(d[1]), "+f"(d[2]), "+f"(d[3])
        : "r"(a[0]), "r"(a[1]), "r"(a[2]), "r"(a[3]), "r"(b0), "r"(b1));
}
__device__ __forceinline__ void cpa16(uint32_t s, const void* g) {
    asm volatile("cp.async.cg.shared.global [%0], [%1], 16;" :: "r"(s), "l"(g));
}
__device__ __forceinline__ uint32_t pack_bf16(float a, float b) {
    __nv_bfloat162 h = __floats2bfloat162_rn(a, b);
    return *(uint32_t*)&h;
}

// 32-col bf16 tile (64B rows): swizzle for gemm
__device__ __forceinline__ uint32_t sw_off(int r, int c) {
    return (uint32_t)(r * 64 + ((c ^ ((r >> 1) & 3)) * 16));
}
// 64-col bf16 tile (128B rows): swizzle for attention
__device__ __forceinline__ uint32_t sw64(int r, int c) {
    return (uint32_t)(r * 128 + ((c ^ (r & 7)) * 16));
}

// ---------------------------------------------------------------------------
// HMMA GEMM:  C = (Ah+Al)[M,K] @ (Bh+Bl)[N,K]^T + bias, then *scale.
// Output either fp32 (Cf) or bf16 hi/lo pair (Ch, Cl).
// ---------------------------------------------------------------------------
#define GEMM_SMEM 65536

__global__ __launch_bounds__(256, 2) void gemm_mma(
    const __nv_bfloat16* __restrict__ Ah, const __nv_bfloat16* __restrict__ Al,
    const __nv_bfloat16* __restrict__ Bh, const __nv_bfloat16* __restrict__ Bl,
    const float* __restrict__ bias, float* __restrict__ Cf,
    __nv_bfloat16* __restrict__ Ch, __nv_bfloat16* __restrict__ Cl,
    float scale)
{
    extern __shared__ __align__(1024) char sm[];
    const int t    = threadIdx.x;
    const int bm   = blockIdx.y * 128;
    const int bn   = blockIdx.x * 128;
    const int lane = t & 31;
    const int w    = t >> 5;
    const int wm   = (w & 1) * 64;
    const int wn   = (w >> 1) * 32;
    const int lr   = lane & 15;
    const int kc   = lane >> 4;
    const uint32_t smb = smem_u32(sm);

    float d[4][4][4];
#pragma unroll
    for (int i = 0; i < 4; i++)
#pragma unroll
        for (int j = 0; j < 4; j++)
#pragma unroll
            for (int r = 0; r < 4; r++) d[i][j][r] = 0.0f;

    const int r0 = t >> 2, c0 = t & 3;
    const int r1 = (t + 256) >> 2;
    const __nv_bfloat16* srcs[4] = {Ah, Al, Bh, Bl};

    auto issue_stage = [&](int st, int kt) {
#pragma unroll
        for (int arr = 0; arr < 4; arr++) {
            const __nv_bfloat16* s = srcs[arr];
            const int rb = (arr < 2) ? bm : bn;
            cpa16(smb + st * 32768 + arr * 8192 + sw_off(r0, c0),
                  s + (size_t)(rb + r0) * DMODEL + kt * 32 + c0 * 8);
            cpa16(smb + st * 32768 + arr * 8192 + sw_off(r1, c0),
                  s + (size_t)(rb + r1) * DMODEL + kt * 32 + c0 * 8);
        }
        asm volatile("cp.async.commit_group;");
    };

    issue_stage(0, 0);

#pragma unroll 1
    for (int kt = 0; kt < 64; kt++) {
        if (kt < 63) {
            issue_stage((kt + 1) & 1, kt + 1);
            asm volatile("cp.async.wait_group 1;");
        } else {
            asm volatile("cp.async.wait_group 0;");
        }
        __syncthreads();

        const uint32_t sb = smb + (kt & 1) * 32768;
#pragma unroll
        for (int kk = 0; kk < 2; kk++) {
            const int c = kk * 2 + kc;
            uint32_t af[4][4], bf[2][4];
#pragma unroll
            for (int i = 0; i < 4; i++)
                ldsm4(sb + 0 * 8192 + sw_off(wm + i * 16 + lr, c), af[i]);
#pragma unroll
            for (int p = 0; p < 2; p++)
                ldsm4(sb + 2 * 8192 + sw_off(wn + p * 16 + lr, c), bf[p]);
#pragma unroll
            for (int i = 0; i < 4; i++)
#pragma unroll
                for (int j = 0; j < 4; j++)
                    mma16816(d[i][j], af[i], bf[j >> 1][j & 1], bf[j >> 1][(j & 1) + 2]);
#pragma unroll
            for (int i = 0; i < 4; i++)
                ldsm4(sb + 1 * 8192 + sw_off(wm + i * 16 + lr, c), af[i]);
#pragma unroll
            for (int i = 0; i < 4; i++)
#pragma unroll
                for (int j = 0; j < 4; j++)
                    mma16816(d[i][j], af[i], bf[j >> 1][j & 1], bf[j >> 1][(j & 1) + 2]);
#pragma unroll
            for (int i = 0; i < 4; i++)
                ldsm4(sb + 0 * 8192 + sw_off(wm + i * 16 + lr, c), af[i]);
#pragma unroll
            for (int p = 0; p < 2; p++)
                ldsm4(sb + 3 * 8192 + sw_off(wn + p * 16 + lr, c), bf[p]);
#pragma unroll
            for (int i = 0; i < 4; i++)
#pragma unroll
                for (int j = 0; j < 4; j++)
                    mma16816(d[i][j], af[i], bf[j >> 1][j & 1], bf[j >> 1][(j & 1) + 2]);
        }
        __syncthreads();
    }

    const int tg = lane >> 2, t4 = lane & 3;
#pragma unroll
    for (int i = 0; i < 4; i++) {
        const int row = bm + wm + i * 16 + tg;
#pragma unroll
        for (int j = 0; j < 4; j++) {
            const int col = bn + wn + j * 8 + t4 * 2;
            const float b0 = bias[col], b1 = bias[col + 1];
            float v0 = (d[i][j][0] + b0) * scale, v1 = (d[i][j][1] + b1) * scale;
            float v2 = (d[i][j][2] + b0) * scale, v3 = (d[i][j][3] + b1) * scale;
            if (Cf) {
                *(float2*)&Cf[(size_t)row * DMODEL + col] = make_float2(v0, v1);
                *(float2*)&Cf[(size_t)(row + 8) * DMODEL + col] = make_float2(v2, v3);
            } else {
                uint32_t h0 = pack_bf16(v0, v1), h1 = pack_bf16(v2, v3);
                __nv_bfloat162 hh0 = *(__nv_bfloat162*)&h0;
                __nv_bfloat162 hh1 = *(__nv_bfloat162*)&h1;
                uint32_t l0 = pack_bf16(v0 - __bfloat162float(hh0.x),
                                        v1 - __bfloat162float(hh0.y));
                uint32_t l1 = pack_bf16(v2 - __bfloat162float(hh1.x),
                                        v3 - __bfloat162float(hh1.y));
                *(uint32_t*)&Ch[(size_t)row * DMODEL + col] = h0;
                *(uint32_t*)&Ch[(size_t)(row + 8) * DMODEL + col] = h1;
                *(uint32_t*)&Cl[(size_t)row * DMODEL + col] = l0;
                *(uint32_t*)&Cl[(size_t)(row + 8) * DMODEL + col] = l1;
            }
        }
    }
}

// ---------------------------------------------------------------------------
// Tensor-core flash attention.
// Grid (SEQ/64, NH), 128 threads (4 warps x 16 q-rows).
// Q pre-scaled by 0.125.  3-pass bf16-split QK^T and PV.
// smem: Qh|Ql 16KB  +  2 stages x (Kh|Kl|Vh|Vl 32KB) = 80KB.
// ---------------------------------------------------------------------------
#define ATTN_SMEM (16384 + 2 * 32768)

__global__ __launch_bounds__(128, 2) void attn_mma(
    const __nv_bfloat16* __restrict__ Qh, const __nv_bfloat16* __restrict__ Ql,
    const __nv_bfloat16* __restrict__ Kh, const __nv_bfloat16* __restrict__ Kl,
    const __nv_bfloat16* __restrict__ Vh, const __nv_bfloat16* __restrict__ Vl,
    const void* __restrict__ mask_raw, const float* __restrict__ pb,
    __nv_bfloat16* __restrict__ Oh, __nv_bfloat16* __restrict__ Ol)
{
    extern __shared__ __align__(1024) char sm[];
    const int t = threadIdx.x, lane = t & 31, w = t >> 5;
    const int lr = lane & 15, kc = lane >> 4;
    const int group = lane >> 2, t4 = lane & 3;
    const int qbase = blockIdx.x * 64;
    const int h = blockIdx.y;
    const int mode = g_mask_mode;
    const uint32_t smb = smem_u32(sm);

    const unsigned char* m8 = (const unsigned char*)mask_raw;
    const int*   m32 = (const int*)mask_raw;
    const float* mf  = (const float*)mask_raw;

    // Q prologue (rows qbase+r, cols h*64 + ...)
    {
        const __nv_bfloat16* qs[2] = {Qh, Ql};
#pragma unroll
        for (int arr = 0; arr < 2; arr++)
#pragma unroll
            for (int i = 0; i < 4; i++) {
                int idx = t + i * 128;
                int r = idx >> 3, c = idx & 7;
                cpa16(smb + arr * 8192 + sw64(r, c),
                      qs[arr] + (size_t)(qbase + r) * DMODEL + h * DH + c * 8);
            }
    }
    const __nv_bfloat16* kvs[4] = {Kh, Kl, Vh, Vl};
    auto issue_kv = [&](int st, int tile) {
#pragma unroll
        for (int arr = 0; arr < 4; arr++)
#pragma unroll
            for (int i = 0; i < 4; i++) {
                int idx = t + i * 128;
                int r = idx >> 3, c = idx & 7;
                cpa16(smb + 16384 + st * 32768 + arr * 8192 + sw64(r, c),
                      kvs[arr] + (size_t)(tile * 64 + r) * DMODEL + h * DH + c * 8);
            }
        asm volatile("cp.async.commit_group;");
    };
    issue_kv(0, 0);

    float O[8][4];
    float m_i[2] = {-1e30f, -1e30f}, l_i[2] = {0.0f, 0.0f};
#pragma unroll
    for (int j = 0; j < 8; j++)
#pragma unroll
        for (int r = 0; r < 4; r++) O[j][r] = 0.0f;

#pragma unroll 1
    for (int it = 0; it < 32; it++) {
        if (it < 31) {
            issue_kv((it + 1) & 1, it + 1);
            asm volatile("cp.async.wait_group 1;");
        } else {
            asm volatile("cp.async.wait_group 0;");
        }
        __syncthreads();

        const uint32_t sK = smb + 16384 + (it & 1) * 32768;
        const uint32_t sV = sK + 16384;

        // ---- S = (Q/8) K^T  (3-pass split) ----
        float S[8][4];
#pragma unroll
        for (int j = 0; j < 8; j++)
#pragma unroll
            for (int r = 0; r < 4; r++) S[j][r] = 0.0f;

#pragma unroll
        for (int kk = 0; kk < 4; kk++) {
            const int c = kk * 2 + kc;
            uint32_t qh4[4], ql4[4], khf[4][4], klf[4][4];
            ldsm4(smb + sw64(w * 16 + lr, c), qh4);
            ldsm4(smb + 8192 + sw64(w * 16 + lr, c), ql4);
#pragma unroll
            for (int p = 0; p < 4; p++)
                ldsm4(sK + sw64(p * 16 + lr, c), khf[p]);
#pragma unroll
            for (int p = 0; p < 4; p++)
                ldsm4(sK + 8192 + sw64(p * 16 + lr, c), klf[p]);
#pragma unroll
            for (int j = 0; j < 8; j++)
                mma16816(S[j], qh4, khf[j >> 1][j & 1], khf[j >> 1][(j & 1) + 2]);
#pragma unroll
            for (int j = 0; j < 8; j++)
                mma16816(S[j], ql4, khf[j >> 1][j & 1], khf[j >> 1][(j & 1) + 2]);
#pragma unroll
            for (int j = 0; j < 8; j++)
                mma16816(S[j], qh4, klf[j >> 1][j & 1], klf[j >> 1][(j & 1) + 2]);
        }

        // ---- bias + mask + online softmax (per row-half r2) ----
#pragma unroll
        for (int r2 = 0; r2 < 2; r2++) {
            const int qrow = qbase + w * 16 + group + r2 * 8;
            const size_t prow = ((size_t)h * SEQ + qrow) * SEQ + it * 64;
            const size_t mrow = (size_t)qrow * SEQ + it * 64;
            float mx = -1e30f;
#pragma unroll
            for (int j = 0; j < 8; j++) {
                const int col = j * 8 + t4 * 2;
                float2 bv = *(const float2*)&pb[prow + col];
                int ok0, ok1;
                if (mode == 0) {
                    ok0 = m8[mrow + col]; ok1 = m8[mrow + col + 1];
                } else if (mode == 1) {
                    int2 mv = *(const int2*)&m32[mrow + col];
                    ok0 = mv.x; ok1 = mv.y;
                } else {
                    float2 mv = *(const float2*)&mf[mrow + col];
                    ok0 = mv.x != 0.0f; ok1 = mv.y != 0.0f;
                }
                float s0 = ok0 ? S[j][r2 * 2]     + bv.x : -1e30f;
                float s1 = ok1 ? S[j][r2 * 2 + 1] + bv.y : -1e30f;
                S[j][r2 * 2] = s0; S[j][r2 * 2 + 1] = s1;
                mx = fmaxf(mx, fmaxf(s0, s1));
            }
            mx = fmaxf(mx, __shfl_xor_sync(0xffffffffu, mx, 1));
            mx = fmaxf(mx, __shfl_xor_sync(0xffffffffu, mx, 2));
            float mnew = fmaxf(m_i[r2], mx);
            float corr = __expf(m_i[r2] - mnew);
            float rsum = 0.0f;
#pragma unroll
            for (int j = 0; j < 8; j++) {
#pragma unroll
                for (int e = 0; e < 2; e++) {
                    float s = S[j][r2 * 2 + e];
                    float p = (s > -1e29f) ? __expf(s - mnew) : 0.0f;
                    S[j][r2 * 2 + e] = p;
                    rsum += p;
                }
            }
            rsum += __shfl_xor_sync(0xffffffffu, rsum, 1);
            rsum += __shfl_xor_sync(0xffffffffu, rsum, 2);
            l_i[r2] = l_i[r2] * corr + rsum;
            m_i[r2] = mnew;
#pragma unroll
            for (int j = 0; j < 8; j++) {
                O[j][r2 * 2]     *= corr;
                O[j][r2 * 2 + 1] *= corr;
            }
        }

        // ---- pack P into a-frags (hi/lo) directly from S c-frags ----
        uint32_t aPh[4][4], aPl[4][4];
#pragma unroll
        for (int kk = 0; kk < 4; kk++) {
#pragma unroll
            for (int half = 0; half < 2; half++) {      // klo (j=2kk), khi (2kk+1)
                const int j = 2 * kk + half;
#pragma unroll
                for (int rr = 0; rr < 2; rr++) {        // row, row+8
                    float p0 = S[j][rr * 2], p1 = S[j][rr * 2 + 1];
                    uint32_t hp = pack_bf16(p0, p1);
                    __nv_bfloat162 hb = *(__nv_bfloat162*)&hp;
                    aPh[kk][half * 2 + rr] = hp;
                    aPl[kk][half * 2 + rr] =
                        pack_bf16(p0 - __bfloat162float(hb.x),
                                  p1 - __bfloat162float(hb.y));
                }
            }
        }

        // ---- O += P V  (3-pass split), V via ldmatrix.trans ----
#pragma unroll
        for (int kk = 0; kk < 4; kk++) {
#pragma unroll
            for (int jj = 0; jj < 4; jj++) {
                uint32_t vh4[4], vl4[4];
                ldsm4t(sV + sw64(kk * 16 + lr, 2 * jj + kc), vh4);
                ldsm4t(sV + 8192 + sw64(kk * 16 + lr, 2 * jj + kc), vl4);
                mma16816(O[2 * jj],     aPh[kk], vh4[0], vh4[1]);
                mma16816(O[2 * jj + 1], aPh[kk], vh4[2], vh4[3]);
                mma16816(O[2 * jj],     aPl[kk], vh4[0], vh4[1]);
                mma16816(O[2 * jj + 1], aPl[kk], vh4[2], vh4[3]);
                mma16816(O[2 * jj],     aPh[kk], vl4[0], vl4[1]);
                mma16816(O[2 * jj + 1], aPh[kk], vl4[2], vl4[3]);
            }
        }
        __syncthreads();
    }

    // ---- epilogue: normalize, split to bf16 hi/lo ----
#pragma unroll
    for (int r2 = 0; r2 < 2; r2++) {
        const int qrow = qbase + w * 16 + group + r2 * 8;
        const float inv = 1.0f / l_i[r2];
#pragma unroll
        for (int j = 0; j < 8; j++) {
            const int col = h * DH + j * 8 + t4 * 2;
            float v0 = O[j][r2 * 2] * inv, v1 = O[j][r2 * 2 + 1] * inv;
            uint32_t hp = pack_bf16(v0, v1);
            __nv_bfloat162 hb = *(__nv_bfloat162*)&hp;
            uint32_t lp = pack_bf16(v0 - __bfloat162float(hb.x),
                                    v1 - __bfloat162float(hb.y));
            *(uint32_t*)&Oh[(size_t)qrow * DMODEL + col] = hp;
            *(uint32_t*)&Ol[(size_t)qrow * DMODEL + col] = lp;
        }
    }
}

// ---------------------------------------------------------------------------
extern "C" void kernel_launch(void* const* d_in, const int* in_sizes, int n_in,
                              void* d_out, int out_size)
{
    const float* hq   = (const float*)d_in[0];
    const float* hkv  = (const float*)d_in[1];
    const void*  mask = d_in[2];
    const float* pb   = (const float*)d_in[3];
    const float* wq   = (const float*)d_in[4];
    const float* bq   = (const float*)d_in[5];
    const float* wk   = (const float*)d_in[6];
    const float* bk   = (const float*)d_in[7];
    const float* wv   = (const float*)d_in[8];
    const float* bv   = (const float*)d_in[9];
    const float* wo   = (const float*)d_in[10];
    const float* bo   = (const float*)d_in[11];
    float* out = (float*)d_out;

    __nv_bfloat16 *xh, *xl, *wh, *wl, *qh, *ql, *kh, *kl, *vh, *vl, *ah, *al;
    cudaGetSymbolAddress((void**)&xh, g_xh);
    cudaGetSymbolAddress((void**)&xl, g_xl);
    cudaGetSymbolAddress((void**)&wh, g_wh);
    cudaGetSymbolAddress((void**)&wl, g_wl);
    cudaGetSymbolAddress((void**)&qh, g_qh);
    cudaGetSymbolAddress((void**)&ql, g_ql);
    cudaGetSymbolAddress((void**)&kh, g_kh);
    cudaGetSymbolAddress((void**)&kl, g_kl);
    cudaGetSymbolAddress((void**)&vh, g_vh);
    cudaGetSymbolAddress((void**)&vl, g_vl);
    cudaGetSymbolAddress((void**)&ah, g_ah);
    cudaGetSymbolAddress((void**)&al, g_al);

    cudaFuncSetAttribute(gemm_mma,
                         cudaFuncAttributeMaxDynamicSharedMemorySize, GEMM_SMEM);
    cudaFuncSetAttribute(attn_mma,
                         cudaFuncAttributeMaxDynamicSharedMemorySize, ATTN_SMEM);

    detect_mask_kernel<<<1, 32>>>((const unsigned char*)mask);

    dim3 gg(DMODEL / 128, SEQ / 128);

    // Q = (hq @ wq^T + bq) * 0.125  -> bf16 hi/lo
    split_bf16<<<2048, 256>>>(hq, xh, xl);
    split_bf16<<<2048, 256>>>(wq, wh, wl);
    gemm_mma<<<gg, 256, GEMM_SMEM>>>(xh, xl, wh, wl, bq, nullptr, qh, ql, 0.125f);

    // K, V
    split_bf16<<<2048, 256>>>(hkv, xh, xl);
    split_bf16<<<2048, 256>>>(wk, wh, wl);
    gemm_mma<<<gg, 256, GEMM_SMEM>>>(xh, xl, wh, wl, bk, nullptr, kh, kl, 1.0f);
    split_bf16<<<2048, 256>>>(wv, wh, wl);
    gemm_mma<<<gg, 256, GEMM_SMEM>>>(xh, xl, wh, wl, bv, nullptr, vh, vl, 1.0f);

    // attention (tensor cores) -> bf16 hi/lo
    attn_mma<<<dim3(SEQ / 64, NH), 128, ATTN_SMEM>>>(
        qh, ql, kh, kl, vh, vl, mask, pb, ah, al);

    // out = attn @ wo^T + bo  (fp32)
    split_bf16<<<2048, 256>>>(wo, wh, wl);
    gemm_mma<<<gg, 256, GEMM_SMEM>>>(ah, al, wh, wl, bo, out, nullptr, nullptr, 1.0f);
}

// round 9
// speedup vs baseline: 2.3834x; 1.0763x over previous
#include <cuda_runtime.h>
#include <cuda_bf16.h>
#include <cstdint>
#include <cstddef>

#define SEQ 2048
#define DMODEL 2048
#define NH 32
#define DH 64

// ---------------------------------------------------------------------------
// Scratch (device globals: allocation-free rule)
// ---------------------------------------------------------------------------
__device__ __nv_bfloat16 g_xh[SEQ * DMODEL];
__device__ __nv_bfloat16 g_xl[SEQ * DMODEL];
__device__ __nv_bfloat16 g_wh[SEQ * DMODEL];
__device__ __nv_bfloat16 g_wl[SEQ * DMODEL];
__device__ __nv_bfloat16 g_qh[SEQ * DMODEL];
__device__ __nv_bfloat16 g_ql[SEQ * DMODEL];
__device__ __nv_bfloat16 g_kh[SEQ * DMODEL];
__device__ __nv_bfloat16 g_kl[SEQ * DMODEL];
__device__ __nv_bfloat16 g_vh[SEQ * DMODEL];
__device__ __nv_bfloat16 g_vl[SEQ * DMODEL];
__device__ __nv_bfloat16 g_ah[SEQ * DMODEL];
__device__ __nv_bfloat16 g_al[SEQ * DMODEL];
__device__ int g_mask_mode;  // 0=uint8, 1=int32, 2=float32

// ---------------------------------------------------------------------------
__global__ void detect_mask_kernel(const unsigned char* __restrict__ m) {
    if (threadIdx.x == 0) {
        int mx = 0, off = 0;
        for (int i = 0; i < 256; i++) {
            int b = m[i];
            if (b > mx) mx = b;
            if ((i & 3) && b) off = 1;
        }
        g_mask_mode = (mx > 1) ? 2 : (off ? 0 : 1);
    }
}

// ---------------------------------------------------------------------------
__global__ __launch_bounds__(256) void split_bf16(
    const float* __restrict__ x,
    __nv_bfloat16* __restrict__ hi, __nv_bfloat16* __restrict__ lo)
{
    size_t base = ((size_t)blockIdx.x * 256 + threadIdx.x) * 8;
    float4 a = *(const float4*)(x + base);
    float4 b = *(const float4*)(x + base + 4);
    float v[8] = {a.x, a.y, a.z, a.w, b.x, b.y, b.z, b.w};
    __nv_bfloat162 h2[4], l2[4];
#pragma unroll
    for (int i = 0; i < 4; i++) {
        __nv_bfloat16 h0 = __float2bfloat16_rn(v[2 * i]);
        __nv_bfloat16 h1 = __float2bfloat16_rn(v[2 * i + 1]);
        __nv_bfloat16 l0 = __float2bfloat16_rn(v[2 * i] - __bfloat162float(h0));
        __nv_bfloat16 l1 = __float2bfloat16_rn(v[2 * i + 1] - __bfloat162float(h1));
        h2[i] = __nv_bfloat162(h0, h1);
        l2[i] = __nv_bfloat162(l0, l1);
    }
    *(uint4*)(hi + base) = *(uint4*)h2;
    *(uint4*)(lo + base) = *(uint4*)l2;
}

// ---------------------------------------------------------------------------
__device__ __forceinline__ uint32_t smem_u32(const void* p) {
    uint32_t a;
    asm("{ .reg .u64 t; cvta.to.shared.u64 t, %1; cvt.u32.u64 %0, t; }"
        : "=r"(a) : "l"(p));
    return a;
}
__device__ __forceinline__ void ldsm4(uint32_t addr, uint32_t* r) {
    asm volatile("ldmatrix.sync.aligned.m8n8.x4.shared.b16 {%0,%1,%2,%3}, [%4];"
        : "=r"(r[0]), "=r"(r[1]), "=r"(r[2]), "=r"(r[3]) : "r"(addr));
}
__device__ __forceinline__ void ldsm4t(uint32_t addr, uint32_t* r) {
    asm volatile("ldmatrix.sync.aligned.m8n8.x4.trans.shared.b16 {%0,%1,%2,%3}, [%4];"
        : "=r"(r[0]), "=r"(r[1]), "=r"(r[2]), "=r"(r[3]) : "r"(addr));
}
__device__ __forceinline__ void mma16816(float* d, const uint32_t* a,
                                         uint32_t b0, uint32_t b1) {
    asm volatile(
        "mma.sync.aligned.m16n8k16.row.col.f32.bf16.bf16.f32 "
        "{%0,%1,%2,%3}, {%4,%5,%6,%7}, {%8,%9}, {%0,%1,%2,%3};"
        : "+f"(d[0]), "+f"(d[1]), "+f"(d[2]), "+f"(d[3])
        : "r"(a[0]), "r"(a[1]), "r"(a[2]), "r"(a[3]), "r"(b0), "r"(b1));
}
__device__ __forceinline__ void cpa16(uint32_t s, const void* g) {
    asm volatile("cp.async.cg.shared.global [%0], [%1], 16;" :: "r"(s), "l"(g));
}
__device__ __forceinline__ uint32_t pack_bf16(float a, float b) {
    __nv_bfloat162 h = __floats2bfloat162_rn(a, b);
    return *(uint32_t*)&h;
}

// 32-col bf16 tile (64B rows)
__device__ __forceinline__ uint32_t sw_off(int r, int c) {
    return (uint32_t)(r * 64 + ((c ^ ((r >> 1) & 3)) * 16));
}
// 64-col bf16 tile (128B rows)
__device__ __forceinline__ uint32_t sw64(int r, int c) {
    return (uint32_t)(r * 128 + ((c ^ (r & 7)) * 16));
}

// ---------------------------------------------------------------------------
// HMMA GEMM: C = (Ah+Al)@(Bh+Bl)^T + bias, *scale.  3-stage cp.async,
// precomputed XOR-stepped ldsm addresses, 12 ldsm / k16-chunk.
// Stage layout (32KB): Ah +0 | Al +8192 | Bh +16384 | Bl +24576.
// ---------------------------------------------------------------------------
#define GEMM_SMEM (3 * 32768)

__global__ __launch_bounds__(256, 2) void gemm_mma(
    const __nv_bfloat16* __restrict__ Ah, const __nv_bfloat16* __restrict__ Al,
    const __nv_bfloat16* __restrict__ Bh, const __nv_bfloat16* __restrict__ Bl,
    const float* __restrict__ bias, float* __restrict__ Cf,
    __nv_bfloat16* __restrict__ Ch, __nv_bfloat16* __restrict__ Cl,
    float scale)
{
    extern __shared__ __align__(1024) char sm[];
    const int t    = threadIdx.x;
    const int bm   = blockIdx.y * 128;
    const int bn   = blockIdx.x * 128;
    const int lane = t & 31;
    const int w    = t >> 5;
    const int wm   = (w & 1) * 64;
    const int wn   = (w >> 1) * 32;
    const int lr   = lane & 15;
    const int kc   = lane >> 4;
    const uint32_t smb = smem_u32(sm);

    float d[4][4][4];
#pragma unroll
    for (int i = 0; i < 4; i++)
#pragma unroll
        for (int j = 0; j < 4; j++)
#pragma unroll
            for (int r = 0; r < 4; r++) d[i][j][r] = 0.0f;

    // ---- cp.async setup ----
    const int r0 = t >> 2, c0 = t & 3;
    const int r1 = r0 + 64;
    const __nv_bfloat16* srcs[4] = {Ah, Al, Bh, Bl};
    const __nv_bfloat16* sp[8];
    uint32_t dst[8];
#pragma unroll
    for (int arr = 0; arr < 4; arr++) {
        const int rb = (arr < 2) ? bm : bn;
        sp[2 * arr]     = srcs[arr] + (size_t)(rb + r0) * DMODEL + c0 * 8;
        sp[2 * arr + 1] = srcs[arr] + (size_t)(rb + r1) * DMODEL + c0 * 8;
        dst[2 * arr]     = smb + arr * 8192 + sw_off(r0, c0);
        dst[2 * arr + 1] = smb + arr * 8192 + sw_off(r1, c0);
    }
    auto issue = [&](uint32_t so2, int kt) {
#pragma unroll
        for (int i = 0; i < 8; i++) cpa16(dst[i] + so2, sp[i] + kt * 32);
        asm volatile("cp.async.commit_group;");
    };

    // ---- ldsm base addresses (stage 0, kk=0) ----
    uint32_t aA[4], aB[2];
#pragma unroll
    for (int i = 0; i < 4; i++) aA[i] = smb + sw_off(wm + i * 16 + lr, kc);
#pragma unroll
    for (int p = 0; p < 2; p++) aB[p] = smb + 16384 + sw_off(wn + p * 16 + lr, kc);

    issue(0, 0);
    issue(32768, 1);

    uint32_t so = 0, si = 65536;
#pragma unroll 1
    for (int kt = 0; kt < 64; kt++) {
        if (kt < 63) asm volatile("cp.async.wait_group 1;");
        else         asm volatile("cp.async.wait_group 0;");
        __syncthreads();

#pragma unroll
        for (int kk = 0; kk < 2; kk++) {
            const uint32_t kx = kk * 32;
            uint32_t af[4][4], bh[2][4], bl[2][4];
#pragma unroll
            for (int i = 0; i < 4; i++) ldsm4((aA[i] ^ kx) + so, af[i]);
#pragma unroll
            for (int p = 0; p < 2; p++) ldsm4((aB[p] ^ kx) + so, bh[p]);
#pragma unroll
            for (int p = 0; p < 2; p++) ldsm4((aB[p] ^ kx) + so + 8192, bl[p]);
            // Ah*Bh
#pragma unroll
            for (int i = 0; i < 4; i++)
#pragma unroll
                for (int j = 0; j < 4; j++)
                    mma16816(d[i][j], af[i], bh[j >> 1][j & 1], bh[j >> 1][(j & 1) + 2]);
            // Ah*Bl
#pragma unroll
            for (int i = 0; i < 4; i++)
#pragma unroll
                for (int j = 0; j < 4; j++)
                    mma16816(d[i][j], af[i], bl[j >> 1][j & 1], bl[j >> 1][(j & 1) + 2]);
            // Al*Bh  (Al tile lives at +8192 in the stage)
#pragma unroll
            for (int i = 0; i < 4; i++) ldsm4((aA[i] ^ kx) + so + 8192, af[i]);
#pragma unroll
            for (int i = 0; i < 4; i++)
#pragma unroll
                for (int j = 0; j < 4; j++)
                    mma16816(d[i][j], af[i], bh[j >> 1][j & 1], bh[j >> 1][(j & 1) + 2]);
        }
        __syncthreads();
        if (kt + 2 < 64) issue(si, kt + 2);
        so = (so == 65536) ? 0 : so + 32768;
        si = (si == 65536) ? 0 : si + 32768;
    }

    const int tg = lane >> 2, t4 = lane & 3;
#pragma unroll
    for (int i = 0; i < 4; i++) {
        const int row = bm + wm + i * 16 + tg;
#pragma unroll
        for (int j = 0; j < 4; j++) {
            const int col = bn + wn + j * 8 + t4 * 2;
            const float b0 = bias[col], b1 = bias[col + 1];
            float v0 = (d[i][j][0] + b0) * scale, v1 = (d[i][j][1] + b1) * scale;
            float v2 = (d[i][j][2] + b0) * scale, v3 = (d[i][j][3] + b1) * scale;
            if (Cf) {
                *(float2*)&Cf[(size_t)row * DMODEL + col] = make_float2(v0, v1);
                *(float2*)&Cf[(size_t)(row + 8) * DMODEL + col] = make_float2(v2, v3);
            } else {
                uint32_t h0 = pack_bf16(v0, v1), h1 = pack_bf16(v2, v3);
                __nv_bfloat162 hh0 = *(__nv_bfloat162*)&h0;
                __nv_bfloat162 hh1 = *(__nv_bfloat162*)&h1;
                uint32_t l0 = pack_bf16(v0 - __bfloat162float(hh0.x),
                                        v1 - __bfloat162float(hh0.y));
                uint32_t l1 = pack_bf16(v2 - __bfloat162float(hh1.x),
                                        v3 - __bfloat162float(hh1.y));
                *(uint32_t*)&Ch[(size_t)row * DMODEL + col] = h0;
                *(uint32_t*)&Ch[(size_t)(row + 8) * DMODEL + col] = h1;
                *(uint32_t*)&Cl[(size_t)row * DMODEL + col] = l0;
                *(uint32_t*)&Cl[(size_t)(row + 8) * DMODEL + col] = l1;
            }
        }
    }
}

// ---------------------------------------------------------------------------
// Tensor-core flash attention with pb/mask register prefetch.
// Grid (SEQ/64, NH), 128 threads.  smem: Qh|Ql 16KB + 2 x 32KB KV stages.
// KV stage layout: Kh +0 | Kl +8192 | Vh +16384 | Vl +24576.
// ---------------------------------------------------------------------------
#define ATTN_SMEM (16384 + 2 * 32768)

__global__ __launch_bounds__(128, 2) void attn_mma(
    const __nv_bfloat16* __restrict__ Qh, const __nv_bfloat16* __restrict__ Ql,
    const __nv_bfloat16* __restrict__ Kh, const __nv_bfloat16* __restrict__ Kl,
    const __nv_bfloat16* __restrict__ Vh, const __nv_bfloat16* __restrict__ Vl,
    const void* __restrict__ mask_raw, const float* __restrict__ pb,
    __nv_bfloat16* __restrict__ Oh, __nv_bfloat16* __restrict__ Ol)
{
    extern __shared__ __align__(1024) char sm[];
    const int t = threadIdx.x, lane = t & 31, w = t >> 5;
    const int lr = lane & 15, kc = lane >> 4;
    const int group = lane >> 2, t4 = lane & 3;
    const int qbase = blockIdx.x * 64;
    const int h = blockIdx.y;
    const int mode = g_mask_mode;
    const uint32_t smb = smem_u32(sm);

    const unsigned char* m8 = (const unsigned char*)mask_raw;
    const int*   m32 = (const int*)mask_raw;
    const float* mf  = (const float*)mask_raw;

    // Q prologue
    {
        const __nv_bfloat16* qs[2] = {Qh, Ql};
#pragma unroll
        for (int arr = 0; arr < 2; arr++)
#pragma unroll
            for (int i = 0; i < 4; i++) {
                int idx = t + i * 128;
                int r = idx >> 3, c = idx & 7;
                cpa16(smb + arr * 8192 + sw64(r, c),
                      qs[arr] + (size_t)(qbase + r) * DMODEL + h * DH + c * 8);
            }
    }
    const __nv_bfloat16* kvs[4] = {Kh, Kl, Vh, Vl};
    auto issue_kv = [&](int st, int tile) {
#pragma unroll
        for (int arr = 0; arr < 4; arr++)
#pragma unroll
            for (int i = 0; i < 4; i++) {
                int idx = t + i * 128;
                int r = idx >> 3, c = idx & 7;
                cpa16(smb + 16384 + st * 32768 + arr * 8192 + sw64(r, c),
                      kvs[arr] + (size_t)(tile * 64 + r) * DMODEL + h * DH + c * 8);
            }
        asm volatile("cp.async.commit_group;");
    };
    issue_kv(0, 0);

    // ldsm base addresses (kk=0 / jj=0, stage 0)
    const uint32_t aQ = smb + sw64(w * 16 + lr, kc);
    uint32_t aK[4], aV[4];
#pragma unroll
    for (int p = 0; p < 4; p++) aK[p] = smb + 16384 + sw64(p * 16 + lr, kc);
#pragma unroll
    for (int p = 0; p < 4; p++) aV[p] = smb + 32768 + sw64(p * 16 + lr, kc);

    float O[8][4];
    float m_i[2] = {-1e30f, -1e30f}, l_i[2] = {0.0f, 0.0f};
#pragma unroll
    for (int j = 0; j < 8; j++)
#pragma unroll
        for (int r = 0; r < 4; r++) O[j][r] = 0.0f;

#pragma unroll 1
    for (int it = 0; it < 32; it++) {
        if (it < 31) issue_kv((it + 1) & 1, it + 1);

        // ---- prefetch pb + mask into registers (overlaps S mma) ----
        float2 pbv[2][8];
        int okp[2][8];
#pragma unroll
        for (int r2 = 0; r2 < 2; r2++) {
            const int qrow = qbase + w * 16 + group + r2 * 8;
            const size_t prow = ((size_t)h * SEQ + qrow) * SEQ + it * 64;
            const size_t mrow = (size_t)qrow * SEQ + it * 64;
#pragma unroll
            for (int j = 0; j < 8; j++) {
                const int col = j * 8 + t4 * 2;
                pbv[r2][j] = *(const float2*)&pb[prow + col];
                if (mode == 0) {
                    uchar2 mv = *(const uchar2*)&m8[mrow + col];
                    okp[r2][j] = mv.x | (mv.y << 16);
                } else if (mode == 1) {
                    int2 mv = *(const int2*)&m32[mrow + col];
                    okp[r2][j] = (mv.x ? 1 : 0) | ((mv.y ? 1 : 0) << 16);
                } else {
                    float2 mv = *(const float2*)&mf[mrow + col];
                    okp[r2][j] = (mv.x != 0.0f ? 1 : 0) | ((mv.y != 0.0f ? 1 : 0) << 16);
                }
            }
        }

        if (it < 31) asm volatile("cp.async.wait_group 1;");
        else         asm volatile("cp.async.wait_group 0;");
        __syncthreads();

        const uint32_t so = (it & 1) * 32768;

        // ---- S = (Q/8) K^T  (3-pass split) ----
        float S[8][4];
#pragma unroll
        for (int j = 0; j < 8; j++)
#pragma unroll
            for (int r = 0; r < 4; r++) S[j][r] = 0.0f;

#pragma unroll
        for (int kk = 0; kk < 4; kk++) {
            const uint32_t kx = kk * 32;
            uint32_t qh4[4], ql4[4], khf[4][4], klf[4][4];
            ldsm4((aQ ^ kx), qh4);
            ldsm4((aQ ^ kx) + 8192, ql4);
#pragma unroll
            for (int p = 0; p < 4; p++) ldsm4((aK[p] ^ kx) + so, khf[p]);
#pragma unroll
            for (int p = 0; p < 4; p++) ldsm4((aK[p] ^ kx) + so + 8192, klf[p]);
#pragma unroll
            for (int j = 0; j < 8; j++)
                mma16816(S[j], qh4, khf[j >> 1][j & 1], khf[j >> 1][(j & 1) + 2]);
#pragma unroll
            for (int j = 0; j < 8; j++)
                mma16816(S[j], ql4, khf[j >> 1][j & 1], khf[j >> 1][(j & 1) + 2]);
#pragma unroll
            for (int j = 0; j < 8; j++)
                mma16816(S[j], qh4, klf[j >> 1][j & 1], klf[j >> 1][(j & 1) + 2]);
        }

        // ---- bias + mask + online softmax ----
#pragma unroll
        for (int r2 = 0; r2 < 2; r2++) {
            float mx = -1e30f;
#pragma unroll
            for (int j = 0; j < 8; j++) {
                float s0 = (okp[r2][j] & 0xffff) ? S[j][r2 * 2]     + pbv[r2][j].x : -1e30f;
                float s1 = (okp[r2][j] >> 16)    ? S[j][r2 * 2 + 1] + pbv[r2][j].y : -1e30f;
                S[j][r2 * 2] = s0; S[j][r2 * 2 + 1] = s1;
                mx = fmaxf(mx, fmaxf(s0, s1));
            }
            mx = fmaxf(mx, __shfl_xor_sync(0xffffffffu, mx, 1));
            mx = fmaxf(mx, __shfl_xor_sync(0xffffffffu, mx, 2));
            float mnew = fmaxf(m_i[r2], mx);
            float corr = __expf(m_i[r2] - mnew);
            float rsum = 0.0f;
#pragma unroll
            for (int j = 0; j < 8; j++) {
#pragma unroll
                for (int e = 0; e < 2; e++) {
                    float s = S[j][r2 * 2 + e];
                    float p = (s > -1e29f) ? __expf(s - mnew) : 0.0f;
                    S[j][r2 * 2 + e] = p;
                    rsum += p;
                }
            }
            rsum += __shfl_xor_sync(0xffffffffu, rsum, 1);
            rsum += __shfl_xor_sync(0xffffffffu, rsum, 2);
            l_i[r2] = l_i[r2] * corr + rsum;
            m_i[r2] = mnew;
#pragma unroll
            for (int j = 0; j < 8; j++) {
                O[j][r2 * 2]     *= corr;
                O[j][r2 * 2 + 1] *= corr;
            }
        }

        // ---- pack P into hi/lo a-frags ----
        uint32_t aPh[4][4], aPl[4][4];
#pragma unroll
        for (int kk = 0; kk < 4; kk++) {
#pragma unroll
            for (int half = 0; half < 2; half++) {
                const int j = 2 * kk + half;
#pragma unroll
                for (int rr = 0; rr < 2; rr++) {
                    float p0 = S[j][rr * 2], p1 = S[j][rr * 2 + 1];
                    uint32_t hp = pack_bf16(p0, p1);
                    __nv_bfloat162 hb = *(__nv_bfloat162*)&hp;
                    aPh[kk][half * 2 + rr] = hp;
                    aPl[kk][half * 2 + rr] =
                        pack_bf16(p0 - __bfloat162float(hb.x),
                                  p1 - __bfloat162float(hb.y));
                }
            }
        }

        // ---- O += P V  (3-pass split) ----
#pragma unroll
        for (int kk = 0; kk < 4; kk++) {
#pragma unroll
            for (int jj = 0; jj < 4; jj++) {
                const uint32_t jx = jj * 32;
                uint32_t vh4[4], vl4[4];
                ldsm4t((aV[kk] ^ jx) + so, vh4);
                ldsm4t((aV[kk] ^ jx) + so + 8192, vl4);
                mma16816(O[2 * jj],     aPh[kk], vh4[0], vh4[1]);
                mma16816(O[2 * jj + 1], aPh[kk], vh4[2], vh4[3]);
                mma16816(O[2 * jj],     aPl[kk], vh4[0], vh4[1]);
                mma16816(O[2 * jj + 1], aPl[kk], vh4[2], vh4[3]);
                mma16816(O[2 * jj],     aPh[kk], vl4[0], vl4[1]);
                mma16816(O[2 * jj + 1], aPh[kk], vl4[2], vl4[3]);
            }
        }
        __syncthreads();
    }

    // ---- epilogue ----
#pragma unroll
    for (int r2 = 0; r2 < 2; r2++) {
        const int qrow = qbase + w * 16 + group + r2 * 8;
        const float inv = 1.0f / l_i[r2];
#pragma unroll
        for (int j = 0; j < 8; j++) {
            const int col = h * DH + j * 8 + t4 * 2;
            float v0 = O[j][r2 * 2] * inv, v1 = O[j][r2 * 2 + 1] * inv;
            uint32_t hp = pack_bf16(v0, v1);
            __nv_bfloat162 hb = *(__nv_bfloat162*)&hp;
            uint32_t lp = pack_bf16(v0 - __bfloat162float(hb.x),
                                    v1 - __bfloat162float(hb.y));
            *(uint32_t*)&Oh[(size_t)qrow * DMODEL + col] = hp;
            *(uint32_t*)&Ol[(size_t)qrow * DMODEL + col] = lp;
        }
    }
}

// ---------------------------------------------------------------------------
extern "C" void kernel_launch(void* const* d_in, const int* in_sizes, int n_in,
                              void* d_out, int out_size)
{
    const float* hq   = (const float*)d_in[0];
    const float* hkv  = (const float*)d_in[1];
    const void*  mask = d_in[2];
    const float* pb   = (const float*)d_in[3];
    const float* wq   = (const float*)d_in[4];
    const float* bq   = (const float*)d_in[5];
    const float* wk   = (const float*)d_in[6];
    const float* bk   = (const float*)d_in[7];
    const float* wv   = (const float*)d_in[8];
    const float* bv   = (const float*)d_in[9];
    const float* wo   = (const float*)d_in[10];
    const float* bo   = (const float*)d_in[11];
    float* out = (float*)d_out;

    __nv_bfloat16 *xh, *xl, *wh, *wl, *qh, *ql, *kh, *kl, *vh, *vl, *ah, *al;
    cudaGetSymbolAddress((void**)&xh, g_xh);
    cudaGetSymbolAddress((void**)&xl, g_xl);
    cudaGetSymbolAddress((void**)&wh, g_wh);
    cudaGetSymbolAddress((void**)&wl, g_wl);
    cudaGetSymbolAddress((void**)&qh, g_qh);
    cudaGetSymbolAddress((void**)&ql, g_ql);
    cudaGetSymbolAddress((void**)&kh, g_kh);
    cudaGetSymbolAddress((void**)&kl, g_kl);
    cudaGetSymbolAddress((void**)&vh, g_vh);
    cudaGetSymbolAddress((void**)&vl, g_vl);
    cudaGetSymbolAddress((void**)&ah, g_ah);
    cudaGetSymbolAddress((void**)&al, g_al);

    cudaFuncSetAttribute(gemm_mma,
                         cudaFuncAttributeMaxDynamicSharedMemorySize, GEMM_SMEM);
    cudaFuncSetAttribute(attn_mma,
                         cudaFuncAttributeMaxDynamicSharedMemorySize, ATTN_SMEM);

    detect_mask_kernel<<<1, 32>>>((const unsigned char*)mask);

    dim3 gg(DMODEL / 128, SEQ / 128);

    split_bf16<<<2048, 256>>>(hq, xh, xl);
    split_bf16<<<2048, 256>>>(wq, wh, wl);
    gemm_mma<<<gg, 256, GEMM_SMEM>>>(xh, xl, wh, wl, bq, nullptr, qh, ql, 0.125f);

    split_bf16<<<2048, 256>>>(hkv, xh, xl);
    split_bf16<<<2048, 256>>>(wk, wh, wl);
    gemm_mma<<<gg, 256, GEMM_SMEM>>>(xh, xl, wh, wl, bk, nullptr, kh, kl, 1.0f);
    split_bf16<<<2048, 256>>>(wv, wh, wl);
    gemm_mma<<<gg, 256, GEMM_SMEM>>>(xh, xl, wh, wl, bv, nullptr, vh, vl, 1.0f);

    attn_mma<<<dim3(SEQ / 64, NH), 128, ATTN_SMEM>>>(
        qh, ql, kh, kl, vh, vl, mask, pb, ah, al);

    split_bf16<<<2048, 256>>>(wo, wh, wl);
    gemm_mma<<<gg, 256, GEMM_SMEM>>>(ah, al, wh, wl, bo, out, nullptr, nullptr, 1.0f);
}

// round 10
// speedup vs baseline: 2.4169x; 1.0141x over previous
#include <cuda_runtime.h>
#include <cuda_bf16.h>
#include <cstdint>
#include <cstddef>

#define SEQ 2048
#define DMODEL 2048
#define NH 32
#define DH 64

// ---------------------------------------------------------------------------
// Scratch (device globals: allocation-free rule)
// ---------------------------------------------------------------------------
__device__ __nv_bfloat16 g_xh[SEQ * DMODEL];
__device__ __nv_bfloat16 g_xl[SEQ * DMODEL];
__device__ __nv_bfloat16 g_wh[SEQ * DMODEL];
__device__ __nv_bfloat16 g_wl[SEQ * DMODEL];
__device__ __nv_bfloat16 g_qh[SEQ * DMODEL];
__device__ __nv_bfloat16 g_ql[SEQ * DMODEL];
__device__ __nv_bfloat16 g_kh[SEQ * DMODEL];
__device__ __nv_bfloat16 g_kl[SEQ * DMODEL];
__device__ __nv_bfloat16 g_vh[SEQ * DMODEL];
__device__ __nv_bfloat16 g_vl[SEQ * DMODEL];
__device__ __nv_bfloat16 g_ah[SEQ * DMODEL];
__device__ __nv_bfloat16 g_al[SEQ * DMODEL];
__device__ int g_mask_mode;  // 0=uint8, 1=int32, 2=float32

// ---------------------------------------------------------------------------
__global__ void detect_mask_kernel(const unsigned char* __restrict__ m) {
    if (threadIdx.x == 0) {
        int mx = 0, off = 0;
        for (int i = 0; i < 256; i++) {
            int b = m[i];
            if (b > mx) mx = b;
            if ((i & 3) && b) off = 1;
        }
        g_mask_mode = (mx > 1) ? 2 : (off ? 0 : 1);
    }
}

// ---------------------------------------------------------------------------
__global__ __launch_bounds__(256) void split_bf16(
    const float* __restrict__ x,
    __nv_bfloat16* __restrict__ hi, __nv_bfloat16* __restrict__ lo)
{
    size_t base = ((size_t)blockIdx.x * 256 + threadIdx.x) * 8;
    float4 a = *(const float4*)(x + base);
    float4 b = *(const float4*)(x + base + 4);
    float v[8] = {a.x, a.y, a.z, a.w, b.x, b.y, b.z, b.w};
    __nv_bfloat162 h2[4], l2[4];
#pragma unroll
    for (int i = 0; i < 4; i++) {
        __nv_bfloat16 h0 = __float2bfloat16_rn(v[2 * i]);
        __nv_bfloat16 h1 = __float2bfloat16_rn(v[2 * i + 1]);
        __nv_bfloat16 l0 = __float2bfloat16_rn(v[2 * i] - __bfloat162float(h0));
        __nv_bfloat16 l1 = __float2bfloat16_rn(v[2 * i + 1] - __bfloat162float(h1));
        h2[i] = __nv_bfloat162(h0, h1);
        l2[i] = __nv_bfloat162(l0, l1);
    }
    *(uint4*)(hi + base) = *(uint4*)h2;
    *(uint4*)(lo + base) = *(uint4*)l2;
}

// ---------------------------------------------------------------------------
__device__ __forceinline__ uint32_t smem_u32(const void* p) {
    uint32_t a;
    asm("{ .reg .u64 t; cvta.to.shared.u64 t, %1; cvt.u32.u64 %0, t; }"
        : "=r"(a) : "l"(p));
    return a;
}
__device__ __forceinline__ void ldsm4(uint32_t addr, uint32_t* r) {
    asm volatile("ldmatrix.sync.aligned.m8n8.x4.shared.b16 {%0,%1,%2,%3}, [%4];"
        : "=r"(r[0]), "=r"(r[1]), "=r"(r[2]), "=r"(r[3]) : "r"(addr));
}
__device__ __forceinline__ void ldsm4t(uint32_t addr, uint32_t* r) {
    asm volatile("ldmatrix.sync.aligned.m8n8.x4.trans.shared.b16 {%0,%1,%2,%3}, [%4];"
        : "=r"(r[0]), "=r"(r[1]), "=r"(r[2]), "=r"(r[3]) : "r"(addr));
}
__device__ __forceinline__ void mma16816(float* d, const uint32_t* a,
                                         uint32_t b0, uint32_t b1) {
    asm volatile(
        "mma.sync.aligned.m16n8k16.row.col.f32.bf16.bf16.f32 "
        "{%0,%1,%2,%3}, {%4,%5,%6,%7}, {%8,%9}, {%0,%1,%2,%3};"
        : "+f"(d[0]), "+f"(d[1]), "+f"(d[2]), "+f"(d[3])
        : "r"(a[0]), "r"(a[1]), "r"(a[2]), "r"(a[3]), "r"(b0), "r"(b1));
}
__device__ __forceinline__ void cpa16(uint32_t s, const void* g) {
    asm volatile("cp.async.cg.shared.global [%0], [%1], 16;" :: "r"(s), "l"(g));
}
__device__ __forceinline__ uint32_t pack_bf16(float a, float b) {
    __nv_bfloat162 h = __floats2bfloat162_rn(a, b);
    return *(uint32_t*)&h;
}

// 32-col bf16 tile (64B rows)
__device__ __forceinline__ uint32_t sw_off(int r, int c) {
    return (uint32_t)(r * 64 + ((c ^ ((r >> 1) & 3)) * 16));
}
// 64-col bf16 tile (128B rows)
__device__ __forceinline__ uint32_t sw64(int r, int c) {
    return (uint32_t)(r * 128 + ((c ^ (r & 7)) * 16));
}

// ---------------------------------------------------------------------------
// HMMA GEMM: C = (Ah+Al)@(Bh+Bl)^T + bias, *scale.  3-stage cp.async,
// ONE barrier per k-iteration, cp.async issued right after the barrier.
// Stage layout (32KB): Ah +0 | Al +8192 | Bh +16384 | Bl +24576.
// ---------------------------------------------------------------------------
#define GEMM_SMEM (3 * 32768)

__global__ __launch_bounds__(256, 2) void gemm_mma(
    const __nv_bfloat16* __restrict__ Ah, const __nv_bfloat16* __restrict__ Al,
    const __nv_bfloat16* __restrict__ Bh, const __nv_bfloat16* __restrict__ Bl,
    const float* __restrict__ bias, float* __restrict__ Cf,
    __nv_bfloat16* __restrict__ Ch, __nv_bfloat16* __restrict__ Cl,
    float scale)
{
    extern __shared__ __align__(1024) char sm[];
    const int t    = threadIdx.x;
    const int bm   = blockIdx.y * 128;
    const int bn   = blockIdx.x * 128;
    const int lane = t & 31;
    const int w    = t >> 5;
    const int wm   = (w & 1) * 64;
    const int wn   = (w >> 1) * 32;
    const int lr   = lane & 15;
    const int kc   = lane >> 4;
    const uint32_t smb = smem_u32(sm);

    float d[4][4][4];
#pragma unroll
    for (int i = 0; i < 4; i++)
#pragma unroll
        for (int j = 0; j < 4; j++)
#pragma unroll
            for (int r = 0; r < 4; r++) d[i][j][r] = 0.0f;

    // ---- cp.async setup ----
    const int r0 = t >> 2, c0 = t & 3;
    const int r1 = r0 + 64;
    const __nv_bfloat16* srcs[4] = {Ah, Al, Bh, Bl};
    const __nv_bfloat16* sp[8];
    uint32_t dst[8];
#pragma unroll
    for (int arr = 0; arr < 4; arr++) {
        const int rb = (arr < 2) ? bm : bn;
        sp[2 * arr]     = srcs[arr] + (size_t)(rb + r0) * DMODEL + c0 * 8;
        sp[2 * arr + 1] = srcs[arr] + (size_t)(rb + r1) * DMODEL + c0 * 8;
        dst[2 * arr]     = smb + arr * 8192 + sw_off(r0, c0);
        dst[2 * arr + 1] = smb + arr * 8192 + sw_off(r1, c0);
    }
    auto issue = [&](uint32_t so2, int kt) {
#pragma unroll
        for (int i = 0; i < 8; i++) cpa16(dst[i] + so2, sp[i] + kt * 32);
        asm volatile("cp.async.commit_group;");
    };

    // ---- ldsm base addresses (stage 0, kk=0) ----
    uint32_t aA[4], aB[2];
#pragma unroll
    for (int i = 0; i < 4; i++) aA[i] = smb + sw_off(wm + i * 16 + lr, kc);
#pragma unroll
    for (int p = 0; p < 2; p++) aB[p] = smb + 16384 + sw_off(wn + p * 16 + lr, kc);

    issue(0, 0);
    issue(32768, 1);

    uint32_t so = 0, si = 65536;
#pragma unroll 1
    for (int kt = 0; kt < 64; kt++) {
        if (kt < 63) asm volatile("cp.async.wait_group 1;");
        else         asm volatile("cp.async.wait_group 0;");
        __syncthreads();
        // Overwrite of stage si is safe: its last readers ran in iteration
        // kt-1 and are ordered before this barrier.
        if (kt + 2 < 64) issue(si, kt + 2);

#pragma unroll
        for (int kk = 0; kk < 2; kk++) {
            const uint32_t kx = kk * 32;
            uint32_t af[4][4], bh[2][4], bl[2][4];
#pragma unroll
            for (int i = 0; i < 4; i++) ldsm4((aA[i] ^ kx) + so, af[i]);
#pragma unroll
            for (int p = 0; p < 2; p++) ldsm4((aB[p] ^ kx) + so, bh[p]);
#pragma unroll
            for (int p = 0; p < 2; p++) ldsm4((aB[p] ^ kx) + so + 8192, bl[p]);
            // Ah*Bh
#pragma unroll
            for (int i = 0; i < 4; i++)
#pragma unroll
                for (int j = 0; j < 4; j++)
                    mma16816(d[i][j], af[i], bh[j >> 1][j & 1], bh[j >> 1][(j & 1) + 2]);
            // Ah*Bl
#pragma unroll
            for (int i = 0; i < 4; i++)
#pragma unroll
                for (int j = 0; j < 4; j++)
                    mma16816(d[i][j], af[i], bl[j >> 1][j & 1], bl[j >> 1][(j & 1) + 2]);
            // Al*Bh  (Al tile lives at +8192 in the stage)
#pragma unroll
            for (int i = 0; i < 4; i++) ldsm4((aA[i] ^ kx) + so + 8192, af[i]);
#pragma unroll
            for (int i = 0; i < 4; i++)
#pragma unroll
                for (int j = 0; j < 4; j++)
                    mma16816(d[i][j], af[i], bh[j >> 1][j & 1], bh[j >> 1][(j & 1) + 2]);
        }
        so = (so == 65536) ? 0 : so + 32768;
        si = (si == 65536) ? 0 : si + 32768;
    }

    const int tg = lane >> 2, t4 = lane & 3;
#pragma unroll
    for (int i = 0; i < 4; i++) {
        const int row = bm + wm + i * 16 + tg;
#pragma unroll
        for (int j = 0; j < 4; j++) {
            const int col = bn + wn + j * 8 + t4 * 2;
            const float b0 = bias[col], b1 = bias[col + 1];
            float v0 = (d[i][j][0] + b0) * scale, v1 = (d[i][j][1] + b1) * scale;
            float v2 = (d[i][j][2] + b0) * scale, v3 = (d[i][j][3] + b1) * scale;
            if (Cf) {
                *(float2*)&Cf[(size_t)row * DMODEL + col] = make_float2(v0, v1);
                *(float2*)&Cf[(size_t)(row + 8) * DMODEL + col] = make_float2(v2, v3);
            } else {
                uint32_t h0 = pack_bf16(v0, v1), h1 = pack_bf16(v2, v3);
                __nv_bfloat162 hh0 = *(__nv_bfloat162*)&h0;
                __nv_bfloat162 hh1 = *(__nv_bfloat162*)&h1;
                uint32_t l0 = pack_bf16(v0 - __bfloat162float(hh0.x),
                                        v1 - __bfloat162float(hh0.y));
                uint32_t l1 = pack_bf16(v2 - __bfloat162float(hh1.x),
                                        v3 - __bfloat162float(hh1.y));
                *(uint32_t*)&Ch[(size_t)row * DMODEL + col] = h0;
                *(uint32_t*)&Ch[(size_t)(row + 8) * DMODEL + col] = h1;
                *(uint32_t*)&Cl[(size_t)row * DMODEL + col] = l0;
                *(uint32_t*)&Cl[(size_t)(row + 8) * DMODEL + col] = l1;
            }
        }
    }
}

// ---------------------------------------------------------------------------
// Tensor-core flash attention.  Q fragments held in REGISTERS for the whole
// kernel (loaded once, direct LDG in a-frag layout).  Mask folded into the
// prefetched bias (-1e30 on masked lanes).  smem = 2 x 32KB KV stages only
// -> 3 CTAs/SM.  KV stage layout: Kh +0 | Kl +8192 | Vh +16384 | Vl +24576.
// ---------------------------------------------------------------------------
#define ATTN_SMEM (2 * 32768)

__global__ __launch_bounds__(128, 3) void attn_mma(
    const __nv_bfloat16* __restrict__ Qh, const __nv_bfloat16* __restrict__ Ql,
    const __nv_bfloat16* __restrict__ Kh, const __nv_bfloat16* __restrict__ Kl,
    const __nv_bfloat16* __restrict__ Vh, const __nv_bfloat16* __restrict__ Vl,
    const void* __restrict__ mask_raw, const float* __restrict__ pb,
    __nv_bfloat16* __restrict__ Oh, __nv_bfloat16* __restrict__ Ol)
{
    extern __shared__ __align__(1024) char sm[];
    const int t = threadIdx.x, lane = t & 31, w = t >> 5;
    const int lr = lane & 15, kc = lane >> 4;
    const int group = lane >> 2, t4 = lane & 3;
    const int qbase = blockIdx.x * 64;
    const int h = blockIdx.y;
    const int mode = g_mask_mode;
    const uint32_t smb = smem_u32(sm);

    const unsigned char* m8 = (const unsigned char*)mask_raw;
    const int*   m32 = (const int*)mask_raw;
    const float* mf  = (const float*)mask_raw;

    const __nv_bfloat16* kvs[4] = {Kh, Kl, Vh, Vl};
    auto issue_kv = [&](int st, int tile) {
#pragma unroll
        for (int arr = 0; arr < 4; arr++)
#pragma unroll
            for (int i = 0; i < 4; i++) {
                int idx = t + i * 128;
                int r = idx >> 3, c = idx & 7;
                cpa16(smb + st * 32768 + arr * 8192 + sw64(r, c),
                      kvs[arr] + (size_t)(tile * 64 + r) * DMODEL + h * DH + c * 8);
            }
        asm volatile("cp.async.commit_group;");
    };
    issue_kv(0, 0);

    // ---- Q fragments in registers (a-frag layout, loaded once) ----
    uint32_t qfh[4][4], qfl[4][4];
    {
        const int g = qbase + w * 16 + group;
#pragma unroll
        for (int kk = 0; kk < 4; kk++) {
            const size_t col = (size_t)h * DH + kk * 16 + t4 * 2;
            qfh[kk][0] = *(const uint32_t*)&Qh[(size_t)g * DMODEL + col];
            qfh[kk][1] = *(const uint32_t*)&Qh[(size_t)(g + 8) * DMODEL + col];
            qfh[kk][2] = *(const uint32_t*)&Qh[(size_t)g * DMODEL + col + 8];
            qfh[kk][3] = *(const uint32_t*)&Qh[(size_t)(g + 8) * DMODEL + col + 8];
            qfl[kk][0] = *(const uint32_t*)&Ql[(size_t)g * DMODEL + col];
            qfl[kk][1] = *(const uint32_t*)&Ql[(size_t)(g + 8) * DMODEL + col];
            qfl[kk][2] = *(const uint32_t*)&Ql[(size_t)g * DMODEL + col + 8];
            qfl[kk][3] = *(const uint32_t*)&Ql[(size_t)(g + 8) * DMODEL + col + 8];
        }
    }

    // ldsm base addresses (stage 0, kk/jj = 0)
    uint32_t aK[4], aV[4];
#pragma unroll
    for (int p = 0; p < 4; p++) aK[p] = smb + sw64(p * 16 + lr, kc);
#pragma unroll
    for (int p = 0; p < 4; p++) aV[p] = smb + 16384 + sw64(p * 16 + lr, kc);

    float O[8][4];
    float m_i[2] = {-1e30f, -1e30f}, l_i[2] = {0.0f, 0.0f};
#pragma unroll
    for (int j = 0; j < 8; j++)
#pragma unroll
        for (int r = 0; r < 4; r++) O[j][r] = 0.0f;

#pragma unroll 1
    for (int it = 0; it < 32; it++) {
        if (it < 31) issue_kv((it + 1) & 1, it + 1);

        // ---- prefetch bias with mask folded in (-1e30 on masked lanes) ----
        float2 pbv[2][8];
#pragma unroll
        for (int r2 = 0; r2 < 2; r2++) {
            const int qrow = qbase + w * 16 + group + r2 * 8;
            const size_t prow = ((size_t)h * SEQ + qrow) * SEQ + it * 64;
            const size_t mrow = (size_t)qrow * SEQ + it * 64;
#pragma unroll
            for (int j = 0; j < 8; j++) {
                const int col = j * 8 + t4 * 2;
                float2 bv = *(const float2*)&pb[prow + col];
                int ok0, ok1;
                if (mode == 0) {
                    uchar2 mv = *(const uchar2*)&m8[mrow + col];
                    ok0 = mv.x; ok1 = mv.y;
                } else if (mode == 1) {
                    int2 mv = *(const int2*)&m32[mrow + col];
                    ok0 = mv.x; ok1 = mv.y;
                } else {
                    float2 mv = *(const float2*)&mf[mrow + col];
                    ok0 = (mv.x != 0.0f); ok1 = (mv.y != 0.0f);
                }
                pbv[r2][j].x = ok0 ? bv.x : -1e30f;
                pbv[r2][j].y = ok1 ? bv.y : -1e30f;
            }
        }

        if (it < 31) asm volatile("cp.async.wait_group 1;");
        else         asm volatile("cp.async.wait_group 0;");
        __syncthreads();

        const uint32_t so = (it & 1) * 32768;

        // ---- S = (Q/8) K^T  (3-pass split) ----
        float S[8][4];
#pragma unroll
        for (int j = 0; j < 8; j++)
#pragma unroll
            for (int r = 0; r < 4; r++) S[j][r] = 0.0f;

#pragma unroll
        for (int kk = 0; kk < 4; kk++) {
            const uint32_t kx = kk * 32;
            uint32_t khf[4][4], klf[4][4];
#pragma unroll
            for (int p = 0; p < 4; p++) ldsm4((aK[p] ^ kx) + so, khf[p]);
#pragma unroll
            for (int p = 0; p < 4; p++) ldsm4((aK[p] ^ kx) + so + 8192, klf[p]);
#pragma unroll
            for (int j = 0; j < 8; j++)
                mma16816(S[j], qfh[kk], khf[j >> 1][j & 1], khf[j >> 1][(j & 1) + 2]);
#pragma unroll
            for (int j = 0; j < 8; j++)
                mma16816(S[j], qfl[kk], khf[j >> 1][j & 1], khf[j >> 1][(j & 1) + 2]);
#pragma unroll
            for (int j = 0; j < 8; j++)
                mma16816(S[j], qfh[kk], klf[j >> 1][j & 1], klf[j >> 1][(j & 1) + 2]);
        }

        // ---- bias(+mask) + online softmax ----
#pragma unroll
        for (int r2 = 0; r2 < 2; r2++) {
            float mx = -1e30f;
#pragma unroll
            for (int j = 0; j < 8; j++) {
                float s0 = S[j][r2 * 2]     + pbv[r2][j].x;
                float s1 = S[j][r2 * 2 + 1] + pbv[r2][j].y;
                S[j][r2 * 2] = s0; S[j][r2 * 2 + 1] = s1;
                mx = fmaxf(mx, fmaxf(s0, s1));
            }
            mx = fmaxf(mx, __shfl_xor_sync(0xffffffffu, mx, 1));
            mx = fmaxf(mx, __shfl_xor_sync(0xffffffffu, mx, 2));
            float mnew = fmaxf(m_i[r2], mx);
            float corr = __expf(m_i[r2] - mnew);
            float rsum = 0.0f;
#pragma unroll
            for (int j = 0; j < 8; j++) {
#pragma unroll
                for (int e = 0; e < 2; e++) {
                    float s = S[j][r2 * 2 + e];
                    float p = (s > -1e29f) ? __expf(s - mnew) : 0.0f;
                    S[j][r2 * 2 + e] = p;
                    rsum += p;
                }
            }
            rsum += __shfl_xor_sync(0xffffffffu, rsum, 1);
            rsum += __shfl_xor_sync(0xffffffffu, rsum, 2);
            l_i[r2] = l_i[r2] * corr + rsum;
            m_i[r2] = mnew;
#pragma unroll
            for (int j = 0; j < 8; j++) {
                O[j][r2 * 2]     *= corr;
                O[j][r2 * 2 + 1] *= corr;
            }
        }

        // ---- pack P into hi/lo a-frags ----
        uint32_t aPh[4][4], aPl[4][4];
#pragma unroll
        for (int kk = 0; kk < 4; kk++) {
#pragma unroll
            for (int half = 0; half < 2; half++) {
                const int j = 2 * kk + half;
#pragma unroll
                for (int rr = 0; rr < 2; rr++) {
                    float p0 = S[j][rr * 2], p1 = S[j][rr * 2 + 1];
                    uint32_t hp = pack_bf16(p0, p1);
                    __nv_bfloat162 hb = *(__nv_bfloat162*)&hp;
                    aPh[kk][half * 2 + rr] = hp;
                    aPl[kk][half * 2 + rr] =
                        pack_bf16(p0 - __bfloat162float(hb.x),
                                  p1 - __bfloat162float(hb.y));
                }
            }
        }

        // ---- O += P V  (3-pass split) ----
#pragma unroll
        for (int kk = 0; kk < 4; kk++) {
#pragma unroll
            for (int jj = 0; jj < 4; jj++) {
                const uint32_t jx = jj * 32;
                uint32_t vh4[4], vl4[4];
                ldsm4t((aV[kk] ^ jx) + so, vh4);
                ldsm4t((aV[kk] ^ jx) + so + 8192, vl4);
                mma16816(O[2 * jj],     aPh[kk], vh4[0], vh4[1]);
                mma16816(O[2 * jj + 1], aPh[kk], vh4[2], vh4[3]);
                mma16816(O[2 * jj],     aPl[kk], vh4[0], vh4[1]);
                mma16816(O[2 * jj + 1], aPl[kk], vh4[2], vh4[3]);
                mma16816(O[2 * jj],     aPh[kk], vl4[0], vl4[1]);
                mma16816(O[2 * jj + 1], aPh[kk], vl4[2], vl4[3]);
            }
        }
        __syncthreads();
    }

    // ---- epilogue ----
#pragma unroll
    for (int r2 = 0; r2 < 2; r2++) {
        const int qrow = qbase + w * 16 + group + r2 * 8;
        const float inv = 1.0f / l_i[r2];
#pragma unroll
        for (int j = 0; j < 8; j++) {
            const int col = h * DH + j * 8 + t4 * 2;
            float v0 = O[j][r2 * 2] * inv, v1 = O[j][r2 * 2 + 1] * inv;
            uint32_t hp = pack_bf16(v0, v1);
            __nv_bfloat162 hb = *(__nv_bfloat162*)&hp;
            uint32_t lp = pack_bf16(v0 - __bfloat162float(hb.x),
                                    v1 - __bfloat162float(hb.y));
            *(uint32_t*)&Oh[(size_t)qrow * DMODEL + col] = hp;
            *(uint32_t*)&Ol[(size_t)qrow * DMODEL + col] = lp;
        }
    }
}

// ---------------------------------------------------------------------------
extern "C" void kernel_launch(void* const* d_in, const int* in_sizes, int n_in,
                              void* d_out, int out_size)
{
    const float* hq   = (const float*)d_in[0];
    const float* hkv  = (const float*)d_in[1];
    const void*  mask = d_in[2];
    const float* pb   = (const float*)d_in[3];
    const float* wq   = (const float*)d_in[4];
    const float* bq   = (const float*)d_in[5];
    const float* wk   = (const float*)d_in[6];
    const float* bk   = (const float*)d_in[7];
    const float* wv   = (const float*)d_in[8];
    const float* bv   = (const float*)d_in[9];
    const float* wo   = (const float*)d_in[10];
    const float* bo   = (const float*)d_in[11];
    float* out = (float*)d_out;

    __nv_bfloat16 *xh, *xl, *wh, *wl, *qh, *ql, *kh, *kl, *vh, *vl, *ah, *al;
    cudaGetSymbolAddress((void**)&xh, g_xh);
    cudaGetSymbolAddress((void**)&xl, g_xl);
    cudaGetSymbolAddress((void**)&wh, g_wh);
    cudaGetSymbolAddress((void**)&wl, g_wl);
    cudaGetSymbolAddress((void**)&qh, g_qh);
    cudaGetSymbolAddress((void**)&ql, g_ql);
    cudaGetSymbolAddress((void**)&kh, g_kh);
    cudaGetSymbolAddress((void**)&kl, g_kl);
    cudaGetSymbolAddress((void**)&vh, g_vh);
    cudaGetSymbolAddress((void**)&vl, g_vl);
    cudaGetSymbolAddress((void**)&ah, g_ah);
    cudaGetSymbolAddress((void**)&al, g_al);

    cudaFuncSetAttribute(gemm_mma,
                         cudaFuncAttributeMaxDynamicSharedMemorySize, GEMM_SMEM);
    cudaFuncSetAttribute(attn_mma,
                         cudaFuncAttributeMaxDynamicSharedMemorySize, ATTN_SMEM);

    detect_mask_kernel<<<1, 32>>>((const unsigned char*)mask);

    dim3 gg(DMODEL / 128, SEQ / 128);

    split_bf16<<<2048, 256>>>(hq, xh, xl);
    split_bf16<<<2048, 256>>>(wq, wh, wl);
    gemm_mma<<<gg, 256, GEMM_SMEM>>>(xh, xl, wh, wl, bq, nullptr, qh, ql, 0.125f);

    split_bf16<<<2048, 256>>>(hkv, xh, xl);
    split_bf16<<<2048, 256>>>(wk, wh, wl);
    gemm_mma<<<gg, 256, GEMM_SMEM>>>(xh, xl, wh, wl, bk, nullptr, kh, kl, 1.0f);
    split_bf16<<<2048, 256>>>(wv, wh, wl);
    gemm_mma<<<gg, 256, GEMM_SMEM>>>(xh, xl, wh, wl, bv, nullptr, vh, vl, 1.0f);

    attn_mma<<<dim3(SEQ / 64, NH), 128, ATTN_SMEM>>>(
        qh, ql, kh, kl, vh, vl, mask, pb, ah, al);

    split_bf16<<<2048, 256>>>(wo, wh, wl);
    gemm_mma<<<gg, 256, GEMM_SMEM>>>(ah, al, wh, wl, bo, out, nullptr, nullptr, 1.0f);
}

// round 11
// speedup vs baseline: 3.2503x; 1.3448x over previous
#include <cuda_runtime.h>
#include <cuda_fp16.h>
#include <cstdint>
#include <cstddef>

#define SEQ 2048
#define DMODEL 2048
#define NH 32
#define DH 64

// ---------------------------------------------------------------------------
// Scratch (device globals: allocation-free rule).  fp16 data path.
// ---------------------------------------------------------------------------
__device__ __half g_xh[SEQ * DMODEL];   // activation hi
__device__ __half g_xl[SEQ * DMODEL];   // activation lo
__device__ __half g_wb[SEQ * DMODEL];   // weight, single fp16 (B operand)
__device__ __half g_qh[SEQ * DMODEL];   // Q (pre-scaled 0.125) hi/lo
__device__ __half g_ql[SEQ * DMODEL];
__device__ __half g_k [SEQ * DMODEL];   // K single fp16
__device__ __half g_v [SEQ * DMODEL];   // V single fp16
__device__ __half g_ah[SEQ * DMODEL];   // attention out hi/lo
__device__ __half g_al[SEQ * DMODEL];
__device__ int g_mask_mode;  // 0=uint8, 1=int32, 2=float32

// ---------------------------------------------------------------------------
__global__ void detect_mask_kernel(const unsigned char* __restrict__ m) {
    if (threadIdx.x == 0) {
        int mx = 0, off = 0;
        for (int i = 0; i < 256; i++) {
            int b = m[i];
            if (b > mx) mx = b;
            if ((i & 3) && b) off = 1;
        }
        g_mask_mode = (mx > 1) ? 2 : (off ? 0 : 1);
    }
}

// ---------------------------------------------------------------------------
// fp32 -> fp16 hi/lo split (hi = rn(x), lo = rn(x - hi); x to ~2^-23)
// ---------------------------------------------------------------------------
__global__ __launch_bounds__(256) void split_f16(
    const float* __restrict__ x,
    __half* __restrict__ hi, __half* __restrict__ lo)
{
    size_t base = ((size_t)blockIdx.x * 256 + threadIdx.x) * 8;
    float4 a = *(const float4*)(x + base);
    float4 b = *(const float4*)(x + base + 4);
    float v[8] = {a.x, a.y, a.z, a.w, b.x, b.y, b.z, b.w};
    __half2 h2[4], l2[4];
#pragma unroll
    for (int i = 0; i < 4; i++) {
        float v0 = v[2 * i], v1 = v[2 * i + 1];
        __half h0 = __float2half_rn(v0);
        __half h1 = __float2half_rn(v1);
        h2[i] = __halves2half2(h0, h1);
        l2[i] = __floats2half2_rn(v0 - __half2float(h0), v1 - __half2float(h1));
    }
    *(uint4*)(hi + base) = *(uint4*)h2;
    *(uint4*)(lo + base) = *(uint4*)l2;
}

// fp32 -> fp16 single (weights / B operands)
__global__ __launch_bounds__(256) void conv_f16(
    const float* __restrict__ x, __half* __restrict__ y)
{
    size_t base = ((size_t)blockIdx.x * 256 + threadIdx.x) * 8;
    float4 a = *(const float4*)(x + base);
    float4 b = *(const float4*)(x + base + 4);
    __half2 h2[4];
    h2[0] = __floats2half2_rn(a.x, a.y);
    h2[1] = __floats2half2_rn(a.z, a.w);
    h2[2] = __floats2half2_rn(b.x, b.y);
    h2[3] = __floats2half2_rn(b.z, b.w);
    *(uint4*)(y + base) = *(uint4*)h2;
}

// ---------------------------------------------------------------------------
__device__ __forceinline__ uint32_t smem_u32(const void* p) {
    uint32_t a;
    asm("{ .reg .u64 t; cvta.to.shared.u64 t, %1; cvt.u32.u64 %0, t; }"
        : "=r"(a) : "l"(p));
    return a;
}
__device__ __forceinline__ void ldsm4(uint32_t addr, uint32_t* r) {
    asm volatile("ldmatrix.sync.aligned.m8n8.x4.shared.b16 {%0,%1,%2,%3}, [%4];"
        : "=r"(r[0]), "=r"(r[1]), "=r"(r[2]), "=r"(r[3]) : "r"(addr));
}
__device__ __forceinline__ void ldsm4t(uint32_t addr, uint32_t* r) {
    asm volatile("ldmatrix.sync.aligned.m8n8.x4.trans.shared.b16 {%0,%1,%2,%3}, [%4];"
        : "=r"(r[0]), "=r"(r[1]), "=r"(r[2]), "=r"(r[3]) : "r"(addr));
}
__device__ __forceinline__ void mma16816(float* d, const uint32_t* a,
                                         uint32_t b0, uint32_t b1) {
    asm volatile(
        "mma.sync.aligned.m16n8k16.row.col.f32.f16.f16.f32 "
        "{%0,%1,%2,%3}, {%4,%5,%6,%7}, {%8,%9}, {%0,%1,%2,%3};"
        : "+f"(d[0]), "+f"(d[1]), "+f"(d[2]), "+f"(d[3])
        : "r"(a[0]), "r"(a[1]), "r"(a[2]), "r"(a[3]), "r"(b0), "r"(b1));
}
__device__ __forceinline__ void cpa16(uint32_t s, const void* g) {
    asm volatile("cp.async.cg.shared.global [%0], [%1], 16;" :: "r"(s), "l"(g));
}
__device__ __forceinline__ uint32_t pack_f16(float a, float b) {
    __half2 h = __floats2half2_rn(a, b);
    return *(uint32_t*)&h;
}

// 32-col f16 tile (64B rows)
__device__ __forceinline__ uint32_t sw_off(int r, int c) {
    return (uint32_t)(r * 64 + ((c ^ ((r >> 1) & 3)) * 16));
}
// 64-col f16 tile (128B rows)
__device__ __forceinline__ uint32_t sw64(int r, int c) {
    return (uint32_t)(r * 128 + ((c ^ (r & 7)) * 16));
}

// ---------------------------------------------------------------------------
// HMMA GEMM (fp16 2-pass): C = (Ah+Al)[M,K] @ B[N,K]^T + bias, *scale.
// 3-stage cp.async, one barrier per k-iter.
// Stage layout (24KB): Ah +0 | Al +8192 | B +16384.
// Output: Cf fp32, or (Ch,Cl) fp16 split, or Ch single fp16 (Cl null).
// ---------------------------------------------------------------------------
#define GEMM_SMEM (3 * 24576)

__global__ __launch_bounds__(256, 2) void gemm_mma(
    const __half* __restrict__ Ah, const __half* __restrict__ Al,
    const __half* __restrict__ B,
    const float* __restrict__ bias, float* __restrict__ Cf,
    __half* __restrict__ Ch, __half* __restrict__ Cl,
    float scale)
{
    extern __shared__ __align__(1024) char sm[];
    const int t    = threadIdx.x;
    const int bm   = blockIdx.y * 128;
    const int bn   = blockIdx.x * 128;
    const int lane = t & 31;
    const int w    = t >> 5;
    const int wm   = (w & 1) * 64;
    const int wn   = (w >> 1) * 32;
    const int lr   = lane & 15;
    const int kc   = lane >> 4;
    const uint32_t smb = smem_u32(sm);

    float d[4][4][4];
#pragma unroll
    for (int i = 0; i < 4; i++)
#pragma unroll
        for (int j = 0; j < 4; j++)
#pragma unroll
            for (int r = 0; r < 4; r++) d[i][j][r] = 0.0f;

    // ---- cp.async setup: 3 tiles (Ah, Al, B), 2 chunks each per thread ----
    const int r0 = t >> 2, c0 = t & 3;
    const int r1 = r0 + 64;
    const __half* srcs[3] = {Ah, Al, B};
    const __half* sp[6];
    uint32_t dst[6];
#pragma unroll
    for (int arr = 0; arr < 3; arr++) {
        const int rb = (arr < 2) ? bm : bn;
        sp[2 * arr]     = srcs[arr] + (size_t)(rb + r0) * DMODEL + c0 * 8;
        sp[2 * arr + 1] = srcs[arr] + (size_t)(rb + r1) * DMODEL + c0 * 8;
        dst[2 * arr]     = smb + arr * 8192 + sw_off(r0, c0);
        dst[2 * arr + 1] = smb + arr * 8192 + sw_off(r1, c0);
    }
    auto issue = [&](uint32_t so2, int kt) {
#pragma unroll
        for (int i = 0; i < 6; i++) cpa16(dst[i] + so2, sp[i] + kt * 32);
        asm volatile("cp.async.commit_group;");
    };

    // ---- ldsm base addresses (stage 0, kk=0) ----
    uint32_t aA[4], aB[2];
#pragma unroll
    for (int i = 0; i < 4; i++) aA[i] = smb + sw_off(wm + i * 16 + lr, kc);
#pragma unroll
    for (int p = 0; p < 2; p++) aB[p] = smb + 16384 + sw_off(wn + p * 16 + lr, kc);

    issue(0, 0);
    issue(24576, 1);

    uint32_t so = 0, si = 49152;
#pragma unroll 1
    for (int kt = 0; kt < 64; kt++) {
        if (kt < 63) asm volatile("cp.async.wait_group 1;");
        else         asm volatile("cp.async.wait_group 0;");
        __syncthreads();
        if (kt + 2 < 64) issue(si, kt + 2);

#pragma unroll
        for (int kk = 0; kk < 2; kk++) {
            const uint32_t kx = kk * 32;
            uint32_t af[4][4], bf[2][4];
#pragma unroll
            for (int i = 0; i < 4; i++) ldsm4((aA[i] ^ kx) + so, af[i]);
#pragma unroll
            for (int p = 0; p < 2; p++) ldsm4((aB[p] ^ kx) + so, bf[p]);
            // pass 1: Ah * B
#pragma unroll
            for (int i = 0; i < 4; i++)
#pragma unroll
                for (int j = 0; j < 4; j++)
                    mma16816(d[i][j], af[i], bf[j >> 1][j & 1], bf[j >> 1][(j & 1) + 2]);
            // pass 2: Al * B  (Al tile at +8192)
#pragma unroll
            for (int i = 0; i < 4; i++) ldsm4((aA[i] ^ kx) + so + 8192, af[i]);
#pragma unroll
            for (int i = 0; i < 4; i++)
#pragma unroll
                for (int j = 0; j < 4; j++)
                    mma16816(d[i][j], af[i], bf[j >> 1][j & 1], bf[j >> 1][(j & 1) + 2]);
        }
        so = (so == 49152) ? 0 : so + 24576;
        si = (si == 49152) ? 0 : si + 24576;
    }

    const int tg = lane >> 2, t4 = lane & 3;
#pragma unroll
    for (int i = 0; i < 4; i++) {
        const int row = bm + wm + i * 16 + tg;
#pragma unroll
        for (int j = 0; j < 4; j++) {
            const int col = bn + wn + j * 8 + t4 * 2;
            const float b0 = bias[col], b1 = bias[col + 1];
            float v0 = (d[i][j][0] + b0) * scale, v1 = (d[i][j][1] + b1) * scale;
            float v2 = (d[i][j][2] + b0) * scale, v3 = (d[i][j][3] + b1) * scale;
            if (Cf) {
                *(float2*)&Cf[(size_t)row * DMODEL + col] = make_float2(v0, v1);
                *(float2*)&Cf[(size_t)(row + 8) * DMODEL + col] = make_float2(v2, v3);
            } else if (Cl) {
                uint32_t h0 = pack_f16(v0, v1), h1 = pack_f16(v2, v3);
                __half2 hh0 = *(__half2*)&h0;
                __half2 hh1 = *(__half2*)&h1;
                uint32_t l0 = pack_f16(v0 - __half2float(__low2half(hh0)),
                                       v1 - __half2float(__high2half(hh0)));
                uint32_t l1 = pack_f16(v2 - __half2float(__low2half(hh1)),
                                       v3 - __half2float(__high2half(hh1)));
                *(uint32_t*)&Ch[(size_t)row * DMODEL + col] = h0;
                *(uint32_t*)&Ch[(size_t)(row + 8) * DMODEL + col] = h1;
                *(uint32_t*)&Cl[(size_t)row * DMODEL + col] = l0;
                *(uint32_t*)&Cl[(size_t)(row + 8) * DMODEL + col] = l1;
            } else {
                *(uint32_t*)&Ch[(size_t)row * DMODEL + col] = pack_f16(v0, v1);
                *(uint32_t*)&Ch[(size_t)(row + 8) * DMODEL + col] = pack_f16(v2, v3);
            }
        }
    }
}

// ---------------------------------------------------------------------------
// Tensor-core flash attention (fp16 2-pass).  Q split in registers;
// K, V single fp16 in smem.  Stage (16KB): K +0 | V +8192; 2 stages.
// ---------------------------------------------------------------------------
#define ATTN_SMEM (2 * 16384)

__global__ __launch_bounds__(128, 3) void attn_mma(
    const __half* __restrict__ Qh, const __half* __restrict__ Ql,
    const __half* __restrict__ K, const __half* __restrict__ V,
    const void* __restrict__ mask_raw, const float* __restrict__ pb,
    __half* __restrict__ Oh, __half* __restrict__ Ol)
{
    extern __shared__ __align__(1024) char sm[];
    const int t = threadIdx.x, lane = t & 31, w = t >> 5;
    const int lr = lane & 15, kc = lane >> 4;
    const int group = lane >> 2, t4 = lane & 3;
    const int qbase = blockIdx.x * 64;
    const int h = blockIdx.y;
    const int mode = g_mask_mode;
    const uint32_t smb = smem_u32(sm);

    const unsigned char* m8 = (const unsigned char*)mask_raw;
    const int*   m32 = (const int*)mask_raw;
    const float* mf  = (const float*)mask_raw;

    const __half* kvs[2] = {K, V};
    auto issue_kv = [&](int st, int tile) {
#pragma unroll
        for (int arr = 0; arr < 2; arr++)
#pragma unroll
            for (int i = 0; i < 4; i++) {
                int idx = t + i * 128;
                int r = idx >> 3, c = idx & 7;
                cpa16(smb + st * 16384 + arr * 8192 + sw64(r, c),
                      kvs[arr] + (size_t)(tile * 64 + r) * DMODEL + h * DH + c * 8);
            }
        asm volatile("cp.async.commit_group;");
    };
    issue_kv(0, 0);

    // ---- Q fragments in registers (a-frag layout, loaded once) ----
    uint32_t qfh[4][4], qfl[4][4];
    {
        const int g = qbase + w * 16 + group;
#pragma unroll
        for (int kk = 0; kk < 4; kk++) {
            const size_t col = (size_t)h * DH + kk * 16 + t4 * 2;
            qfh[kk][0] = *(const uint32_t*)&Qh[(size_t)g * DMODEL + col];
            qfh[kk][1] = *(const uint32_t*)&Qh[(size_t)(g + 8) * DMODEL + col];
            qfh[kk][2] = *(const uint32_t*)&Qh[(size_t)g * DMODEL + col + 8];
            qfh[kk][3] = *(const uint32_t*)&Qh[(size_t)(g + 8) * DMODEL + col + 8];
            qfl[kk][0] = *(const uint32_t*)&Ql[(size_t)g * DMODEL + col];
            qfl[kk][1] = *(const uint32_t*)&Ql[(size_t)(g + 8) * DMODEL + col];
            qfl[kk][2] = *(const uint32_t*)&Ql[(size_t)g * DMODEL + col + 8];
            qfl[kk][3] = *(const uint32_t*)&Ql[(size_t)(g + 8) * DMODEL + col + 8];
        }
    }

    // ldsm base addresses (stage 0, kk/jj = 0)
    uint32_t aK[4], aV[4];
#pragma unroll
    for (int p = 0; p < 4; p++) aK[p] = smb + sw64(p * 16 + lr, kc);
#pragma unroll
    for (int p = 0; p < 4; p++) aV[p] = smb + 8192 + sw64(p * 16 + lr, kc);

    float O[8][4];
    float m_i[2] = {-1e30f, -1e30f}, l_i[2] = {0.0f, 0.0f};
#pragma unroll
    for (int j = 0; j < 8; j++)
#pragma unroll
        for (int r = 0; r < 4; r++) O[j][r] = 0.0f;

#pragma unroll 1
    for (int it = 0; it < 32; it++) {
        if (it < 31) issue_kv((it + 1) & 1, it + 1);

        // ---- prefetch bias with mask folded in (-1e30 on masked lanes) ----
        float2 pbv[2][8];
#pragma unroll
        for (int r2 = 0; r2 < 2; r2++) {
            const int qrow = qbase + w * 16 + group + r2 * 8;
            const size_t prow = ((size_t)h * SEQ + qrow) * SEQ + it * 64;
            const size_t mrow = (size_t)qrow * SEQ + it * 64;
#pragma unroll
            for (int j = 0; j < 8; j++) {
                const int col = j * 8 + t4 * 2;
                float2 bv = *(const float2*)&pb[prow + col];
                int ok0, ok1;
                if (mode == 0) {
                    uchar2 mv = *(const uchar2*)&m8[mrow + col];
                    ok0 = mv.x; ok1 = mv.y;
                } else if (mode == 1) {
                    int2 mv = *(const int2*)&m32[mrow + col];
                    ok0 = mv.x; ok1 = mv.y;
                } else {
                    float2 mv = *(const float2*)&mf[mrow + col];
                    ok0 = (mv.x != 0.0f); ok1 = (mv.y != 0.0f);
                }
                pbv[r2][j].x = ok0 ? bv.x : -1e30f;
                pbv[r2][j].y = ok1 ? bv.y : -1e30f;
            }
        }

        if (it < 31) asm volatile("cp.async.wait_group 1;");
        else         asm volatile("cp.async.wait_group 0;");
        __syncthreads();

        const uint32_t so = (it & 1) * 16384;

        // ---- S = (Qh+Ql) K^T  (2-pass) ----
        float S[8][4];
#pragma unroll
        for (int j = 0; j < 8; j++)
#pragma unroll
            for (int r = 0; r < 4; r++) S[j][r] = 0.0f;

#pragma unroll
        for (int kk = 0; kk < 4; kk++) {
            const uint32_t kx = kk * 32;
            uint32_t khf[4][4];
#pragma unroll
            for (int p = 0; p < 4; p++) ldsm4((aK[p] ^ kx) + so, khf[p]);
#pragma unroll
            for (int j = 0; j < 8; j++)
                mma16816(S[j], qfh[kk], khf[j >> 1][j & 1], khf[j >> 1][(j & 1) + 2]);
#pragma unroll
            for (int j = 0; j < 8; j++)
                mma16816(S[j], qfl[kk], khf[j >> 1][j & 1], khf[j >> 1][(j & 1) + 2]);
        }

        // ---- bias(+mask) + online softmax ----
#pragma unroll
        for (int r2 = 0; r2 < 2; r2++) {
            float mx = -1e30f;
#pragma unroll
            for (int j = 0; j < 8; j++) {
                float s0 = S[j][r2 * 2]     + pbv[r2][j].x;
                float s1 = S[j][r2 * 2 + 1] + pbv[r2][j].y;
                S[j][r2 * 2] = s0; S[j][r2 * 2 + 1] = s1;
                mx = fmaxf(mx, fmaxf(s0, s1));
            }
            mx = fmaxf(mx, __shfl_xor_sync(0xffffffffu, mx, 1));
            mx = fmaxf(mx, __shfl_xor_sync(0xffffffffu, mx, 2));
            float mnew = fmaxf(m_i[r2], mx);
            float corr = __expf(m_i[r2] - mnew);
            float rsum = 0.0f;
#pragma unroll
            for (int j = 0; j < 8; j++) {
#pragma unroll
                for (int e = 0; e < 2; e++) {
                    float s = S[j][r2 * 2 + e];
                    float p = (s > -1e29f) ? __expf(s - mnew) : 0.0f;
                    S[j][r2 * 2 + e] = p;
                    rsum += p;
                }
            }
            rsum += __shfl_xor_sync(0xffffffffu, rsum, 1);
            rsum += __shfl_xor_sync(0xffffffffu, rsum, 2);
            l_i[r2] = l_i[r2] * corr + rsum;
            m_i[r2] = mnew;
#pragma unroll
            for (int j = 0; j < 8; j++) {
                O[j][r2 * 2]     *= corr;
                O[j][r2 * 2 + 1] *= corr;
            }
        }

        // ---- pack P into hi/lo fp16 a-frags ----
        uint32_t aPh[4][4], aPl[4][4];
#pragma unroll
        for (int kk = 0; kk < 4; kk++) {
#pragma unroll
            for (int half_ = 0; half_ < 2; half_++) {
                const int j = 2 * kk + half_;
#pragma unroll
                for (int rr = 0; rr < 2; rr++) {
                    float p0 = S[j][rr * 2], p1 = S[j][rr * 2 + 1];
                    uint32_t hp = pack_f16(p0, p1);
                    __half2 hb = *(__half2*)&hp;
                    aPh[kk][half_ * 2 + rr] = hp;
                    aPl[kk][half_ * 2 + rr] =
                        pack_f16(p0 - __half2float(__low2half(hb)),
                                 p1 - __half2float(__high2half(hb)));
                }
            }
        }

        // ---- O += (Ph+Pl) V  (2-pass) ----
#pragma unroll
        for (int kk = 0; kk < 4; kk++) {
#pragma unroll
            for (int jj = 0; jj < 4; jj++) {
                const uint32_t jx = jj * 32;
                uint32_t vh4[4];
                ldsm4t((aV[kk] ^ jx) + so, vh4);
                mma16816(O[2 * jj],     aPh[kk], vh4[0], vh4[1]);
                mma16816(O[2 * jj + 1], aPh[kk], vh4[2], vh4[3]);
                mma16816(O[2 * jj],     aPl[kk], vh4[0], vh4[1]);
                mma16816(O[2 * jj + 1], aPl[kk], vh4[2], vh4[3]);
            }
        }
        __syncthreads();
    }

    // ---- epilogue: normalize, fp16 hi/lo split ----
#pragma unroll
    for (int r2 = 0; r2 < 2; r2++) {
        const int qrow = qbase + w * 16 + group + r2 * 8;
        const float inv = 1.0f / l_i[r2];
#pragma unroll
        for (int j = 0; j < 8; j++) {
            const int col = h * DH + j * 8 + t4 * 2;
            float v0 = O[j][r2 * 2] * inv, v1 = O[j][r2 * 2 + 1] * inv;
            uint32_t hp = pack_f16(v0, v1);
            __half2 hb = *(__half2*)&hp;
            uint32_t lp = pack_f16(v0 - __half2float(__low2half(hb)),
                                   v1 - __half2float(__high2half(hb)));
            *(uint32_t*)&Oh[(size_t)qrow * DMODEL + col] = hp;
            *(uint32_t*)&Ol[(size_t)qrow * DMODEL + col] = lp;
        }
    }
}

// ---------------------------------------------------------------------------
extern "C" void kernel_launch(void* const* d_in, const int* in_sizes, int n_in,
                              void* d_out, int out_size)
{
    const float* hq   = (const float*)d_in[0];
    const float* hkv  = (const float*)d_in[1];
    const void*  mask = d_in[2];
    const float* pb   = (const float*)d_in[3];
    const float* wq   = (const float*)d_in[4];
    const float* bq   = (const float*)d_in[5];
    const float* wk   = (const float*)d_in[6];
    const float* bk   = (const float*)d_in[7];
    const float* wv   = (const float*)d_in[8];
    const float* bv   = (const float*)d_in[9];
    const float* wo   = (const float*)d_in[10];
    const float* bo   = (const float*)d_in[11];
    float* out = (float*)d_out;

    __half *xh, *xl, *wb, *qh, *ql, *kp, *vp, *ah, *al;
    cudaGetSymbolAddress((void**)&xh, g_xh);
    cudaGetSymbolAddress((void**)&xl, g_xl);
    cudaGetSymbolAddress((void**)&wb, g_wb);
    cudaGetSymbolAddress((void**)&qh, g_qh);
    cudaGetSymbolAddress((void**)&ql, g_ql);
    cudaGetSymbolAddress((void**)&kp, g_k);
    cudaGetSymbolAddress((void**)&vp, g_v);
    cudaGetSymbolAddress((void**)&ah, g_ah);
    cudaGetSymbolAddress((void**)&al, g_al);

    cudaFuncSetAttribute(gemm_mma,
                         cudaFuncAttributeMaxDynamicSharedMemorySize, GEMM_SMEM);
    cudaFuncSetAttribute(attn_mma,
                         cudaFuncAttributeMaxDynamicSharedMemorySize, ATTN_SMEM);

    detect_mask_kernel<<<1, 32>>>((const unsigned char*)mask);

    dim3 gg(DMODEL / 128, SEQ / 128);

    // Q = (hq @ wq^T + bq) * 0.125  -> fp16 hi/lo
    split_f16<<<2048, 256>>>(hq, xh, xl);
    conv_f16<<<2048, 256>>>(wq, wb);
    gemm_mma<<<gg, 256, GEMM_SMEM>>>(xh, xl, wb, bq, nullptr, qh, ql, 0.125f);

    // K, V -> single fp16
    split_f16<<<2048, 256>>>(hkv, xh, xl);
    conv_f16<<<2048, 256>>>(wk, wb);
    gemm_mma<<<gg, 256, GEMM_SMEM>>>(xh, xl, wb, bk, nullptr, kp, nullptr, 1.0f);
    conv_f16<<<2048, 256>>>(wv, wb);
    gemm_mma<<<gg, 256, GEMM_SMEM>>>(xh, xl, wb, bv, nullptr, vp, nullptr, 1.0f);

    // attention -> fp16 hi/lo
    attn_mma<<<dim3(SEQ / 64, NH), 128, ATTN_SMEM>>>(
        qh, ql, kp, vp, mask, pb, ah, al);

    // out = attn @ wo^T + bo  (fp32)
    conv_f16<<<2048, 256>>>(wo, wb);
    gemm_mma<<<gg, 256, GEMM_SMEM>>>(ah, al, wb, bo, out, nullptr, nullptr, 1.0f);
}

// round 12
// speedup vs baseline: 3.3876x; 1.0422x over previous
#include <cuda_runtime.h>
#include <cuda_fp16.h>
#include <cstdint>
#include <cstddef>

#define SEQ 2048
#define DMODEL 2048
#define NH 32
#define DH 64

// ---------------------------------------------------------------------------
// Scratch (device globals: allocation-free rule).  fp16 data path.
// ---------------------------------------------------------------------------
__device__ __half g_xh[SEQ * DMODEL];   // hq split hi
__device__ __half g_xl[SEQ * DMODEL];   // hq split lo
__device__ __half g_yh[SEQ * DMODEL];   // hkv split hi
__device__ __half g_yl[SEQ * DMODEL];   // hkv split lo
__device__ __half g_wq16[SEQ * DMODEL];
__device__ __half g_wk16[SEQ * DMODEL];
__device__ __half g_wv16[SEQ * DMODEL];
__device__ __half g_wo16[SEQ * DMODEL];
__device__ __half g_qh[SEQ * DMODEL];   // Q (pre-scaled 0.125) hi/lo
__device__ __half g_ql[SEQ * DMODEL];
__device__ __half g_k [SEQ * DMODEL];   // K single fp16
__device__ __half g_v [SEQ * DMODEL];   // V single fp16
__device__ __half g_ah[SEQ * DMODEL];   // attention out hi/lo
__device__ __half g_al[SEQ * DMODEL];
__device__ int g_mask_mode;  // 0=uint8, 1=int32, 2=float32

// ---------------------------------------------------------------------------
__global__ void detect_mask_kernel(const unsigned char* __restrict__ m) {
    if (threadIdx.x == 0) {
        int mx = 0, off = 0;
        for (int i = 0; i < 256; i++) {
            int b = m[i];
            if (b > mx) mx = b;
            if ((i & 3) && b) off = 1;
        }
        g_mask_mode = (mx > 1) ? 2 : (off ? 0 : 1);
    }
}

// ---------------------------------------------------------------------------
// Fused hi/lo split of BOTH activations (hq -> xh/xl, hkv -> yh/yl).
// grid = 4096; blocks [0,2048) do hq, [2048,4096) do hkv.
// ---------------------------------------------------------------------------
__global__ __launch_bounds__(256) void split2_f16(
    const float* __restrict__ x0, __half* __restrict__ h0, __half* __restrict__ l0,
    const float* __restrict__ x1, __half* __restrict__ h1, __half* __restrict__ l1)
{
    int b = blockIdx.x;
    const float* x; __half *hi, *lo;
    if (b < 2048) { x = x0; hi = h0; lo = l0; }
    else          { x = x1; hi = h1; lo = l1; b -= 2048; }
    size_t base = ((size_t)b * 256 + threadIdx.x) * 8;
    float4 a = *(const float4*)(x + base);
    float4 c = *(const float4*)(x + base + 4);
    float v[8] = {a.x, a.y, a.z, a.w, c.x, c.y, c.z, c.w};
    __half2 h2[4], l2[4];
#pragma unroll
    for (int i = 0; i < 4; i++) {
        float v0 = v[2 * i], v1 = v[2 * i + 1];
        __half hh0 = __float2half_rn(v0);
        __half hh1 = __float2half_rn(v1);
        h2[i] = __halves2half2(hh0, hh1);
        l2[i] = __floats2half2_rn(v0 - __half2float(hh0), v1 - __half2float(hh1));
    }
    *(uint4*)(hi + base) = *(uint4*)h2;
    *(uint4*)(lo + base) = *(uint4*)l2;
}

// ---------------------------------------------------------------------------
// Fused fp32 -> fp16 conversion of all four weight matrices.
// grid = 8192; sel = blockIdx >> 11.
// ---------------------------------------------------------------------------
__global__ __launch_bounds__(256) void conv4_f16(
    const float* __restrict__ w0, const float* __restrict__ w1,
    const float* __restrict__ w2, const float* __restrict__ w3,
    __half* __restrict__ y0, __half* __restrict__ y1,
    __half* __restrict__ y2, __half* __restrict__ y3)
{
    int sel = blockIdx.x >> 11;
    int b   = blockIdx.x & 2047;
    const float* x = (sel == 0) ? w0 : (sel == 1) ? w1 : (sel == 2) ? w2 : w3;
    __half* y      = (sel == 0) ? y0 : (sel == 1) ? y1 : (sel == 2) ? y2 : y3;
    size_t base = ((size_t)b * 256 + threadIdx.x) * 8;
    float4 a = *(const float4*)(x + base);
    float4 c = *(const float4*)(x + base + 4);
    __half2 h2[4];
    h2[0] = __floats2half2_rn(a.x, a.y);
    h2[1] = __floats2half2_rn(a.z, a.w);
    h2[2] = __floats2half2_rn(c.x, c.y);
    h2[3] = __floats2half2_rn(c.z, c.w);
    *(uint4*)(y + base) = *(uint4*)h2;
}

// ---------------------------------------------------------------------------
__device__ __forceinline__ uint32_t smem_u32(const void* p) {
    uint32_t a;
    asm("{ .reg .u64 t; cvta.to.shared.u64 t, %1; cvt.u32.u64 %0, t; }"
        : "=r"(a) : "l"(p));
    return a;
}
__device__ __forceinline__ void ldsm4(uint32_t addr, uint32_t* r) {
    asm volatile("ldmatrix.sync.aligned.m8n8.x4.shared.b16 {%0,%1,%2,%3}, [%4];"
        : "=r"(r[0]), "=r"(r[1]), "=r"(r[2]), "=r"(r[3]) : "r"(addr));
}
__device__ __forceinline__ void ldsm4t(uint32_t addr, uint32_t* r) {
    asm volatile("ldmatrix.sync.aligned.m8n8.x4.trans.shared.b16 {%0,%1,%2,%3}, [%4];"
        : "=r"(r[0]), "=r"(r[1]), "=r"(r[2]), "=r"(r[3]) : "r"(addr));
}
__device__ __forceinline__ void mma16816(float* d, const uint32_t* a,
                                         uint32_t b0, uint32_t b1) {
    asm volatile(
        "mma.sync.aligned.m16n8k16.row.col.f32.f16.f16.f32 "
        "{%0,%1,%2,%3}, {%4,%5,%6,%7}, {%8,%9}, {%0,%1,%2,%3};"
        : "+f"(d[0]), "+f"(d[1]), "+f"(d[2]), "+f"(d[3])
        : "r"(a[0]), "r"(a[1]), "r"(a[2]), "r"(a[3]), "r"(b0), "r"(b1));
}
__device__ __forceinline__ void cpa16(uint32_t s, const void* g) {
    asm volatile("cp.async.cg.shared.global [%0], [%1], 16;" :: "r"(s), "l"(g));
}
__device__ __forceinline__ uint32_t pack_f16(float a, float b) {
    __half2 h = __floats2half2_rn(a, b);
    return *(uint32_t*)&h;
}

// 32-col f16 tile (64B rows)
__device__ __forceinline__ uint32_t sw_off(int r, int c) {
    return (uint32_t)(r * 64 + ((c ^ ((r >> 1) & 3)) * 16));
}
// 64-col f16 tile (128B rows)
__device__ __forceinline__ uint32_t sw64(int r, int c) {
    return (uint32_t)(r * 128 + ((c ^ (r & 7)) * 16));
}

// ---------------------------------------------------------------------------
// HMMA GEMM (fp16 2-pass): C = (Ah+Al)[M,K] @ B[N,K]^T + bias, *scale.
// 3-stage cp.async, one barrier per k-iter.
// Stage layout (24KB): Ah +0 | Al +8192 | B +16384.
// Output: Cf fp32, or (Ch,Cl) fp16 split, or Ch single fp16 (Cl null).
// ---------------------------------------------------------------------------
#define GEMM_SMEM (3 * 24576)

__global__ __launch_bounds__(256, 2) void gemm_mma(
    const __half* __restrict__ Ah, const __half* __restrict__ Al,
    const __half* __restrict__ B,
    const float* __restrict__ bias, float* __restrict__ Cf,
    __half* __restrict__ Ch, __half* __restrict__ Cl,
    float scale)
{
    extern __shared__ __align__(1024) char sm[];
    const int t    = threadIdx.x;
    const int bm   = blockIdx.y * 128;
    const int bn   = blockIdx.x * 128;
    const int lane = t & 31;
    const int w    = t >> 5;
    const int wm   = (w & 1) * 64;
    const int wn   = (w >> 1) * 32;
    const int lr   = lane & 15;
    const int kc   = lane >> 4;
    const uint32_t smb = smem_u32(sm);

    float d[4][4][4];
#pragma unroll
    for (int i = 0; i < 4; i++)
#pragma unroll
        for (int j = 0; j < 4; j++)
#pragma unroll
            for (int r = 0; r < 4; r++) d[i][j][r] = 0.0f;

    const int r0 = t >> 2, c0 = t & 3;
    const int r1 = r0 + 64;
    const __half* srcs[3] = {Ah, Al, B};
    const __half* sp[6];
    uint32_t dst[6];
#pragma unroll
    for (int arr = 0; arr < 3; arr++) {
        const int rb = (arr < 2) ? bm : bn;
        sp[2 * arr]     = srcs[arr] + (size_t)(rb + r0) * DMODEL + c0 * 8;
        sp[2 * arr + 1] = srcs[arr] + (size_t)(rb + r1) * DMODEL + c0 * 8;
        dst[2 * arr]     = smb + arr * 8192 + sw_off(r0, c0);
        dst[2 * arr + 1] = smb + arr * 8192 + sw_off(r1, c0);
    }
    auto issue = [&](uint32_t so2, int kt) {
#pragma unroll
        for (int i = 0; i < 6; i++) cpa16(dst[i] + so2, sp[i] + kt * 32);
        asm volatile("cp.async.commit_group;");
    };

    uint32_t aA[4], aB[2];
#pragma unroll
    for (int i = 0; i < 4; i++) aA[i] = smb + sw_off(wm + i * 16 + lr, kc);
#pragma unroll
    for (int p = 0; p < 2; p++) aB[p] = smb + 16384 + sw_off(wn + p * 16 + lr, kc);

    issue(0, 0);
    issue(24576, 1);

    uint32_t so = 0, si = 49152;
#pragma unroll 1
    for (int kt = 0; kt < 64; kt++) {
        if (kt < 63) asm volatile("cp.async.wait_group 1;");
        else         asm volatile("cp.async.wait_group 0;");
        __syncthreads();
        if (kt + 2 < 64) issue(si, kt + 2);

#pragma unroll
        for (int kk = 0; kk < 2; kk++) {
            const uint32_t kx = kk * 32;
            uint32_t af[4][4], bf[2][4];
#pragma unroll
            for (int i = 0; i < 4; i++) ldsm4((aA[i] ^ kx) + so, af[i]);
#pragma unroll
            for (int p = 0; p < 2; p++) ldsm4((aB[p] ^ kx) + so, bf[p]);
            // pass 1: Ah * B
#pragma unroll
            for (int i = 0; i < 4; i++)
#pragma unroll
                for (int j = 0; j < 4; j++)
                    mma16816(d[i][j], af[i], bf[j >> 1][j & 1], bf[j >> 1][(j & 1) + 2]);
            // pass 2: Al * B  (Al tile at +8192)
#pragma unroll
            for (int i = 0; i < 4; i++) ldsm4((aA[i] ^ kx) + so + 8192, af[i]);
#pragma unroll
            for (int i = 0; i < 4; i++)
#pragma unroll
                for (int j = 0; j < 4; j++)
                    mma16816(d[i][j], af[i], bf[j >> 1][j & 1], bf[j >> 1][(j & 1) + 2]);
        }
        so = (so == 49152) ? 0 : so + 24576;
        si = (si == 49152) ? 0 : si + 24576;
    }

    const int tg = lane >> 2, t4 = lane & 3;
#pragma unroll
    for (int i = 0; i < 4; i++) {
        const int row = bm + wm + i * 16 + tg;
#pragma unroll
        for (int j = 0; j < 4; j++) {
            const int col = bn + wn + j * 8 + t4 * 2;
            const float b0 = bias[col], b1 = bias[col + 1];
            float v0 = (d[i][j][0] + b0) * scale, v1 = (d[i][j][1] + b1) * scale;
            float v2 = (d[i][j][2] + b0) * scale, v3 = (d[i][j][3] + b1) * scale;
            if (Cf) {
                *(float2*)&Cf[(size_t)row * DMODEL + col] = make_float2(v0, v1);
                *(float2*)&Cf[(size_t)(row + 8) * DMODEL + col] = make_float2(v2, v3);
            } else if (Cl) {
                uint32_t h0 = pack_f16(v0, v1), h1 = pack_f16(v2, v3);
                __half2 hh0 = *(__half2*)&h0;
                __half2 hh1 = *(__half2*)&h1;
                uint32_t l0 = pack_f16(v0 - __half2float(__low2half(hh0)),
                                       v1 - __half2float(__high2half(hh0)));
                uint32_t l1 = pack_f16(v2 - __half2float(__low2half(hh1)),
                                       v3 - __half2float(__high2half(hh1)));
                *(uint32_t*)&Ch[(size_t)row * DMODEL + col] = h0;
                *(uint32_t*)&Ch[(size_t)(row + 8) * DMODEL + col] = h1;
                *(uint32_t*)&Cl[(size_t)row * DMODEL + col] = l0;
                *(uint32_t*)&Cl[(size_t)(row + 8) * DMODEL + col] = l1;
            } else {
                *(uint32_t*)&Ch[(size_t)row * DMODEL + col] = pack_f16(v0, v1);
                *(uint32_t*)&Ch[(size_t)(row + 8) * DMODEL + col] = pack_f16(v2, v3);
            }
        }
    }
}

// ---------------------------------------------------------------------------
// Tensor-core flash attention.  Q split (2-pass QK^T); P SINGLE fp16 (1-pass
// PV — P rounding contributes only ~2.4e-4 rel).  K, V single fp16 in smem.
// Stage (16KB): K +0 | V +8192; 2 stages.
// ---------------------------------------------------------------------------
#define ATTN_SMEM (2 * 16384)

__global__ __launch_bounds__(128, 3) void attn_mma(
    const __half* __restrict__ Qh, const __half* __restrict__ Ql,
    const __half* __restrict__ K, const __half* __restrict__ V,
    const void* __restrict__ mask_raw, const float* __restrict__ pb,
    __half* __restrict__ Oh, __half* __restrict__ Ol)
{
    extern __shared__ __align__(1024) char sm[];
    const int t = threadIdx.x, lane = t & 31, w = t >> 5;
    const int lr = lane & 15, kc = lane >> 4;
    const int group = lane >> 2, t4 = lane & 3;
    const int qbase = blockIdx.x * 64;
    const int h = blockIdx.y;
    const int mode = g_mask_mode;
    const uint32_t smb = smem_u32(sm);

    const unsigned char* m8 = (const unsigned char*)mask_raw;
    const int*   m32 = (const int*)mask_raw;
    const float* mf  = (const float*)mask_raw;

    const __half* kvs[2] = {K, V};
    auto issue_kv = [&](int st, int tile) {
#pragma unroll
        for (int arr = 0; arr < 2; arr++)
#pragma unroll
            for (int i = 0; i < 4; i++) {
                int idx = t + i * 128;
                int r = idx >> 3, c = idx & 7;
                cpa16(smb + st * 16384 + arr * 8192 + sw64(r, c),
                      kvs[arr] + (size_t)(tile * 64 + r) * DMODEL + h * DH + c * 8);
            }
        asm volatile("cp.async.commit_group;");
    };
    issue_kv(0, 0);

    // ---- Q fragments in registers (a-frag layout, loaded once) ----
    uint32_t qfh[4][4], qfl[4][4];
    {
        const int g = qbase + w * 16 + group;
#pragma unroll
        for (int kk = 0; kk < 4; kk++) {
            const size_t col = (size_t)h * DH + kk * 16 + t4 * 2;
            qfh[kk][0] = *(const uint32_t*)&Qh[(size_t)g * DMODEL + col];
            qfh[kk][1] = *(const uint32_t*)&Qh[(size_t)(g + 8) * DMODEL + col];
            qfh[kk][2] = *(const uint32_t*)&Qh[(size_t)g * DMODEL + col + 8];
            qfh[kk][3] = *(const uint32_t*)&Qh[(size_t)(g + 8) * DMODEL + col + 8];
            qfl[kk][0] = *(const uint32_t*)&Ql[(size_t)g * DMODEL + col];
            qfl[kk][1] = *(const uint32_t*)&Ql[(size_t)(g + 8) * DMODEL + col];
            qfl[kk][2] = *(const uint32_t*)&Ql[(size_t)g * DMODEL + col + 8];
            qfl[kk][3] = *(const uint32_t*)&Ql[(size_t)(g + 8) * DMODEL + col + 8];
        }
    }

    uint32_t aK[4], aV[4];
#pragma unroll
    for (int p = 0; p < 4; p++) aK[p] = smb + sw64(p * 16 + lr, kc);
#pragma unroll
    for (int p = 0; p < 4; p++) aV[p] = smb + 8192 + sw64(p * 16 + lr, kc);

    float O[8][4];
    float m_i[2] = {-1e30f, -1e30f}, l_i[2] = {0.0f, 0.0f};
#pragma unroll
    for (int j = 0; j < 8; j++)
#pragma unroll
        for (int r = 0; r < 4; r++) O[j][r] = 0.0f;

#pragma unroll 1
    for (int it = 0; it < 32; it++) {
        if (it < 31) issue_kv((it + 1) & 1, it + 1);

        // ---- prefetch bias with mask folded in (-1e30 on masked lanes) ----
        float2 pbv[2][8];
#pragma unroll
        for (int r2 = 0; r2 < 2; r2++) {
            const int qrow = qbase + w * 16 + group + r2 * 8;
            const size_t prow = ((size_t)h * SEQ + qrow) * SEQ + it * 64;
            const size_t mrow = (size_t)qrow * SEQ + it * 64;
#pragma unroll
            for (int j = 0; j < 8; j++) {
                const int col = j * 8 + t4 * 2;
                float2 bv = *(const float2*)&pb[prow + col];
                int ok0, ok1;
                if (mode == 0) {
                    uchar2 mv = *(const uchar2*)&m8[mrow + col];
                    ok0 = mv.x; ok1 = mv.y;
                } else if (mode == 1) {
                    int2 mv = *(const int2*)&m32[mrow + col];
                    ok0 = mv.x; ok1 = mv.y;
                } else {
                    float2 mv = *(const float2*)&mf[mrow + col];
                    ok0 = (mv.x != 0.0f); ok1 = (mv.y != 0.0f);
                }
                pbv[r2][j].x = ok0 ? bv.x : -1e30f;
                pbv[r2][j].y = ok1 ? bv.y : -1e30f;
            }
        }

        if (it < 31) asm volatile("cp.async.wait_group 1;");
        else         asm volatile("cp.async.wait_group 0;");
        __syncthreads();

        const uint32_t so = (it & 1) * 16384;

        // ---- S = (Qh+Ql) K^T  (2-pass) ----
        float S[8][4];
#pragma unroll
        for (int j = 0; j < 8; j++)
#pragma unroll
            for (int r = 0; r < 4; r++) S[j][r] = 0.0f;

#pragma unroll
        for (int kk = 0; kk < 4; kk++) {
            const uint32_t kx = kk * 32;
            uint32_t khf[4][4];
#pragma unroll
            for (int p = 0; p < 4; p++) ldsm4((aK[p] ^ kx) + so, khf[p]);
#pragma unroll
            for (int j = 0; j < 8; j++)
                mma16816(S[j], qfh[kk], khf[j >> 1][j & 1], khf[j >> 1][(j & 1) + 2]);
#pragma unroll
            for (int j = 0; j < 8; j++)
                mma16816(S[j], qfl[kk], khf[j >> 1][j & 1], khf[j >> 1][(j & 1) + 2]);
        }

        // ---- bias(+mask) + online softmax ----
#pragma unroll
        for (int r2 = 0; r2 < 2; r2++) {
            float mx = -1e30f;
#pragma unroll
            for (int j = 0; j < 8; j++) {
                float s0 = S[j][r2 * 2]     + pbv[r2][j].x;
                float s1 = S[j][r2 * 2 + 1] + pbv[r2][j].y;
                S[j][r2 * 2] = s0; S[j][r2 * 2 + 1] = s1;
                mx = fmaxf(mx, fmaxf(s0, s1));
            }
            mx = fmaxf(mx, __shfl_xor_sync(0xffffffffu, mx, 1));
            mx = fmaxf(mx, __shfl_xor_sync(0xffffffffu, mx, 2));
            float mnew = fmaxf(m_i[r2], mx);
            float corr = __expf(m_i[r2] - mnew);
            float rsum = 0.0f;
#pragma unroll
            for (int j = 0; j < 8; j++) {
#pragma unroll
                for (int e = 0; e < 2; e++) {
                    float s = S[j][r2 * 2 + e];
                    float p = (s > -1e29f) ? __expf(s - mnew) : 0.0f;
                    S[j][r2 * 2 + e] = p;
                    rsum += p;
                }
            }
            rsum += __shfl_xor_sync(0xffffffffu, rsum, 1);
            rsum += __shfl_xor_sync(0xffffffffu, rsum, 2);
            l_i[r2] = l_i[r2] * corr + rsum;
            m_i[r2] = mnew;
#pragma unroll
            for (int j = 0; j < 8; j++) {
                O[j][r2 * 2]     *= corr;
                O[j][r2 * 2 + 1] *= corr;
            }
        }

        // ---- pack P into single-fp16 a-frags ----
        uint32_t aP[4][4];
#pragma unroll
        for (int kk = 0; kk < 4; kk++) {
#pragma unroll
            for (int half_ = 0; half_ < 2; half_++) {
                const int j = 2 * kk + half_;
#pragma unroll
                for (int rr = 0; rr < 2; rr++)
                    aP[kk][half_ * 2 + rr] = pack_f16(S[j][rr * 2], S[j][rr * 2 + 1]);
            }
        }

        // ---- O += P V  (single pass) ----
#pragma unroll
        for (int kk = 0; kk < 4; kk++) {
#pragma unroll
            for (int jj = 0; jj < 4; jj++) {
                const uint32_t jx = jj * 32;
                uint32_t vh4[4];
                ldsm4t((aV[kk] ^ jx) + so, vh4);
                mma16816(O[2 * jj],     aP[kk], vh4[0], vh4[1]);
                mma16816(O[2 * jj + 1], aP[kk], vh4[2], vh4[3]);
            }
        }
        __syncthreads();
    }

    // ---- epilogue: normalize, fp16 hi/lo split ----
#pragma unroll
    for (int r2 = 0; r2 < 2; r2++) {
        const int qrow = qbase + w * 16 + group + r2 * 8;
        const float inv = 1.0f / l_i[r2];
#pragma unroll
        for (int j = 0; j < 8; j++) {
            const int col = h * DH + j * 8 + t4 * 2;
            float v0 = O[j][r2 * 2] * inv, v1 = O[j][r2 * 2 + 1] * inv;
            uint32_t hp = pack_f16(v0, v1);
            __half2 hb = *(__half2*)&hp;
            uint32_t lp = pack_f16(v0 - __half2float(__low2half(hb)),
                                   v1 - __half2float(__high2half(hb)));
            *(uint32_t*)&Oh[(size_t)qrow * DMODEL + col] = hp;
            *(uint32_t*)&Ol[(size_t)qrow * DMODEL + col] = lp;
        }
    }
}

// ---------------------------------------------------------------------------
extern "C" void kernel_launch(void* const* d_in, const int* in_sizes, int n_in,
                              void* d_out, int out_size)
{
    const float* hq   = (const float*)d_in[0];
    const float* hkv  = (const float*)d_in[1];
    const void*  mask = d_in[2];
    const float* pb   = (const float*)d_in[3];
    const float* wq   = (const float*)d_in[4];
    const float* bq   = (const float*)d_in[5];
    const float* wk   = (const float*)d_in[6];
    const float* bk   = (const float*)d_in[7];
    const float* wv   = (const float*)d_in[8];
    const float* bv   = (const float*)d_in[9];
    const float* wo   = (const float*)d_in[10];
    const float* bo   = (const float*)d_in[11];
    float* out = (float*)d_out;

    __half *xh, *xl, *yh, *yl, *wq16, *wk16, *wv16, *wo16;
    __half *qh, *ql, *kp, *vp, *ah, *al;
    cudaGetSymbolAddress((void**)&xh, g_xh);
    cudaGetSymbolAddress((void**)&xl, g_xl);
    cudaGetSymbolAddress((void**)&yh, g_yh);
    cudaGetSymbolAddress((void**)&yl, g_yl);
    cudaGetSymbolAddress((void**)&wq16, g_wq16);
    cudaGetSymbolAddress((void**)&wk16, g_wk16);
    cudaGetSymbolAddress((void**)&wv16, g_wv16);
    cudaGetSymbolAddress((void**)&wo16, g_wo16);
    cudaGetSymbolAddress((void**)&qh, g_qh);
    cudaGetSymbolAddress((void**)&ql, g_ql);
    cudaGetSymbolAddress((void**)&kp, g_k);
    cudaGetSymbolAddress((void**)&vp, g_v);
    cudaGetSymbolAddress((void**)&ah, g_ah);
    cudaGetSymbolAddress((void**)&al, g_al);

    cudaFuncSetAttribute(gemm_mma,
                         cudaFuncAttributeMaxDynamicSharedMemorySize, GEMM_SMEM);
    cudaFuncSetAttribute(attn_mma,
                         cudaFuncAttributeMaxDynamicSharedMemorySize, ATTN_SMEM);

    detect_mask_kernel<<<1, 32>>>((const unsigned char*)mask);

    // Fused preprocessing: both activation splits, all four weight convs.
    split2_f16<<<4096, 256>>>(hq, xh, xl, hkv, yh, yl);
    conv4_f16<<<8192, 256>>>(wq, wk, wv, wo, wq16, wk16, wv16, wo16);

    dim3 gg(DMODEL / 128, SEQ / 128);

    // Q = (hq @ wq^T + bq) * 0.125  -> fp16 hi/lo
    gemm_mma<<<gg, 256, GEMM_SMEM>>>(xh, xl, wq16, bq, nullptr, qh, ql, 0.125f);
    // K, V -> single fp16
    gemm_mma<<<gg, 256, GEMM_SMEM>>>(yh, yl, wk16, bk, nullptr, kp, nullptr, 1.0f);
    gemm_mma<<<gg, 256, GEMM_SMEM>>>(yh, yl, wv16, bv, nullptr, vp, nullptr, 1.0f);

    // attention -> fp16 hi/lo
    attn_mma<<<dim3(SEQ / 64, NH), 128, ATTN_SMEM>>>(
        qh, ql, kp, vp, mask, pb, ah, al);

    // out = attn @ wo^T + bo  (fp32)
    gemm_mma<<<gg, 256, GEMM_SMEM>>>(ah, al, wo16, bo, out, nullptr, nullptr, 1.0f);
}

// round 13
// speedup vs baseline: 3.4946x; 1.0316x over previous
#include <cuda_runtime.h>
#include <cuda_fp16.h>
#include <cstdint>
#include <cstddef>

#define SEQ 2048
#define DMODEL 2048
#define NH 32
#define DH 64

// ---------------------------------------------------------------------------
// Scratch (device globals: allocation-free rule).  fp16 data path.
// Error budget (quadrature, each single-fp16 rounding ~2.4e-4):
//   wq,wk,wv,wo single  : 4 terms   (rounds 11-12, measured base 5.25e-4)
//   P single            : 1 term
//   Q single (this rnd) : ~3e-4
//   => predicted ~6.1e-4  (gate 1e-3)
// ---------------------------------------------------------------------------
__device__ __half g_xh[SEQ * DMODEL];   // hq split hi
__device__ __half g_xl[SEQ * DMODEL];   // hq split lo
__device__ __half g_yh[SEQ * DMODEL];   // hkv split hi
__device__ __half g_yl[SEQ * DMODEL];   // hkv split lo
__device__ __half g_wq16[SEQ * DMODEL];
__device__ __half g_wk16[SEQ * DMODEL];
__device__ __half g_wv16[SEQ * DMODEL];
__device__ __half g_wo16[SEQ * DMODEL];
__device__ __half g_q [SEQ * DMODEL];   // Q single fp16 (pre-scaled 0.125)
__device__ __half g_k [SEQ * DMODEL];   // K single fp16
__device__ __half g_v [SEQ * DMODEL];   // V single fp16
__device__ __half g_ah[SEQ * DMODEL];   // attention out hi/lo
__device__ __half g_al[SEQ * DMODEL];
__device__ int g_mask_mode;  // 0=uint8, 1=int32, 2=float32

// ---------------------------------------------------------------------------
__global__ void detect_mask_kernel(const unsigned char* __restrict__ m) {
    if (threadIdx.x == 0) {
        int mx = 0, off = 0;
        for (int i = 0; i < 256; i++) {
            int b = m[i];
            if (b > mx) mx = b;
            if ((i & 3) && b) off = 1;
        }
        g_mask_mode = (mx > 1) ? 2 : (off ? 0 : 1);
    }
}

// ---------------------------------------------------------------------------
// Fused hi/lo split of BOTH activations (hq -> xh/xl, hkv -> yh/yl).
// ---------------------------------------------------------------------------
__global__ __launch_bounds__(256) void split2_f16(
    const float* __restrict__ x0, __half* __restrict__ h0, __half* __restrict__ l0,
    const float* __restrict__ x1, __half* __restrict__ h1, __half* __restrict__ l1)
{
    int b = blockIdx.x;
    const float* x; __half *hi, *lo;
    if (b < 2048) { x = x0; hi = h0; lo = l0; }
    else          { x = x1; hi = h1; lo = l1; b -= 2048; }
    size_t base = ((size_t)b * 256 + threadIdx.x) * 8;
    float4 a = *(const float4*)(x + base);
    float4 c = *(const float4*)(x + base + 4);
    float v[8] = {a.x, a.y, a.z, a.w, c.x, c.y, c.z, c.w};
    __half2 h2[4], l2[4];
#pragma unroll
    for (int i = 0; i < 4; i++) {
        float v0 = v[2 * i], v1 = v[2 * i + 1];
        __half hh0 = __float2half_rn(v0);
        __half hh1 = __float2half_rn(v1);
        h2[i] = __halves2half2(hh0, hh1);
        l2[i] = __floats2half2_rn(v0 - __half2float(hh0), v1 - __half2float(hh1));
    }
    *(uint4*)(hi + base) = *(uint4*)h2;
    *(uint4*)(lo + base) = *(uint4*)l2;
}

// ---------------------------------------------------------------------------
// Fused fp32 -> fp16 conversion of all four weight matrices.
// ---------------------------------------------------------------------------
__global__ __launch_bounds__(256) void conv4_f16(
    const float* __restrict__ w0, const float* __restrict__ w1,
    const float* __restrict__ w2, const float* __restrict__ w3,
    __half* __restrict__ y0, __half* __restrict__ y1,
    __half* __restrict__ y2, __half* __restrict__ y3)
{
    int sel = blockIdx.x >> 11;
    int b   = blockIdx.x & 2047;
    const float* x = (sel == 0) ? w0 : (sel == 1) ? w1 : (sel == 2) ? w2 : w3;
    __half* y      = (sel == 0) ? y0 : (sel == 1) ? y1 : (sel == 2) ? y2 : y3;
    size_t base = ((size_t)b * 256 + threadIdx.x) * 8;
    float4 a = *(const float4*)(x + base);
    float4 c = *(const float4*)(x + base + 4);
    __half2 h2[4];
    h2[0] = __floats2half2_rn(a.x, a.y);
    h2[1] = __floats2half2_rn(a.z, a.w);
    h2[2] = __floats2half2_rn(c.x, c.y);
    h2[3] = __floats2half2_rn(c.z, c.w);
    *(uint4*)(y + base) = *(uint4*)h2;
}

// ---------------------------------------------------------------------------
__device__ __forceinline__ uint32_t smem_u32(const void* p) {
    uint32_t a;
    asm("{ .reg .u64 t; cvta.to.shared.u64 t, %1; cvt.u32.u64 %0, t; }"
        : "=r"(a) : "l"(p));
    return a;
}
__device__ __forceinline__ void ldsm4(uint32_t addr, uint32_t* r) {
    asm volatile("ldmatrix.sync.aligned.m8n8.x4.shared.b16 {%0,%1,%2,%3}, [%4];"
        : "=r"(r[0]), "=r"(r[1]), "=r"(r[2]), "=r"(r[3]) : "r"(addr));
}
__device__ __forceinline__ void ldsm4t(uint32_t addr, uint32_t* r) {
    asm volatile("ldmatrix.sync.aligned.m8n8.x4.trans.shared.b16 {%0,%1,%2,%3}, [%4];"
        : "=r"(r[0]), "=r"(r[1]), "=r"(r[2]), "=r"(r[3]) : "r"(addr));
}
__device__ __forceinline__ void mma16816(float* d, const uint32_t* a,
                                         uint32_t b0, uint32_t b1) {
    asm volatile(
        "mma.sync.aligned.m16n8k16.row.col.f32.f16.f16.f32 "
        "{%0,%1,%2,%3}, {%4,%5,%6,%7}, {%8,%9}, {%0,%1,%2,%3};"
        : "+f"(d[0]), "+f"(d[1]), "+f"(d[2]), "+f"(d[3])
        : "r"(a[0]), "r"(a[1]), "r"(a[2]), "r"(a[3]), "r"(b0), "r"(b1));
}
__device__ __forceinline__ void cpa16(uint32_t s, const void* g) {
    asm volatile("cp.async.cg.shared.global [%0], [%1], 16;" :: "r"(s), "l"(g));
}
__device__ __forceinline__ uint32_t pack_f16(float a, float b) {
    __half2 h = __floats2half2_rn(a, b);
    return *(uint32_t*)&h;
}

// 32-col f16 tile (64B rows)
__device__ __forceinline__ uint32_t sw_off(int r, int c) {
    return (uint32_t)(r * 64 + ((c ^ ((r >> 1) & 3)) * 16));
}
// 64-col f16 tile (128B rows)
__device__ __forceinline__ uint32_t sw64(int r, int c) {
    return (uint32_t)(r * 128 + ((c ^ (r & 7)) * 16));
}

// ---------------------------------------------------------------------------
// Shared GEMM body (fp16 2-pass): C = (Ah+Al)[M,K] @ B[N,K]^T + bias, *scale.
// 3-stage cp.async, one barrier per k-iter.
// Stage layout (24KB): Ah +0 | Al +8192 | B +16384.
// Output: Cf fp32, or (Ch,Cl) fp16 split, or Ch single fp16 (Cl null).
// ---------------------------------------------------------------------------
#define GEMM_SMEM (3 * 24576)

__device__ __forceinline__ void gemm_body(
    const __half* __restrict__ Ah, const __half* __restrict__ Al,
    const __half* __restrict__ B,
    const float* __restrict__ bias, float* __restrict__ Cf,
    __half* __restrict__ Ch, __half* __restrict__ Cl,
    float scale, char* sm)
{
    const int t    = threadIdx.x;
    const int bm   = blockIdx.y * 128;
    const int bn   = blockIdx.x * 128;
    const int lane = t & 31;
    const int w    = t >> 5;
    const int wm   = (w & 1) * 64;
    const int wn   = (w >> 1) * 32;
    const int lr   = lane & 15;
    const int kc   = lane >> 4;
    const uint32_t smb = smem_u32(sm);

    float d[4][4][4];
#pragma unroll
    for (int i = 0; i < 4; i++)
#pragma unroll
        for (int j = 0; j < 4; j++)
#pragma unroll
            for (int r = 0; r < 4; r++) d[i][j][r] = 0.0f;

    const int r0 = t >> 2, c0 = t & 3;
    const int r1 = r0 + 64;
    const __half* srcs[3] = {Ah, Al, B};
    const __half* sp[6];
    uint32_t dst[6];
#pragma unroll
    for (int arr = 0; arr < 3; arr++) {
        const int rb = (arr < 2) ? bm : bn;
        sp[2 * arr]     = srcs[arr] + (size_t)(rb + r0) * DMODEL + c0 * 8;
        sp[2 * arr + 1] = srcs[arr] + (size_t)(rb + r1) * DMODEL + c0 * 8;
        dst[2 * arr]     = smb + arr * 8192 + sw_off(r0, c0);
        dst[2 * arr + 1] = smb + arr * 8192 + sw_off(r1, c0);
    }
    auto issue = [&](uint32_t so2, int kt) {
#pragma unroll
        for (int i = 0; i < 6; i++) cpa16(dst[i] + so2, sp[i] + kt * 32);
        asm volatile("cp.async.commit_group;");
    };

    uint32_t aA[4], aB[2];
#pragma unroll
    for (int i = 0; i < 4; i++) aA[i] = smb + sw_off(wm + i * 16 + lr, kc);
#pragma unroll
    for (int p = 0; p < 2; p++) aB[p] = smb + 16384 + sw_off(wn + p * 16 + lr, kc);

    issue(0, 0);
    issue(24576, 1);

    uint32_t so = 0, si = 49152;
#pragma unroll 1
    for (int kt = 0; kt < 64; kt++) {
        if (kt < 63) asm volatile("cp.async.wait_group 1;");
        else         asm volatile("cp.async.wait_group 0;");
        __syncthreads();
        if (kt + 2 < 64) issue(si, kt + 2);

#pragma unroll
        for (int kk = 0; kk < 2; kk++) {
            const uint32_t kx = kk * 32;
            uint32_t af[4][4], bf[2][4];
#pragma unroll
            for (int i = 0; i < 4; i++) ldsm4((aA[i] ^ kx) + so, af[i]);
#pragma unroll
            for (int p = 0; p < 2; p++) ldsm4((aB[p] ^ kx) + so, bf[p]);
            // pass 1: Ah * B
#pragma unroll
            for (int i = 0; i < 4; i++)
#pragma unroll
                for (int j = 0; j < 4; j++)
                    mma16816(d[i][j], af[i], bf[j >> 1][j & 1], bf[j >> 1][(j & 1) + 2]);
            // pass 2: Al * B  (Al tile at +8192)
#pragma unroll
            for (int i = 0; i < 4; i++) ldsm4((aA[i] ^ kx) + so + 8192, af[i]);
#pragma unroll
            for (int i = 0; i < 4; i++)
#pragma unroll
                for (int j = 0; j < 4; j++)
                    mma16816(d[i][j], af[i], bf[j >> 1][j & 1], bf[j >> 1][(j & 1) + 2]);
        }
        so = (so == 49152) ? 0 : so + 24576;
        si = (si == 49152) ? 0 : si + 24576;
    }

    const int tg = lane >> 2, t4 = lane & 3;
#pragma unroll
    for (int i = 0; i < 4; i++) {
        const int row = bm + wm + i * 16 + tg;
#pragma unroll
        for (int j = 0; j < 4; j++) {
            const int col = bn + wn + j * 8 + t4 * 2;
            const float b0 = bias[col], b1 = bias[col + 1];
            float v0 = (d[i][j][0] + b0) * scale, v1 = (d[i][j][1] + b1) * scale;
            float v2 = (d[i][j][2] + b0) * scale, v3 = (d[i][j][3] + b1) * scale;
            if (Cf) {
                *(float2*)&Cf[(size_t)row * DMODEL + col] = make_float2(v0, v1);
                *(float2*)&Cf[(size_t)(row + 8) * DMODEL + col] = make_float2(v2, v3);
            } else if (Cl) {
                uint32_t h0 = pack_f16(v0, v1), h1 = pack_f16(v2, v3);
                __half2 hh0 = *(__half2*)&h0;
                __half2 hh1 = *(__half2*)&h1;
                uint32_t l0 = pack_f16(v0 - __half2float(__low2half(hh0)),
                                       v1 - __half2float(__high2half(hh0)));
                uint32_t l1 = pack_f16(v2 - __half2float(__low2half(hh1)),
                                       v3 - __half2float(__high2half(hh1)));
                *(uint32_t*)&Ch[(size_t)row * DMODEL + col] = h0;
                *(uint32_t*)&Ch[(size_t)(row + 8) * DMODEL + col] = h1;
                *(uint32_t*)&Cl[(size_t)row * DMODEL + col] = l0;
                *(uint32_t*)&Cl[(size_t)(row + 8) * DMODEL + col] = l1;
            } else {
                *(uint32_t*)&Ch[(size_t)row * DMODEL + col] = pack_f16(v0, v1);
                *(uint32_t*)&Ch[(size_t)(row + 8) * DMODEL + col] = pack_f16(v2, v3);
            }
        }
    }
}

// Merged Q/K/V projection: grid (16,16,3); z selects operands.
__global__ __launch_bounds__(256, 2) void gemm_qkv(
    const __half* __restrict__ xh, const __half* __restrict__ xl,
    const __half* __restrict__ yh, const __half* __restrict__ yl,
    const __half* __restrict__ wq, const __half* __restrict__ wk,
    const __half* __restrict__ wv,
    const float* __restrict__ bq, const float* __restrict__ bk,
    const float* __restrict__ bv,
    __half* __restrict__ q, __half* __restrict__ k, __half* __restrict__ v)
{
    extern __shared__ __align__(1024) char sm[];
    const int z = blockIdx.z;
    const __half* Ah = (z == 0) ? xh : yh;
    const __half* Al = (z == 0) ? xl : yl;
    const __half* B  = (z == 0) ? wq : (z == 1) ? wk : wv;
    const float* bias = (z == 0) ? bq : (z == 1) ? bk : bv;
    __half* C = (z == 0) ? q : (z == 1) ? k : v;
    const float scale = (z == 0) ? 0.125f : 1.0f;
    gemm_body(Ah, Al, B, bias, nullptr, C, nullptr, scale, sm);
}

// Output projection: fp32 out, split A.
__global__ __launch_bounds__(256, 2) void gemm_out(
    const __half* __restrict__ Ah, const __half* __restrict__ Al,
    const __half* __restrict__ B,
    const float* __restrict__ bias, float* __restrict__ Cf)
{
    extern __shared__ __align__(1024) char sm[];
    gemm_body(Ah, Al, B, bias, Cf, nullptr, nullptr, 1.0f, sm);
}

// ---------------------------------------------------------------------------
// Tensor-core flash attention.  Q single fp16 in registers (1-pass QK^T);
// P single fp16 (1-pass PV).  K, V single fp16 in smem.
// Stage (16KB): K +0 | V +8192; 2 stages.
// ---------------------------------------------------------------------------
#define ATTN_SMEM (2 * 16384)

__global__ __launch_bounds__(128, 3) void attn_mma(
    const __half* __restrict__ Q,
    const __half* __restrict__ K, const __half* __restrict__ V,
    const void* __restrict__ mask_raw, const float* __restrict__ pb,
    __half* __restrict__ Oh, __half* __restrict__ Ol)
{
    extern __shared__ __align__(1024) char sm[];
    const int t = threadIdx.x, lane = t & 31, w = t >> 5;
    const int lr = lane & 15, kc = lane >> 4;
    const int group = lane >> 2, t4 = lane & 3;
    const int qbase = blockIdx.x * 64;
    const int h = blockIdx.y;
    const int mode = g_mask_mode;
    const uint32_t smb = smem_u32(sm);

    const unsigned char* m8 = (const unsigned char*)mask_raw;
    const int*   m32 = (const int*)mask_raw;
    const float* mf  = (const float*)mask_raw;

    const __half* kvs[2] = {K, V};
    auto issue_kv = [&](int st, int tile) {
#pragma unroll
        for (int arr = 0; arr < 2; arr++)
#pragma unroll
            for (int i = 0; i < 4; i++) {
                int idx = t + i * 128;
                int r = idx >> 3, c = idx & 7;
                cpa16(smb + st * 16384 + arr * 8192 + sw64(r, c),
                      kvs[arr] + (size_t)(tile * 64 + r) * DMODEL + h * DH + c * 8);
            }
        asm volatile("cp.async.commit_group;");
    };
    issue_kv(0, 0);

    // ---- Q fragments in registers (a-frag layout, loaded once) ----
    uint32_t qf[4][4];
    {
        const int g = qbase + w * 16 + group;
#pragma unroll
        for (int kk = 0; kk < 4; kk++) {
            const size_t col = (size_t)h * DH + kk * 16 + t4 * 2;
            qf[kk][0] = *(const uint32_t*)&Q[(size_t)g * DMODEL + col];
            qf[kk][1] = *(const uint32_t*)&Q[(size_t)(g + 8) * DMODEL + col];
            qf[kk][2] = *(const uint32_t*)&Q[(size_t)g * DMODEL + col + 8];
            qf[kk][3] = *(const uint32_t*)&Q[(size_t)(g + 8) * DMODEL + col + 8];
        }
    }

    uint32_t aK[4], aV[4];
#pragma unroll
    for (int p = 0; p < 4; p++) aK[p] = smb + sw64(p * 16 + lr, kc);
#pragma unroll
    for (int p = 0; p < 4; p++) aV[p] = smb + 8192 + sw64(p * 16 + lr, kc);

    float O[8][4];
    float m_i[2] = {-1e30f, -1e30f}, l_i[2] = {0.0f, 0.0f};
#pragma unroll
    for (int j = 0; j < 8; j++)
#pragma unroll
        for (int r = 0; r < 4; r++) O[j][r] = 0.0f;

#pragma unroll 1
    for (int it = 0; it < 32; it++) {
        if (it < 31) issue_kv((it + 1) & 1, it + 1);

        // ---- prefetch bias with mask folded in (-1e30 on masked lanes) ----
        float2 pbv[2][8];
#pragma unroll
        for (int r2 = 0; r2 < 2; r2++) {
            const int qrow = qbase + w * 16 + group + r2 * 8;
            const size_t prow = ((size_t)h * SEQ + qrow) * SEQ + it * 64;
            const size_t mrow = (size_t)qrow * SEQ + it * 64;
#pragma unroll
            for (int j = 0; j < 8; j++) {
                const int col = j * 8 + t4 * 2;
                float2 bv = *(const float2*)&pb[prow + col];
                int ok0, ok1;
                if (mode == 0) {
                    uchar2 mv = *(const uchar2*)&m8[mrow + col];
                    ok0 = mv.x; ok1 = mv.y;
                } else if (mode == 1) {
                    int2 mv = *(const int2*)&m32[mrow + col];
                    ok0 = mv.x; ok1 = mv.y;
                } else {
                    float2 mv = *(const float2*)&mf[mrow + col];
                    ok0 = (mv.x != 0.0f); ok1 = (mv.y != 0.0f);
                }
                pbv[r2][j].x = ok0 ? bv.x : -1e30f;
                pbv[r2][j].y = ok1 ? bv.y : -1e30f;
            }
        }

        if (it < 31) asm volatile("cp.async.wait_group 1;");
        else         asm volatile("cp.async.wait_group 0;");
        __syncthreads();

        const uint32_t so = (it & 1) * 16384;

        // ---- S = Q K^T  (single pass) ----
        float S[8][4];
#pragma unroll
        for (int j = 0; j < 8; j++)
#pragma unroll
            for (int r = 0; r < 4; r++) S[j][r] = 0.0f;

#pragma unroll
        for (int kk = 0; kk < 4; kk++) {
            const uint32_t kx = kk * 32;
            uint32_t khf[4][4];
#pragma unroll
            for (int p = 0; p < 4; p++) ldsm4((aK[p] ^ kx) + so, khf[p]);
#pragma unroll
            for (int j = 0; j < 8; j++)
                mma16816(S[j], qf[kk], khf[j >> 1][j & 1], khf[j >> 1][(j & 1) + 2]);
        }

        // ---- bias(+mask) + online softmax ----
#pragma unroll
        for (int r2 = 0; r2 < 2; r2++) {
            float mx = -1e30f;
#pragma unroll
            for (int j = 0; j < 8; j++) {
                float s0 = S[j][r2 * 2]     + pbv[r2][j].x;
                float s1 = S[j][r2 * 2 + 1] + pbv[r2][j].y;
                S[j][r2 * 2] = s0; S[j][r2 * 2 + 1] = s1;
                mx = fmaxf(mx, fmaxf(s0, s1));
            }
            mx = fmaxf(mx, __shfl_xor_sync(0xffffffffu, mx, 1));
            mx = fmaxf(mx, __shfl_xor_sync(0xffffffffu, mx, 2));
            float mnew = fmaxf(m_i[r2], mx);
            float corr = __expf(m_i[r2] - mnew);
            float rsum = 0.0f;
#pragma unroll
            for (int j = 0; j < 8; j++) {
#pragma unroll
                for (int e = 0; e < 2; e++) {
                    float s = S[j][r2 * 2 + e];
                    float p = (s > -1e29f) ? __expf(s - mnew) : 0.0f;
                    S[j][r2 * 2 + e] = p;
                    rsum += p;
                }
            }
            rsum += __shfl_xor_sync(0xffffffffu, rsum, 1);
            rsum += __shfl_xor_sync(0xffffffffu, rsum, 2);
            l_i[r2] = l_i[r2] * corr + rsum;
            m_i[r2] = mnew;
#pragma unroll
            for (int j = 0; j < 8; j++) {
                O[j][r2 * 2]     *= corr;
                O[j][r2 * 2 + 1] *= corr;
            }
        }

        // ---- pack P into single-fp16 a-frags ----
        uint32_t aP[4][4];
#pragma unroll
        for (int kk = 0; kk < 4; kk++) {
#pragma unroll
            for (int half_ = 0; half_ < 2; half_++) {
                const int j = 2 * kk + half_;
#pragma unroll
                for (int rr = 0; rr < 2; rr++)
                    aP[kk][half_ * 2 + rr] = pack_f16(S[j][rr * 2], S[j][rr * 2 + 1]);
            }
        }

        // ---- O += P V  (single pass) ----
#pragma unroll
        for (int kk = 0; kk < 4; kk++) {
#pragma unroll
            for (int jj = 0; jj < 4; jj++) {
                const uint32_t jx = jj * 32;
                uint32_t vh4[4];
                ldsm4t((aV[kk] ^ jx) + so, vh4);
                mma16816(O[2 * jj],     aP[kk], vh4[0], vh4[1]);
                mma16816(O[2 * jj + 1], aP[kk], vh4[2], vh4[3]);
            }
        }
        __syncthreads();
    }

    // ---- epilogue: normalize, fp16 hi/lo split ----
#pragma unroll
    for (int r2 = 0; r2 < 2; r2++) {
        const int qrow = qbase + w * 16 + group + r2 * 8;
        const float inv = 1.0f / l_i[r2];
#pragma unroll
        for (int j = 0; j < 8; j++) {
            const int col = h * DH + j * 8 + t4 * 2;
            float v0 = O[j][r2 * 2] * inv, v1 = O[j][r2 * 2 + 1] * inv;
            uint32_t hp = pack_f16(v0, v1);
            __half2 hb = *(__half2*)&hp;
            uint32_t lp = pack_f16(v0 - __half2float(__low2half(hb)),
                                   v1 - __half2float(__high2half(hb)));
            *(uint32_t*)&Oh[(size_t)qrow * DMODEL + col] = hp;
            *(uint32_t*)&Ol[(size_t)qrow * DMODEL + col] = lp;
        }
    }
}

// ---------------------------------------------------------------------------
extern "C" void kernel_launch(void* const* d_in, const int* in_sizes, int n_in,
                              void* d_out, int out_size)
{
    const float* hq   = (const float*)d_in[0];
    const float* hkv  = (const float*)d_in[1];
    const void*  mask = d_in[2];
    const float* pb   = (const float*)d_in[3];
    const float* wq   = (const float*)d_in[4];
    const float* bq   = (const float*)d_in[5];
    const float* wk   = (const float*)d_in[6];
    const float* bk   = (const float*)d_in[7];
    const float* wv   = (const float*)d_in[8];
    const float* bv   = (const float*)d_in[9];
    const float* wo   = (const float*)d_in[10];
    const float* bo   = (const float*)d_in[11];
    float* out = (float*)d_out;

    __half *xh, *xl, *yh, *yl, *wq16, *wk16, *wv16, *wo16;
    __half *qp, *kp, *vp, *ah, *al;
    cudaGetSymbolAddress((void**)&xh, g_xh);
    cudaGetSymbolAddress((void**)&xl, g_xl);
    cudaGetSymbolAddress((void**)&yh, g_yh);
    cudaGetSymbolAddress((void**)&yl, g_yl);
    cudaGetSymbolAddress((void**)&wq16, g_wq16);
    cudaGetSymbolAddress((void**)&wk16, g_wk16);
    cudaGetSymbolAddress((void**)&wv16, g_wv16);
    cudaGetSymbolAddress((void**)&wo16, g_wo16);
    cudaGetSymbolAddress((void**)&qp, g_q);
    cudaGetSymbolAddress((void**)&kp, g_k);
    cudaGetSymbolAddress((void**)&vp, g_v);
    cudaGetSymbolAddress((void**)&ah, g_ah);
    cudaGetSymbolAddress((void**)&al, g_al);

    cudaFuncSetAttribute(gemm_qkv,
                         cudaFuncAttributeMaxDynamicSharedMemorySize, GEMM_SMEM);
    cudaFuncSetAttribute(gemm_out,
                         cudaFuncAttributeMaxDynamicSharedMemorySize, GEMM_SMEM);
    cudaFuncSetAttribute(attn_mma,
                         cudaFuncAttributeMaxDynamicSharedMemorySize, ATTN_SMEM);

    detect_mask_kernel<<<1, 32>>>((const unsigned char*)mask);

    // Fused preprocessing: both activation splits, all four weight convs.
    split2_f16<<<4096, 256>>>(hq, xh, xl, hkv, yh, yl);
    conv4_f16<<<8192, 256>>>(wq, wk, wv, wo, wq16, wk16, wv16, wo16);

    // Q, K, V projections in one launch (z = 0,1,2).
    gemm_qkv<<<dim3(DMODEL / 128, SEQ / 128, 3), 256, GEMM_SMEM>>>(
        xh, xl, yh, yl, wq16, wk16, wv16, bq, bk, bv, qp, kp, vp);

    // attention -> fp16 hi/lo
    attn_mma<<<dim3(SEQ / 64, NH), 128, ATTN_SMEM>>>(
        qp, kp, vp, mask, pb, ah, al);

    // out = attn @ wo^T + bo  (fp32)
    gemm_out<<<dim3(DMODEL / 128, SEQ / 128), 256, GEMM_SMEM>>>(
        ah, al, wo16, bo, out);
}

// round 14
// speedup vs baseline: 4.7579x; 1.3615x over previous
#include <cuda_runtime.h>
#include <cuda_fp16.h>
#include <cstdint>
#include <cstddef>

#define SEQ 2048
#define DMODEL 2048
#define NH 32
#define DH 64

// ---------------------------------------------------------------------------
// Scratch (device globals: allocation-free rule).  All-fp16 data path.
// Error budget (quadrature, ~2.0e-4 per single-fp16 rounding, calibrated
// rounds 11-13): 8 prior terms (5.66e-4 measured) + hq + 2x hkv + attn-out
// => ~12-13 terms => ~7.2e-4 predicted (gate 1e-3).
// ---------------------------------------------------------------------------
__device__ __half g_x16[SEQ * DMODEL];   // hq fp16
__device__ __half g_y16[SEQ * DMODEL];   // hkv fp16
__device__ __half g_wq16[SEQ * DMODEL];
__device__ __half g_wk16[SEQ * DMODEL];
__device__ __half g_wv16[SEQ * DMODEL];
__device__ __half g_wo16[SEQ * DMODEL];
__device__ __half g_q [SEQ * DMODEL];    // Q fp16 (pre-scaled 0.125)
__device__ __half g_k [SEQ * DMODEL];    // K fp16
__device__ __half g_v [SEQ * DMODEL];    // V fp16
__device__ __half g_a [SEQ * DMODEL];    // attention out fp16
__device__ int g_mask_mode;  // 0=uint8, 1=int32, 2=float32

// ---------------------------------------------------------------------------
__global__ void detect_mask_kernel(const unsigned char* __restrict__ m) {
    if (threadIdx.x == 0) {
        int mx = 0, off = 0;
        for (int i = 0; i < 256; i++) {
            int b = m[i];
            if (b > mx) mx = b;
            if ((i & 3) && b) off = 1;
        }
        g_mask_mode = (mx > 1) ? 2 : (off ? 0 : 1);
    }
}

// ---------------------------------------------------------------------------
// Fused fp32 -> fp16 conversion of all six fp32 sources.
// grid = 6 * 2048; sel = blockIdx.x / 2048.
// ---------------------------------------------------------------------------
__global__ __launch_bounds__(256) void conv6_f16(
    const float* __restrict__ s0, const float* __restrict__ s1,
    const float* __restrict__ s2, const float* __restrict__ s3,
    const float* __restrict__ s4, const float* __restrict__ s5,
    __half* __restrict__ d0, __half* __restrict__ d1,
    __half* __restrict__ d2, __half* __restrict__ d3,
    __half* __restrict__ d4, __half* __restrict__ d5)
{
    int sel = blockIdx.x >> 11;
    int b   = blockIdx.x & 2047;
    const float* x = (sel == 0) ? s0 : (sel == 1) ? s1 : (sel == 2) ? s2
                   : (sel == 3) ? s3 : (sel == 4) ? s4 : s5;
    __half* y      = (sel == 0) ? d0 : (sel == 1) ? d1 : (sel == 2) ? d2
                   : (sel == 3) ? d3 : (sel == 4) ? d4 : d5;
    size_t base = ((size_t)b * 256 + threadIdx.x) * 8;
    float4 a = *(const float4*)(x + base);
    float4 c = *(const float4*)(x + base + 4);
    __half2 h2[4];
    h2[0] = __floats2half2_rn(a.x, a.y);
    h2[1] = __floats2half2_rn(a.z, a.w);
    h2[2] = __floats2half2_rn(c.x, c.y);
    h2[3] = __floats2half2_rn(c.z, c.w);
    *(uint4*)(y + base) = *(uint4*)h2;
}

// ---------------------------------------------------------------------------
__device__ __forceinline__ uint32_t smem_u32(const void* p) {
    uint32_t a;
    asm("{ .reg .u64 t; cvta.to.shared.u64 t, %1; cvt.u32.u64 %0, t; }"
        : "=r"(a) : "l"(p));
    return a;
}
__device__ __forceinline__ void ldsm4(uint32_t addr, uint32_t* r) {
    asm volatile("ldmatrix.sync.aligned.m8n8.x4.shared.b16 {%0,%1,%2,%3}, [%4];"
        : "=r"(r[0]), "=r"(r[1]), "=r"(r[2]), "=r"(r[3]) : "r"(addr));
}
__device__ __forceinline__ void ldsm4t(uint32_t addr, uint32_t* r) {
    asm volatile("ldmatrix.sync.aligned.m8n8.x4.trans.shared.b16 {%0,%1,%2,%3}, [%4];"
        : "=r"(r[0]), "=r"(r[1]), "=r"(r[2]), "=r"(r[3]) : "r"(addr));
}
__device__ __forceinline__ void mma16816(float* d, const uint32_t* a,
                                         uint32_t b0, uint32_t b1) {
    asm volatile(
        "mma.sync.aligned.m16n8k16.row.col.f32.f16.f16.f32 "
        "{%0,%1,%2,%3}, {%4,%5,%6,%7}, {%8,%9}, {%0,%1,%2,%3};"
        : "+f"(d[0]), "+f"(d[1]), "+f"(d[2]), "+f"(d[3])
        : "r"(a[0]), "r"(a[1]), "r"(a[2]), "r"(a[3]), "r"(b0), "r"(b1));
}
__device__ __forceinline__ void cpa16(uint32_t s, const void* g) {
    asm volatile("cp.async.cg.shared.global [%0], [%1], 16;" :: "r"(s), "l"(g));
}
__device__ __forceinline__ uint32_t pack_f16(float a, float b) {
    __half2 h = __floats2half2_rn(a, b);
    return *(uint32_t*)&h;
}

// 32-col f16 tile (64B rows)
__device__ __forceinline__ uint32_t sw_off(int r, int c) {
    return (uint32_t)(r * 64 + ((c ^ ((r >> 1) & 3)) * 16));
}
// 64-col f16 tile (128B rows)
__device__ __forceinline__ uint32_t sw64(int r, int c) {
    return (uint32_t)(r * 128 + ((c ^ (r & 7)) * 16));
}

// ---------------------------------------------------------------------------
// Shared GEMM body (fp16 1-pass): C = A[M,K] @ B[N,K]^T + bias, *scale.
// 3-stage cp.async, one barrier per k-iter.
// Stage layout (16KB): A +0 | B +8192.
// Output: Cf fp32 if non-null, else Ch fp16.
// ---------------------------------------------------------------------------
#define GEMM_SMEM (3 * 16384)

__device__ __forceinline__ void gemm_body(
    const __half* __restrict__ A, const __half* __restrict__ B,
    const float* __restrict__ bias, float* __restrict__ Cf,
    __half* __restrict__ Ch, float scale, char* sm)
{
    const int t    = threadIdx.x;
    const int bm   = blockIdx.y * 128;
    const int bn   = blockIdx.x * 128;
    const int lane = t & 31;
    const int w    = t >> 5;
    const int wm   = (w & 1) * 64;
    const int wn   = (w >> 1) * 32;
    const int lr   = lane & 15;
    const int kc   = lane >> 4;
    const uint32_t smb = smem_u32(sm);

    float d[4][4][4];
#pragma unroll
    for (int i = 0; i < 4; i++)
#pragma unroll
        for (int j = 0; j < 4; j++)
#pragma unroll
            for (int r = 0; r < 4; r++) d[i][j][r] = 0.0f;

    const int r0 = t >> 2, c0 = t & 3;
    const int r1 = r0 + 64;
    const __half* srcs[2] = {A, B};
    const __half* sp[4];
    uint32_t dst[4];
#pragma unroll
    for (int arr = 0; arr < 2; arr++) {
        const int rb = (arr == 0) ? bm : bn;
        sp[2 * arr]     = srcs[arr] + (size_t)(rb + r0) * DMODEL + c0 * 8;
        sp[2 * arr + 1] = srcs[arr] + (size_t)(rb + r1) * DMODEL + c0 * 8;
        dst[2 * arr]     = smb + arr * 8192 + sw_off(r0, c0);
        dst[2 * arr + 1] = smb + arr * 8192 + sw_off(r1, c0);
    }
    auto issue = [&](uint32_t so2, int kt) {
#pragma unroll
        for (int i = 0; i < 4; i++) cpa16(dst[i] + so2, sp[i] + kt * 32);
        asm volatile("cp.async.commit_group;");
    };

    uint32_t aA[4], aB[2];
#pragma unroll
    for (int i = 0; i < 4; i++) aA[i] = smb + sw_off(wm + i * 16 + lr, kc);
#pragma unroll
    for (int p = 0; p < 2; p++) aB[p] = smb + 8192 + sw_off(wn + p * 16 + lr, kc);

    issue(0, 0);
    issue(16384, 1);

    uint32_t so = 0, si = 32768;
#pragma unroll 1
    for (int kt = 0; kt < 64; kt++) {
        if (kt < 63) asm volatile("cp.async.wait_group 1;");
        else         asm volatile("cp.async.wait_group 0;");
        __syncthreads();
        if (kt + 2 < 64) issue(si, kt + 2);

#pragma unroll
        for (int kk = 0; kk < 2; kk++) {
            const uint32_t kx = kk * 32;
            uint32_t af[4][4], bf[2][4];
#pragma unroll
            for (int i = 0; i < 4; i++) ldsm4((aA[i] ^ kx) + so, af[i]);
#pragma unroll
            for (int p = 0; p < 2; p++) ldsm4((aB[p] ^ kx) + so, bf[p]);
#pragma unroll
            for (int i = 0; i < 4; i++)
#pragma unroll
                for (int j = 0; j < 4; j++)
                    mma16816(d[i][j], af[i], bf[j >> 1][j & 1], bf[j >> 1][(j & 1) + 2]);
        }
        so = (so == 32768) ? 0 : so + 16384;
        si = (si == 32768) ? 0 : si + 16384;
    }

    const int tg = lane >> 2, t4 = lane & 3;
#pragma unroll
    for (int i = 0; i < 4; i++) {
        const int row = bm + wm + i * 16 + tg;
#pragma unroll
        for (int j = 0; j < 4; j++) {
            const int col = bn + wn + j * 8 + t4 * 2;
            const float b0 = bias[col], b1 = bias[col + 1];
            float v0 = (d[i][j][0] + b0) * scale, v1 = (d[i][j][1] + b1) * scale;
            float v2 = (d[i][j][2] + b0) * scale, v3 = (d[i][j][3] + b1) * scale;
            if (Cf) {
                *(float2*)&Cf[(size_t)row * DMODEL + col] = make_float2(v0, v1);
                *(float2*)&Cf[(size_t)(row + 8) * DMODEL + col] = make_float2(v2, v3);
            } else {
                *(uint32_t*)&Ch[(size_t)row * DMODEL + col] = pack_f16(v0, v1);
                *(uint32_t*)&Ch[(size_t)(row + 8) * DMODEL + col] = pack_f16(v2, v3);
            }
        }
    }
}

// Merged Q/K/V projection: grid (16,16,3); z selects operands.
__global__ __launch_bounds__(256, 2) void gemm_qkv(
    const __half* __restrict__ x16, const __half* __restrict__ y16,
    const __half* __restrict__ wq, const __half* __restrict__ wk,
    const __half* __restrict__ wv,
    const float* __restrict__ bq, const float* __restrict__ bk,
    const float* __restrict__ bv,
    __half* __restrict__ q, __half* __restrict__ k, __half* __restrict__ v)
{
    extern __shared__ __align__(1024) char sm[];
    const int z = blockIdx.z;
    const __half* A  = (z == 0) ? x16 : y16;
    const __half* B  = (z == 0) ? wq : (z == 1) ? wk : wv;
    const float* bias = (z == 0) ? bq : (z == 1) ? bk : bv;
    __half* C = (z == 0) ? q : (z == 1) ? k : v;
    const float scale = (z == 0) ? 0.125f : 1.0f;
    gemm_body(A, B, bias, nullptr, C, scale, sm);
}

// Output projection: fp32 out.
__global__ __launch_bounds__(256, 2) void gemm_out(
    const __half* __restrict__ A, const __half* __restrict__ B,
    const float* __restrict__ bias, float* __restrict__ Cf)
{
    extern __shared__ __align__(1024) char sm[];
    gemm_body(A, B, bias, Cf, nullptr, 1.0f, sm);
}

// ---------------------------------------------------------------------------
// Tensor-core flash attention.  Q fp16 in registers (1-pass QK^T);
// P fp16 (1-pass PV).  K, V fp16 in smem.  Output single fp16.
// Stage (16KB): K +0 | V +8192; 2 stages.
// ---------------------------------------------------------------------------
#define ATTN_SMEM (2 * 16384)

__global__ __launch_bounds__(128, 3) void attn_mma(
    const __half* __restrict__ Q,
    const __half* __restrict__ K, const __half* __restrict__ V,
    const void* __restrict__ mask_raw, const float* __restrict__ pb,
    __half* __restrict__ O16)
{
    extern __shared__ __align__(1024) char sm[];
    const int t = threadIdx.x, lane = t & 31, w = t >> 5;
    const int lr = lane & 15, kc = lane >> 4;
    const int group = lane >> 2, t4 = lane & 3;
    const int qbase = blockIdx.x * 64;
    const int h = blockIdx.y;
    const int mode = g_mask_mode;
    const uint32_t smb = smem_u32(sm);

    const unsigned char* m8 = (const unsigned char*)mask_raw;
    const int*   m32 = (const int*)mask_raw;
    const float* mf  = (const float*)mask_raw;

    const __half* kvs[2] = {K, V};
    auto issue_kv = [&](int st, int tile) {
#pragma unroll
        for (int arr = 0; arr < 2; arr++)
#pragma unroll
            for (int i = 0; i < 4; i++) {
                int idx = t + i * 128;
                int r = idx >> 3, c = idx & 7;
                cpa16(smb + st * 16384 + arr * 8192 + sw64(r, c),
                      kvs[arr] + (size_t)(tile * 64 + r) * DMODEL + h * DH + c * 8);
            }
        asm volatile("cp.async.commit_group;");
    };
    issue_kv(0, 0);

    // ---- Q fragments in registers (a-frag layout, loaded once) ----
    uint32_t qf[4][4];
    {
        const int g = qbase + w * 16 + group;
#pragma unroll
        for (int kk = 0; kk < 4; kk++) {
            const size_t col = (size_t)h * DH + kk * 16 + t4 * 2;
            qf[kk][0] = *(const uint32_t*)&Q[(size_t)g * DMODEL + col];
            qf[kk][1] = *(const uint32_t*)&Q[(size_t)(g + 8) * DMODEL + col];
            qf[kk][2] = *(const uint32_t*)&Q[(size_t)g * DMODEL + col + 8];
            qf[kk][3] = *(const uint32_t*)&Q[(size_t)(g + 8) * DMODEL + col + 8];
        }
    }

    uint32_t aK[4], aV[4];
#pragma unroll
    for (int p = 0; p < 4; p++) aK[p] = smb + sw64(p * 16 + lr, kc);
#pragma unroll
    for (int p = 0; p < 4; p++) aV[p] = smb + 8192 + sw64(p * 16 + lr, kc);

    float O[8][4];
    float m_i[2] = {-1e30f, -1e30f}, l_i[2] = {0.0f, 0.0f};
#pragma unroll
    for (int j = 0; j < 8; j++)
#pragma unroll
        for (int r = 0; r < 4; r++) O[j][r] = 0.0f;

#pragma unroll 1
    for (int it = 0; it < 32; it++) {
        if (it < 31) issue_kv((it + 1) & 1, it + 1);

        // ---- prefetch bias with mask folded in (-1e30 on masked lanes) ----
        float2 pbv[2][8];
#pragma unroll
        for (int r2 = 0; r2 < 2; r2++) {
            const int qrow = qbase + w * 16 + group + r2 * 8;
            const size_t prow = ((size_t)h * SEQ + qrow) * SEQ + it * 64;
            const size_t mrow = (size_t)qrow * SEQ + it * 64;
#pragma unroll
            for (int j = 0; j < 8; j++) {
                const int col = j * 8 + t4 * 2;
                float2 bv = *(const float2*)&pb[prow + col];
                int ok0, ok1;
                if (mode == 0) {
                    uchar2 mv = *(const uchar2*)&m8[mrow + col];
                    ok0 = mv.x; ok1 = mv.y;
                } else if (mode == 1) {
                    int2 mv = *(const int2*)&m32[mrow + col];
                    ok0 = mv.x; ok1 = mv.y;
                } else {
                    float2 mv = *(const float2*)&mf[mrow + col];
                    ok0 = (mv.x != 0.0f); ok1 = (mv.y != 0.0f);
                }
                pbv[r2][j].x = ok0 ? bv.x : -1e30f;
                pbv[r2][j].y = ok1 ? bv.y : -1e30f;
            }
        }

        if (it < 31) asm volatile("cp.async.wait_group 1;");
        else         asm volatile("cp.async.wait_group 0;");
        __syncthreads();

        const uint32_t so = (it & 1) * 16384;

        // ---- S = Q K^T  (single pass) ----
        float S[8][4];
#pragma unroll
        for (int j = 0; j < 8; j++)
#pragma unroll
            for (int r = 0; r < 4; r++) S[j][r] = 0.0f;

#pragma unroll
        for (int kk = 0; kk < 4; kk++) {
            const uint32_t kx = kk * 32;
            uint32_t khf[4][4];
#pragma unroll
            for (int p = 0; p < 4; p++) ldsm4((aK[p] ^ kx) + so, khf[p]);
#pragma unroll
            for (int j = 0; j < 8; j++)
                mma16816(S[j], qf[kk], khf[j >> 1][j & 1], khf[j >> 1][(j & 1) + 2]);
        }

        // ---- bias(+mask) + online softmax ----
#pragma unroll
        for (int r2 = 0; r2 < 2; r2++) {
            float mx = -1e30f;
#pragma unroll
            for (int j = 0; j < 8; j++) {
                float s0 = S[j][r2 * 2]     + pbv[r2][j].x;
                float s1 = S[j][r2 * 2 + 1] + pbv[r2][j].y;
                S[j][r2 * 2] = s0; S[j][r2 * 2 + 1] = s1;
                mx = fmaxf(mx, fmaxf(s0, s1));
            }
            mx = fmaxf(mx, __shfl_xor_sync(0xffffffffu, mx, 1));
            mx = fmaxf(mx, __shfl_xor_sync(0xffffffffu, mx, 2));
            float mnew = fmaxf(m_i[r2], mx);
            float corr = __expf(m_i[r2] - mnew);
            float rsum = 0.0f;
#pragma unroll
            for (int j = 0; j < 8; j++) {
#pragma unroll
                for (int e = 0; e < 2; e++) {
                    float s = S[j][r2 * 2 + e];
                    float p = (s > -1e29f) ? __expf(s - mnew) : 0.0f;
                    S[j][r2 * 2 + e] = p;
                    rsum += p;
                }
            }
            rsum += __shfl_xor_sync(0xffffffffu, rsum, 1);
            rsum += __shfl_xor_sync(0xffffffffu, rsum, 2);
            l_i[r2] = l_i[r2] * corr + rsum;
            m_i[r2] = mnew;
#pragma unroll
            for (int j = 0; j < 8; j++) {
                O[j][r2 * 2]     *= corr;
                O[j][r2 * 2 + 1] *= corr;
            }
        }

        // ---- pack P into fp16 a-frags ----
        uint32_t aP[4][4];
#pragma unroll
        for (int kk = 0; kk < 4; kk++) {
#pragma unroll
            for (int half_ = 0; half_ < 2; half_++) {
                const int j = 2 * kk + half_;
#pragma unroll
                for (int rr = 0; rr < 2; rr++)
                    aP[kk][half_ * 2 + rr] = pack_f16(S[j][rr * 2], S[j][rr * 2 + 1]);
            }
        }

        // ---- O += P V  (single pass) ----
#pragma unroll
        for (int kk = 0; kk < 4; kk++) {
#pragma unroll
            for (int jj = 0; jj < 4; jj++) {
                const uint32_t jx = jj * 32;
                uint32_t vh4[4];
                ldsm4t((aV[kk] ^ jx) + so, vh4);
                mma16816(O[2 * jj],     aP[kk], vh4[0], vh4[1]);
                mma16816(O[2 * jj + 1], aP[kk], vh4[2], vh4[3]);
            }
        }
        __syncthreads();
    }

    // ---- epilogue: normalize, single fp16 ----
#pragma unroll
    for (int r2 = 0; r2 < 2; r2++) {
        const int qrow = qbase + w * 16 + group + r2 * 8;
        const float inv = 1.0f / l_i[r2];
#pragma unroll
        for (int j = 0; j < 8; j++) {
            const int col = h * DH + j * 8 + t4 * 2;
            *(uint32_t*)&O16[(size_t)qrow * DMODEL + col] =
                pack_f16(O[j][r2 * 2] * inv, O[j][r2 * 2 + 1] * inv);
        }
    }
}

// ---------------------------------------------------------------------------
extern "C" void kernel_launch(void* const* d_in, const int* in_sizes, int n_in,
                              void* d_out, int out_size)
{
    const float* hq   = (const float*)d_in[0];
    const float* hkv  = (const float*)d_in[1];
    const void*  mask = d_in[2];
    const float* pb   = (const float*)d_in[3];
    const float* wq   = (const float*)d_in[4];
    const float* bq   = (const float*)d_in[5];
    const float* wk   = (const float*)d_in[6];
    const float* bk   = (const float*)d_in[7];
    const float* wv   = (const float*)d_in[8];
    const float* bv   = (const float*)d_in[9];
    const float* wo   = (const float*)d_in[10];
    const float* bo   = (const float*)d_in[11];
    float* out = (float*)d_out;

    __half *x16, *y16, *wq16, *wk16, *wv16, *wo16, *qp, *kp, *vp, *ap;
    cudaGetSymbolAddress((void**)&x16, g_x16);
    cudaGetSymbolAddress((void**)&y16, g_y16);
    cudaGetSymbolAddress((void**)&wq16, g_wq16);
    cudaGetSymbolAddress((void**)&wk16, g_wk16);
    cudaGetSymbolAddress((void**)&wv16, g_wv16);
    cudaGetSymbolAddress((void**)&wo16, g_wo16);
    cudaGetSymbolAddress((void**)&qp, g_q);
    cudaGetSymbolAddress((void**)&kp, g_k);
    cudaGetSymbolAddress((void**)&vp, g_v);
    cudaGetSymbolAddress((void**)&ap, g_a);

    cudaFuncSetAttribute(gemm_qkv,
                         cudaFuncAttributeMaxDynamicSharedMemorySize, GEMM_SMEM);
    cudaFuncSetAttribute(gemm_out,
                         cudaFuncAttributeMaxDynamicSharedMemorySize, GEMM_SMEM);
    cudaFuncSetAttribute(attn_mma,
                         cudaFuncAttributeMaxDynamicSharedMemorySize, ATTN_SMEM);

    detect_mask_kernel<<<1, 32>>>((const unsigned char*)mask);

    // Fused preprocessing: both activations + all four weights -> fp16.
    conv6_f16<<<6 * 2048, 256>>>(hq, hkv, wq, wk, wv, wo,
                                 x16, y16, wq16, wk16, wv16, wo16);

    // Q, K, V projections in one launch (z = 0,1,2).
    gemm_qkv<<<dim3(DMODEL / 128, SEQ / 128, 3), 256, GEMM_SMEM>>>(
        x16, y16, wq16, wk16, wv16, bq, bk, bv, qp, kp, vp);

    // attention -> fp16
    attn_mma<<<dim3(SEQ / 64, NH), 128, ATTN_SMEM>>>(
        qp, kp, vp, mask, pb, ap);

    // out = attn @ wo^T + bo  (fp32)
    gemm_out<<<dim3(DMODEL / 128, SEQ / 128), 256, GEMM_SMEM>>>(
        ap, wo16, bo, out);
}

// round 15
// speedup vs baseline: 4.8809x; 1.0259x over previous
#include <cuda_runtime.h>
#include <cuda_fp16.h>
#include <cstdint>
#include <cstddef>

#define SEQ 2048
#define DMODEL 2048
#define NH 32
#define DH 64

// ---------------------------------------------------------------------------
// Scratch (device globals: allocation-free rule).  All-fp16 data path.
// Error budget: ~13 single-fp16 rounding terms ~2e-4 each => ~6.9e-4 measured.
// ---------------------------------------------------------------------------
__device__ __half g_x16[SEQ * DMODEL];   // hq fp16
__device__ __half g_y16[SEQ * DMODEL];   // hkv fp16
__device__ __half g_wq16[SEQ * DMODEL];
__device__ __half g_wk16[SEQ * DMODEL];
__device__ __half g_wv16[SEQ * DMODEL];
__device__ __half g_wo16[SEQ * DMODEL];
__device__ __half g_q [SEQ * DMODEL];    // Q fp16 (pre-scaled 0.125)
__device__ __half g_k [SEQ * DMODEL];    // K fp16
__device__ __half g_v [SEQ * DMODEL];    // V fp16
__device__ __half g_a [SEQ * DMODEL];    // attention out fp16
__device__ int g_mask_mode;  // 0=uint8, 1=int32, 2=float32

// ---------------------------------------------------------------------------
__global__ void detect_mask_kernel(const unsigned char* __restrict__ m) {
    if (threadIdx.x == 0) {
        int mx = 0, off = 0;
        for (int i = 0; i < 256; i++) {
            int b = m[i];
            if (b > mx) mx = b;
            if ((i & 3) && b) off = 1;
        }
        g_mask_mode = (mx > 1) ? 2 : (off ? 0 : 1);
    }
}

// ---------------------------------------------------------------------------
// Fused fp32 -> fp16 conversion of all six fp32 sources.
// ---------------------------------------------------------------------------
__global__ __launch_bounds__(256) void conv6_f16(
    const float* __restrict__ s0, const float* __restrict__ s1,
    const float* __restrict__ s2, const float* __restrict__ s3,
    const float* __restrict__ s4, const float* __restrict__ s5,
    __half* __restrict__ d0, __half* __restrict__ d1,
    __half* __restrict__ d2, __half* __restrict__ d3,
    __half* __restrict__ d4, __half* __restrict__ d5)
{
    int sel = blockIdx.x >> 11;
    int b   = blockIdx.x & 2047;
    const float* x = (sel == 0) ? s0 : (sel == 1) ? s1 : (sel == 2) ? s2
                   : (sel == 3) ? s3 : (sel == 4) ? s4 : s5;
    __half* y      = (sel == 0) ? d0 : (sel == 1) ? d1 : (sel == 2) ? d2
                   : (sel == 3) ? d3 : (sel == 4) ? d4 : d5;
    size_t base = ((size_t)b * 256 + threadIdx.x) * 8;
    float4 a = *(const float4*)(x + base);
    float4 c = *(const float4*)(x + base + 4);
    __half2 h2[4];
    h2[0] = __floats2half2_rn(a.x, a.y);
    h2[1] = __floats2half2_rn(a.z, a.w);
    h2[2] = __floats2half2_rn(c.x, c.y);
    h2[3] = __floats2half2_rn(c.z, c.w);
    *(uint4*)(y + base) = *(uint4*)h2;
}

// ---------------------------------------------------------------------------
__device__ __forceinline__ uint32_t smem_u32(const void* p) {
    uint32_t a;
    asm("{ .reg .u64 t; cvta.to.shared.u64 t, %1; cvt.u32.u64 %0, t; }"
        : "=r"(a) : "l"(p));
    return a;
}
__device__ __forceinline__ void ldsm4(uint32_t addr, uint32_t* r) {
    asm volatile("ldmatrix.sync.aligned.m8n8.x4.shared.b16 {%0,%1,%2,%3}, [%4];"
        : "=r"(r[0]), "=r"(r[1]), "=r"(r[2]), "=r"(r[3]) : "r"(addr));
}
__device__ __forceinline__ void ldsm4t(uint32_t addr, uint32_t* r) {
    asm volatile("ldmatrix.sync.aligned.m8n8.x4.trans.shared.b16 {%0,%1,%2,%3}, [%4];"
        : "=r"(r[0]), "=r"(r[1]), "=r"(r[2]), "=r"(r[3]) : "r"(addr));
}
__device__ __forceinline__ void mma16816(float* d, const uint32_t* a,
                                         uint32_t b0, uint32_t b1) {
    asm volatile(
        "mma.sync.aligned.m16n8k16.row.col.f32.f16.f16.f32 "
        "{%0,%1,%2,%3}, {%4,%5,%6,%7}, {%8,%9}, {%0,%1,%2,%3};"
        : "+f"(d[0]), "+f"(d[1]), "+f"(d[2]), "+f"(d[3])
        : "r"(a[0]), "r"(a[1]), "r"(a[2]), "r"(a[3]), "r"(b0), "r"(b1));
}
__device__ __forceinline__ void cpa16(uint32_t s, const void* g) {
    asm volatile("cp.async.cg.shared.global [%0], [%1], 16;" :: "r"(s), "l"(g));
}
__device__ __forceinline__ uint32_t pack_f16(float a, float b) {
    __half2 h = __floats2half2_rn(a, b);
    return *(uint32_t*)&h;
}

// 32-col f16 tile (64B rows)
__device__ __forceinline__ uint32_t sw_off(int r, int c) {
    return (uint32_t)(r * 64 + ((c ^ ((r >> 1) & 3)) * 16));
}
// 64-col f16 tile (128B rows)
__device__ __forceinline__ uint32_t sw64(int r, int c) {
    return (uint32_t)(r * 128 + ((c ^ (r & 7)) * 16));
}

// ---------------------------------------------------------------------------
// Shared GEMM body (fp16 1-pass): C = A[M,K] @ B[N,K]^T + bias, *scale.
// Stage layout (16KB): A +0 | B +8192.  3 stages.
// ---------------------------------------------------------------------------
#define GEMM_SMEM (3 * 16384)

__device__ __forceinline__ void gemm_body(
    const __half* __restrict__ A, const __half* __restrict__ B,
    const float* __restrict__ bias, float* __restrict__ Cf,
    __half* __restrict__ Ch, float scale, char* sm)
{
    const int t    = threadIdx.x;
    const int bm   = blockIdx.y * 128;
    const int bn   = blockIdx.x * 128;
    const int lane = t & 31;
    const int w    = t >> 5;
    const int wm   = (w & 1) * 64;
    const int wn   = (w >> 1) * 32;
    const int lr   = lane & 15;
    const int kc   = lane >> 4;
    const uint32_t smb = smem_u32(sm);

    float d[4][4][4];
#pragma unroll
    for (int i = 0; i < 4; i++)
#pragma unroll
        for (int j = 0; j < 4; j++)
#pragma unroll
            for (int r = 0; r < 4; r++) d[i][j][r] = 0.0f;

    const int r0 = t >> 2, c0 = t & 3;
    const int r1 = r0 + 64;
    const __half* srcs[2] = {A, B};
    const __half* sp[4];
    uint32_t dst[4];
#pragma unroll
    for (int arr = 0; arr < 2; arr++) {
        const int rb = (arr == 0) ? bm : bn;
        sp[2 * arr]     = srcs[arr] + (size_t)(rb + r0) * DMODEL + c0 * 8;
        sp[2 * arr + 1] = srcs[arr] + (size_t)(rb + r1) * DMODEL + c0 * 8;
        dst[2 * arr]     = smb + arr * 8192 + sw_off(r0, c0);
        dst[2 * arr + 1] = smb + arr * 8192 + sw_off(r1, c0);
    }
    auto issue = [&](uint32_t so2, int kt) {
#pragma unroll
        for (int i = 0; i < 4; i++) cpa16(dst[i] + so2, sp[i] + kt * 32);
        asm volatile("cp.async.commit_group;");
    };

    uint32_t aA[4], aB[2];
#pragma unroll
    for (int i = 0; i < 4; i++) aA[i] = smb + sw_off(wm + i * 16 + lr, kc);
#pragma unroll
    for (int p = 0; p < 2; p++) aB[p] = smb + 8192 + sw_off(wn + p * 16 + lr, kc);

    issue(0, 0);
    issue(16384, 1);

    uint32_t so = 0, si = 32768;
#pragma unroll 1
    for (int kt = 0; kt < 64; kt++) {
        if (kt < 63) asm volatile("cp.async.wait_group 1;");
        else         asm volatile("cp.async.wait_group 0;");
        __syncthreads();
        if (kt + 2 < 64) issue(si, kt + 2);

#pragma unroll
        for (int kk = 0; kk < 2; kk++) {
            const uint32_t kx = kk * 32;
            uint32_t af[4][4], bf[2][4];
#pragma unroll
            for (int i = 0; i < 4; i++) ldsm4((aA[i] ^ kx) + so, af[i]);
#pragma unroll
            for (int p = 0; p < 2; p++) ldsm4((aB[p] ^ kx) + so, bf[p]);
#pragma unroll
            for (int i = 0; i < 4; i++)
#pragma unroll
                for (int j = 0; j < 4; j++)
                    mma16816(d[i][j], af[i], bf[j >> 1][j & 1], bf[j >> 1][(j & 1) + 2]);
        }
        so = (so == 32768) ? 0 : so + 16384;
        si = (si == 32768) ? 0 : si + 16384;
    }

    const int tg = lane >> 2, t4 = lane & 3;
#pragma unroll
    for (int i = 0; i < 4; i++) {
        const int row = bm + wm + i * 16 + tg;
#pragma unroll
        for (int j = 0; j < 4; j++) {
            const int col = bn + wn + j * 8 + t4 * 2;
            const float b0 = bias[col], b1 = bias[col + 1];
            float v0 = (d[i][j][0] + b0) * scale, v1 = (d[i][j][1] + b1) * scale;
            float v2 = (d[i][j][2] + b0) * scale, v3 = (d[i][j][3] + b1) * scale;
            if (Cf) {
                *(float2*)&Cf[(size_t)row * DMODEL + col] = make_float2(v0, v1);
                *(float2*)&Cf[(size_t)(row + 8) * DMODEL + col] = make_float2(v2, v3);
            } else {
                *(uint32_t*)&Ch[(size_t)row * DMODEL + col] = pack_f16(v0, v1);
                *(uint32_t*)&Ch[(size_t)(row + 8) * DMODEL + col] = pack_f16(v2, v3);
            }
        }
    }
}

// Merged Q/K/V projection: grid (16,16,3); z selects operands.
__global__ __launch_bounds__(256, 2) void gemm_qkv(
    const __half* __restrict__ x16, const __half* __restrict__ y16,
    const __half* __restrict__ wq, const __half* __restrict__ wk,
    const __half* __restrict__ wv,
    const float* __restrict__ bq, const float* __restrict__ bk,
    const float* __restrict__ bv,
    __half* __restrict__ q, __half* __restrict__ k, __half* __restrict__ v)
{
    extern __shared__ __align__(1024) char sm[];
    const int z = blockIdx.z;
    const __half* A  = (z == 0) ? x16 : y16;
    const __half* B  = (z == 0) ? wq : (z == 1) ? wk : wv;
    const float* bias = (z == 0) ? bq : (z == 1) ? bk : bv;
    __half* C = (z == 0) ? q : (z == 1) ? k : v;
    const float scale = (z == 0) ? 0.125f : 1.0f;
    gemm_body(A, B, bias, nullptr, C, scale, sm);
}

// Output projection: fp32 out.
__global__ __launch_bounds__(256, 2) void gemm_out(
    const __half* __restrict__ A, const __half* __restrict__ B,
    const float* __restrict__ bias, float* __restrict__ Cf)
{
    extern __shared__ __align__(1024) char sm[];
    gemm_body(A, B, bias, Cf, nullptr, 1.0f, sm);
}

// ---------------------------------------------------------------------------
// Tensor-core flash attention with cp.async-staged position bias.
// Q fp16 in registers (1-pass QK^T); P fp16 (1-pass PV); K,V fp16 in smem.
// smem: KV 2 stages x 16KB at +0  (K +0 | V +8192)
//       pb 2 stages x 17408B at +32768 (64 rows x 272B padded, 256B valid)
// Mask: register-prefetched LDG, packed into 2 bitmask regs.
// ---------------------------------------------------------------------------
#define PB_STRIDE 272
#define PB_STAGE  (64 * PB_STRIDE)      // 17408
#define ATTN_SMEM (32768 + 2 * PB_STAGE)

__global__ __launch_bounds__(128, 3) void attn_mma(
    const __half* __restrict__ Q,
    const __half* __restrict__ K, const __half* __restrict__ V,
    const void* __restrict__ mask_raw, const float* __restrict__ pb,
    __half* __restrict__ O16)
{
    extern __shared__ __align__(1024) char sm[];
    const int t = threadIdx.x, lane = t & 31, w = t >> 5;
    const int lr = lane & 15, kc = lane >> 4;
    const int group = lane >> 2, t4 = lane & 3;
    const int qbase = blockIdx.x * 64;
    const int h = blockIdx.y;
    const int mode = g_mask_mode;
    const uint32_t smb = smem_u32(sm);

    const unsigned char* m8 = (const unsigned char*)mask_raw;
    const int*   m32 = (const int*)mask_raw;
    const float* mf  = (const float*)mask_raw;

    const __half* kvs[2] = {K, V};
    const float* pbbase = pb + ((size_t)h * SEQ + qbase) * SEQ;

    auto issue_stage = [&](int st, int tile) {
        // K, V tiles
#pragma unroll
        for (int arr = 0; arr < 2; arr++)
#pragma unroll
            for (int i = 0; i < 4; i++) {
                int idx = t + i * 128;
                int r = idx >> 3, c = idx & 7;
                cpa16(smb + st * 16384 + arr * 8192 + sw64(r, c),
                      kvs[arr] + (size_t)(tile * 64 + r) * DMODEL + h * DH + c * 8);
            }
        // pb tile: 64 rows x 64 fp32 = 16KB, 8 x 16B chunks per thread
#pragma unroll
        for (int i = 0; i < 8; i++) {
            int c = t + i * 128;            // 0..1023
            int r = c >> 4, c16 = c & 15;
            cpa16(smb + 32768 + st * PB_STAGE + r * PB_STRIDE + c16 * 16,
                  pbbase + (size_t)r * SEQ + tile * 64 + c16 * 4);
        }
        asm volatile("cp.async.commit_group;");
    };
    issue_stage(0, 0);

    // ---- Q fragments in registers (a-frag layout, loaded once) ----
    uint32_t qf[4][4];
    {
        const int g = qbase + w * 16 + group;
#pragma unroll
        for (int kk = 0; kk < 4; kk++) {
            const size_t col = (size_t)h * DH + kk * 16 + t4 * 2;
            qf[kk][0] = *(const uint32_t*)&Q[(size_t)g * DMODEL + col];
            qf[kk][1] = *(const uint32_t*)&Q[(size_t)(g + 8) * DMODEL + col];
            qf[kk][2] = *(const uint32_t*)&Q[(size_t)g * DMODEL + col + 8];
            qf[kk][3] = *(const uint32_t*)&Q[(size_t)(g + 8) * DMODEL + col + 8];
        }
    }

    uint32_t aK[4], aV[4];
#pragma unroll
    for (int p = 0; p < 4; p++) aK[p] = smb + sw64(p * 16 + lr, kc);
#pragma unroll
    for (int p = 0; p < 4; p++) aV[p] = smb + 8192 + sw64(p * 16 + lr, kc);

    // per-row smem byte offsets for pb reads (within a stage)
    uint32_t pbOff[2];
#pragma unroll
    for (int r2 = 0; r2 < 2; r2++)
        pbOff[r2] = smb + 32768 +
                    (uint32_t)((w * 16 + group + r2 * 8) * PB_STRIDE + t4 * 8);

    float O[8][4];
    float m_i[2] = {-1e30f, -1e30f}, l_i[2] = {0.0f, 0.0f};
#pragma unroll
    for (int j = 0; j < 8; j++)
#pragma unroll
        for (int r = 0; r < 4; r++) O[j][r] = 0.0f;

#pragma unroll 1
    for (int it = 0; it < 32; it++) {
        if (it < 31) issue_stage((it + 1) & 1, it + 1);

        // ---- prefetch mask bits for THIS iteration into 2 bitmask regs ----
        uint32_t okb[2] = {0u, 0u};
#pragma unroll
        for (int r2 = 0; r2 < 2; r2++) {
            const int qrow = qbase + w * 16 + group + r2 * 8;
            const size_t mrow = (size_t)qrow * SEQ + it * 64;
#pragma unroll
            for (int j = 0; j < 8; j++) {
                const int col = j * 8 + t4 * 2;
                uint32_t ok0, ok1;
                if (mode == 0) {
                    uchar2 mv = *(const uchar2*)&m8[mrow + col];
                    ok0 = mv.x ? 1u : 0u; ok1 = mv.y ? 1u : 0u;
                } else if (mode == 1) {
                    int2 mv = *(const int2*)&m32[mrow + col];
                    ok0 = mv.x ? 1u : 0u; ok1 = mv.y ? 1u : 0u;
                } else {
                    float2 mv = *(const float2*)&mf[mrow + col];
                    ok0 = (mv.x != 0.0f) ? 1u : 0u; ok1 = (mv.y != 0.0f) ? 1u : 0u;
                }
                okb[r2] |= (ok0 << (2 * j)) | (ok1 << (2 * j + 1));
            }
        }

        if (it < 31) asm volatile("cp.async.wait_group 1;");
        else         asm volatile("cp.async.wait_group 0;");
        __syncthreads();

        const uint32_t so   = (it & 1) * 16384;
        const uint32_t sopb = (it & 1) * PB_STAGE;

        // ---- S = Q K^T  (single pass) ----
        float S[8][4];
#pragma unroll
        for (int j = 0; j < 8; j++)
#pragma unroll
            for (int r = 0; r < 4; r++) S[j][r] = 0.0f;

#pragma unroll
        for (int kk = 0; kk < 4; kk++) {
            const uint32_t kx = kk * 32;
            uint32_t khf[4][4];
#pragma unroll
            for (int p = 0; p < 4; p++) ldsm4((aK[p] ^ kx) + so, khf[p]);
#pragma unroll
            for (int j = 0; j < 8; j++)
                mma16816(S[j], qf[kk], khf[j >> 1][j & 1], khf[j >> 1][(j & 1) + 2]);
        }

        // ---- bias (from smem) + mask bits + online softmax ----
#pragma unroll
        for (int r2 = 0; r2 < 2; r2++) {
            float mx = -1e30f;
#pragma unroll
            for (int j = 0; j < 8; j++) {
                float2 bv;
                asm volatile("ld.shared.v2.f32 {%0,%1}, [%2];"
                    : "=f"(bv.x), "=f"(bv.y)
                    : "r"(pbOff[r2] + sopb + (uint32_t)(j * 32)));
                float s0 = (okb[r2] >> (2 * j)     & 1u) ? S[j][r2 * 2]     + bv.x : -1e30f;
                float s1 = (okb[r2] >> (2 * j + 1) & 1u) ? S[j][r2 * 2 + 1] + bv.y : -1e30f;
                S[j][r2 * 2] = s0; S[j][r2 * 2 + 1] = s1;
                mx = fmaxf(mx, fmaxf(s0, s1));
            }
            mx = fmaxf(mx, __shfl_xor_sync(0xffffffffu, mx, 1));
            mx = fmaxf(mx, __shfl_xor_sync(0xffffffffu, mx, 2));
            float mnew = fmaxf(m_i[r2], mx);
            float corr = __expf(m_i[r2] - mnew);
            float rsum = 0.0f;
#pragma unroll
            for (int j = 0; j < 8; j++) {
#pragma unroll
                for (int e = 0; e < 2; e++) {
                    float s = S[j][r2 * 2 + e];
                    float p = (s > -1e29f) ? __expf(s - mnew) : 0.0f;
                    S[j][r2 * 2 + e] = p;
                    rsum += p;
                }
            }
            rsum += __shfl_xor_sync(0xffffffffu, rsum, 1);
            rsum += __shfl_xor_sync(0xffffffffu, rsum, 2);
            l_i[r2] = l_i[r2] * corr + rsum;
            m_i[r2] = mnew;
#pragma unroll
            for (int j = 0; j < 8; j++) {
                O[j][r2 * 2]     *= corr;
                O[j][r2 * 2 + 1] *= corr;
            }
        }

        // ---- pack P into fp16 a-frags ----
        uint32_t aP[4][4];
#pragma unroll
        for (int kk = 0; kk < 4; kk++) {
#pragma unroll
            for (int half_ = 0; half_ < 2; half_++) {
                const int j = 2 * kk + half_;
#pragma unroll
                for (int rr = 0; rr < 2; rr++)
                    aP[kk][half_ * 2 + rr] = pack_f16(S[j][rr * 2], S[j][rr * 2 + 1]);
            }
        }

        // ---- O += P V  (single pass) ----
#pragma unroll
        for (int kk = 0; kk < 4; kk++) {
#pragma unroll
            for (int jj = 0; jj < 4; jj++) {
                const uint32_t jx = jj * 32;
                uint32_t vh4[4];
                ldsm4t((aV[kk] ^ jx) + so, vh4);
                mma16816(O[2 * jj],     aP[kk], vh4[0], vh4[1]);
                mma16816(O[2 * jj + 1], aP[kk], vh4[2], vh4[3]);
            }
        }
        __syncthreads();
    }

    // ---- epilogue: normalize, single fp16 ----
#pragma unroll
    for (int r2 = 0; r2 < 2; r2++) {
        const int qrow = qbase + w * 16 + group + r2 * 8;
        const float inv = 1.0f / l_i[r2];
#pragma unroll
        for (int j = 0; j < 8; j++) {
            const int col = h * DH + j * 8 + t4 * 2;
            *(uint32_t*)&O16[(size_t)qrow * DMODEL + col] =
                pack_f16(O[j][r2 * 2] * inv, O[j][r2 * 2 + 1] * inv);
        }
    }
}

// ---------------------------------------------------------------------------
extern "C" void kernel_launch(void* const* d_in, const int* in_sizes, int n_in,
                              void* d_out, int out_size)
{
    const float* hq   = (const float*)d_in[0];
    const float* hkv  = (const float*)d_in[1];
    const void*  mask = d_in[2];
    const float* pb   = (const float*)d_in[3];
    const float* wq   = (const float*)d_in[4];
    const float* bq   = (const float*)d_in[5];
    const float* wk   = (const float*)d_in[6];
    const float* bk   = (const float*)d_in[7];
    const float* wv   = (const float*)d_in[8];
    const float* bv   = (const float*)d_in[9];
    const float* wo   = (const float*)d_in[10];
    const float* bo   = (const float*)d_in[11];
    float* out = (float*)d_out;

    __half *x16, *y16, *wq16, *wk16, *wv16, *wo16, *qp, *kp, *vp, *ap;
    cudaGetSymbolAddress((void**)&x16, g_x16);
    cudaGetSymbolAddress((void**)&y16, g_y16);
    cudaGetSymbolAddress((void**)&wq16, g_wq16);
    cudaGetSymbolAddress((void**)&wk16, g_wk16);
    cudaGetSymbolAddress((void**)&wv16, g_wv16);
    cudaGetSymbolAddress((void**)&wo16, g_wo16);
    cudaGetSymbolAddress((void**)&qp, g_q);
    cudaGetSymbolAddress((void**)&kp, g_k);
    cudaGetSymbolAddress((void**)&vp, g_v);
    cudaGetSymbolAddress((void**)&ap, g_a);

    cudaFuncSetAttribute(gemm_qkv,
                         cudaFuncAttributeMaxDynamicSharedMemorySize, GEMM_SMEM);
    cudaFuncSetAttribute(gemm_out,
                         cudaFuncAttributeMaxDynamicSharedMemorySize, GEMM_SMEM);
    cudaFuncSetAttribute(attn_mma,
                         cudaFuncAttributeMaxDynamicSharedMemorySize, ATTN_SMEM);

    detect_mask_kernel<<<1, 32>>>((const unsigned char*)mask);

    // Fused preprocessing: both activations + all four weights -> fp16.
    conv6_f16<<<6 * 2048, 256>>>(hq, hkv, wq, wk, wv, wo,
                                 x16, y16, wq16, wk16, wv16, wo16);

    // Q, K, V projections in one launch (z = 0,1,2).
    gemm_qkv<<<dim3(DMODEL / 128, SEQ / 128, 3), 256, GEMM_SMEM>>>(
        x16, y16, wq16, wk16, wv16, bq, bk, bv, qp, kp, vp);

    // attention -> fp16
    attn_mma<<<dim3(SEQ / 64, NH), 128, ATTN_SMEM>>>(
        qp, kp, vp, mask, pb, ap);

    // out = attn @ wo^T + bo  (fp32)
    gemm_out<<<dim3(DMODEL / 128, SEQ / 128), 256, GEMM_SMEM>>>(
        ap, wo16, bo, out);
}

// round 16
// speedup vs baseline: 5.1237x; 1.0497x over previous
#include <cuda_runtime.h>
#include <cuda_fp16.h>
#include <cstdint>
#include <cstddef>

#define SEQ 2048
#define DMODEL 2048
#define NH 32
#define DH 64

// ---------------------------------------------------------------------------
// Scratch (device globals: allocation-free rule).  All-fp16 data path.
// ---------------------------------------------------------------------------
__device__ __half g_x16[SEQ * DMODEL];   // hq fp16
__device__ __half g_y16[SEQ * DMODEL];   // hkv fp16
__device__ __half g_wq16[SEQ * DMODEL];
__device__ __half g_wk16[SEQ * DMODEL];
__device__ __half g_wv16[SEQ * DMODEL];
__device__ __half g_wo16[SEQ * DMODEL];
__device__ __half g_q [SEQ * DMODEL];    // Q fp16 (pre-scaled 0.125)
__device__ __half g_k [SEQ * DMODEL];    // K fp16
__device__ __half g_v [SEQ * DMODEL];    // V fp16
__device__ __half g_a [SEQ * DMODEL];    // attention out fp16
__device__ int g_mask_mode;  // 0=uint8, 1=int32, 2=float32

// ---------------------------------------------------------------------------
__global__ void detect_mask_kernel(const unsigned char* __restrict__ m) {
    if (threadIdx.x == 0) {
        int mx = 0, off = 0;
        for (int i = 0; i < 256; i++) {
            int b = m[i];
            if (b > mx) mx = b;
            if ((i & 3) && b) off = 1;
        }
        g_mask_mode = (mx > 1) ? 2 : (off ? 0 : 1);
    }
}

// ---------------------------------------------------------------------------
// Fused fp32 -> fp16 conversion of all six fp32 sources.
// ---------------------------------------------------------------------------
__global__ __launch_bounds__(256) void conv6_f16(
    const float* __restrict__ s0, const float* __restrict__ s1,
    const float* __restrict__ s2, const float* __restrict__ s3,
    const float* __restrict__ s4, const float* __restrict__ s5,
    __half* __restrict__ d0, __half* __restrict__ d1,
    __half* __restrict__ d2, __half* __restrict__ d3,
    __half* __restrict__ d4, __half* __restrict__ d5)
{
    int sel = blockIdx.x >> 11;
    int b   = blockIdx.x & 2047;
    const float* x = (sel == 0) ? s0 : (sel == 1) ? s1 : (sel == 2) ? s2
                   : (sel == 3) ? s3 : (sel == 4) ? s4 : s5;
    __half* y      = (sel == 0) ? d0 : (sel == 1) ? d1 : (sel == 2) ? d2
                   : (sel == 3) ? d3 : (sel == 4) ? d4 : d5;
    size_t base = ((size_t)b * 256 + threadIdx.x) * 8;
    float4 a = *(const float4*)(x + base);
    float4 c = *(const float4*)(x + base + 4);
    __half2 h2[4];
    h2[0] = __floats2half2_rn(a.x, a.y);
    h2[1] = __floats2half2_rn(a.z, a.w);
    h2[2] = __floats2half2_rn(c.x, c.y);
    h2[3] = __floats2half2_rn(c.z, c.w);
    *(uint4*)(y + base) = *(uint4*)h2;
}

// ---------------------------------------------------------------------------
__device__ __forceinline__ uint32_t smem_u32(const void* p) {
    uint32_t a;
    asm("{ .reg .u64 t; cvta.to.shared.u64 t, %1; cvt.u32.u64 %0, t; }"
        : "=r"(a) : "l"(p));
    return a;
}
__device__ __forceinline__ void ldsm4(uint32_t addr, uint32_t* r) {
    asm volatile("ldmatrix.sync.aligned.m8n8.x4.shared.b16 {%0,%1,%2,%3}, [%4];"
        : "=r"(r[0]), "=r"(r[1]), "=r"(r[2]), "=r"(r[3]) : "r"(addr));
}
__device__ __forceinline__ void ldsm4t(uint32_t addr, uint32_t* r) {
    asm volatile("ldmatrix.sync.aligned.m8n8.x4.trans.shared.b16 {%0,%1,%2,%3}, [%4];"
        : "=r"(r[0]), "=r"(r[1]), "=r"(r[2]), "=r"(r[3]) : "r"(addr));
}
__device__ __forceinline__ void mma16816(float* d, const uint32_t* a,
                                         uint32_t b0, uint32_t b1) {
    asm volatile(
        "mma.sync.aligned.m16n8k16.row.col.f32.f16.f16.f32 "
        "{%0,%1,%2,%3}, {%4,%5,%6,%7}, {%8,%9}, {%0,%1,%2,%3};"
        : "+f"(d[0]), "+f"(d[1]), "+f"(d[2]), "+f"(d[3])
        : "r"(a[0]), "r"(a[1]), "r"(a[2]), "r"(a[3]), "r"(b0), "r"(b1));
}
__device__ __forceinline__ void cpa16(uint32_t s, const void* g) {
    asm volatile("cp.async.cg.shared.global [%0], [%1], 16;" :: "r"(s), "l"(g));
}
__device__ __forceinline__ uint32_t pack_f16(float a, float b) {
    __half2 h = __floats2half2_rn(a, b);
    return *(uint32_t*)&h;
}
__device__ __forceinline__ uint32_t ex2_f16x2(uint32_t t) {
    uint32_t p;
    asm("ex2.approx.f16x2 %0, %1;" : "=r"(p) : "r"(t));
    return p;
}

// 32-col f16 tile (64B rows)
__device__ __forceinline__ uint32_t sw_off(int r, int c) {
    return (uint32_t)(r * 64 + ((c ^ ((r >> 1) & 3)) * 16));
}
// 64-col f16 tile (128B rows)
__device__ __forceinline__ uint32_t sw64(int r, int c) {
    return (uint32_t)(r * 128 + ((c ^ (r & 7)) * 16));
}

// ---------------------------------------------------------------------------
// Shared GEMM body (fp16 1-pass): C = A[M,K] @ B[N,K]^T + bias, *scale.
// Stage layout (16KB): A +0 | B +8192.  3 stages.
// ---------------------------------------------------------------------------
#define GEMM_SMEM (3 * 16384)

__device__ __forceinline__ void gemm_body(
    const __half* __restrict__ A, const __half* __restrict__ B,
    const float* __restrict__ bias, float* __restrict__ Cf,
    __half* __restrict__ Ch, float scale, char* sm)
{
    const int t    = threadIdx.x;
    const int bm   = blockIdx.y * 128;
    const int bn   = blockIdx.x * 128;
    const int lane = t & 31;
    const int w    = t >> 5;
    const int wm   = (w & 1) * 64;
    const int wn   = (w >> 1) * 32;
    const int lr   = lane & 15;
    const int kc   = lane >> 4;
    const uint32_t smb = smem_u32(sm);

    float d[4][4][4];
#pragma unroll
    for (int i = 0; i < 4; i++)
#pragma unroll
        for (int j = 0; j < 4; j++)
#pragma unroll
            for (int r = 0; r < 4; r++) d[i][j][r] = 0.0f;

    const int r0 = t >> 2, c0 = t & 3;
    const int r1 = r0 + 64;
    const __half* srcs[2] = {A, B};
    const __half* sp[4];
    uint32_t dst[4];
#pragma unroll
    for (int arr = 0; arr < 2; arr++) {
        const int rb = (arr == 0) ? bm : bn;
        sp[2 * arr]     = srcs[arr] + (size_t)(rb + r0) * DMODEL + c0 * 8;
        sp[2 * arr + 1] = srcs[arr] + (size_t)(rb + r1) * DMODEL + c0 * 8;
        dst[2 * arr]     = smb + arr * 8192 + sw_off(r0, c0);
        dst[2 * arr + 1] = smb + arr * 8192 + sw_off(r1, c0);
    }
    auto issue = [&](uint32_t so2, int kt) {
#pragma unroll
        for (int i = 0; i < 4; i++) cpa16(dst[i] + so2, sp[i] + kt * 32);
        asm volatile("cp.async.commit_group;");
    };

    uint32_t aA[4], aB[2];
#pragma unroll
    for (int i = 0; i < 4; i++) aA[i] = smb + sw_off(wm + i * 16 + lr, kc);
#pragma unroll
    for (int p = 0; p < 2; p++) aB[p] = smb + 8192 + sw_off(wn + p * 16 + lr, kc);

    issue(0, 0);
    issue(16384, 1);

    uint32_t so = 0, si = 32768;
#pragma unroll 1
    for (int kt = 0; kt < 64; kt++) {
        if (kt < 63) asm volatile("cp.async.wait_group 1;");
        else         asm volatile("cp.async.wait_group 0;");
        __syncthreads();
        if (kt + 2 < 64) issue(si, kt + 2);

#pragma unroll
        for (int kk = 0; kk < 2; kk++) {
            const uint32_t kx = kk * 32;
            uint32_t af[4][4], bf[2][4];
#pragma unroll
            for (int i = 0; i < 4; i++) ldsm4((aA[i] ^ kx) + so, af[i]);
#pragma unroll
            for (int p = 0; p < 2; p++) ldsm4((aB[p] ^ kx) + so, bf[p]);
#pragma unroll
            for (int i = 0; i < 4; i++)
#pragma unroll
                for (int j = 0; j < 4; j++)
                    mma16816(d[i][j], af[i], bf[j >> 1][j & 1], bf[j >> 1][(j & 1) + 2]);
        }
        so = (so == 32768) ? 0 : so + 16384;
        si = (si == 32768) ? 0 : si + 16384;
    }

    const int tg = lane >> 2, t4 = lane & 3;
#pragma unroll
    for (int i = 0; i < 4; i++) {
        const int row = bm + wm + i * 16 + tg;
#pragma unroll
        for (int j = 0; j < 4; j++) {
            const int col = bn + wn + j * 8 + t4 * 2;
            const float b0 = bias[col], b1 = bias[col + 1];
            float v0 = (d[i][j][0] + b0) * scale, v1 = (d[i][j][1] + b1) * scale;
            float v2 = (d[i][j][2] + b0) * scale, v3 = (d[i][j][3] + b1) * scale;
            if (Cf) {
                *(float2*)&Cf[(size_t)row * DMODEL + col] = make_float2(v0, v1);
                *(float2*)&Cf[(size_t)(row + 8) * DMODEL + col] = make_float2(v2, v3);
            } else {
                *(uint32_t*)&Ch[(size_t)row * DMODEL + col] = pack_f16(v0, v1);
                *(uint32_t*)&Ch[(size_t)(row + 8) * DMODEL + col] = pack_f16(v2, v3);
            }
        }
    }
}

// Merged Q/K/V projection: grid (16,16,3); z selects operands.
__global__ __launch_bounds__(256, 2) void gemm_qkv(
    const __half* __restrict__ x16, const __half* __restrict__ y16,
    const __half* __restrict__ wq, const __half* __restrict__ wk,
    const __half* __restrict__ wv,
    const float* __restrict__ bq, const float* __restrict__ bk,
    const float* __restrict__ bv,
    __half* __restrict__ q, __half* __restrict__ k, __half* __restrict__ v)
{
    extern __shared__ __align__(1024) char sm[];
    const int z = blockIdx.z;
    const __half* A  = (z == 0) ? x16 : y16;
    const __half* B  = (z == 0) ? wq : (z == 1) ? wk : wv;
    const float* bias = (z == 0) ? bq : (z == 1) ? bk : bv;
    __half* C = (z == 0) ? q : (z == 1) ? k : v;
    const float scale = (z == 0) ? 0.125f : 1.0f;
    gemm_body(A, B, bias, nullptr, C, scale, sm);
}

// Output projection: fp32 out.
__global__ __launch_bounds__(256, 2) void gemm_out(
    const __half* __restrict__ A, const __half* __restrict__ B,
    const float* __restrict__ bias, float* __restrict__ Cf)
{
    extern __shared__ __align__(1024) char sm[];
    gemm_body(A, B, bias, Cf, nullptr, 1.0f, sm);
}

// ---------------------------------------------------------------------------
// Tensor-core flash attention.
//  - Q fp16 in registers (1-pass QK^T); P fp16 via ex2.approx.f16x2 (the
//    exponential OUTPUT is the packed a-frag - no separate pack/guard ops).
//  - Row sums l_i computed by an extra ones-column PV mma (c-frag ds),
//    corr-scaled like O: no rsum adds, no shuffles.
//  - pb staged via cp.async (2 stages); mask as packed bitmask regs.
// smem: KV 2 x 16KB at +0 (K +0 | V +8192); pb 2 x 17408B at +32768.
// ---------------------------------------------------------------------------
#define PB_STRIDE 272
#define PB_STAGE  (64 * PB_STRIDE)      // 17408
#define ATTN_SMEM (32768 + 2 * PB_STAGE)
#define LOG2E 1.4426950408889634f

__global__ __launch_bounds__(128, 3) void attn_mma(
    const __half* __restrict__ Q,
    const __half* __restrict__ K, const __half* __restrict__ V,
    const void* __restrict__ mask_raw, const float* __restrict__ pb,
    __half* __restrict__ O16)
{
    extern __shared__ __align__(1024) char sm[];
    const int t = threadIdx.x, lane = t & 31, w = t >> 5;
    const int lr = lane & 15, kc = lane >> 4;
    const int group = lane >> 2, t4 = lane & 3;
    const int qbase = blockIdx.x * 64;
    const int h = blockIdx.y;
    const int mode = g_mask_mode;
    const uint32_t smb = smem_u32(sm);

    const unsigned char* m8 = (const unsigned char*)mask_raw;
    const int*   m32 = (const int*)mask_raw;
    const float* mf  = (const float*)mask_raw;

    const __half* kvs[2] = {K, V};
    const float* pbbase = pb + ((size_t)h * SEQ + qbase) * SEQ;

    auto issue_stage = [&](int st, int tile) {
#pragma unroll
        for (int arr = 0; arr < 2; arr++)
#pragma unroll
            for (int i = 0; i < 4; i++) {
                int idx = t + i * 128;
                int r = idx >> 3, c = idx & 7;
                cpa16(smb + st * 16384 + arr * 8192 + sw64(r, c),
                      kvs[arr] + (size_t)(tile * 64 + r) * DMODEL + h * DH + c * 8);
            }
#pragma unroll
        for (int i = 0; i < 8; i++) {
            int c = t + i * 128;
            int r = c >> 4, c16 = c & 15;
            cpa16(smb + 32768 + st * PB_STAGE + r * PB_STRIDE + c16 * 16,
                  pbbase + (size_t)r * SEQ + tile * 64 + c16 * 4);
        }
        asm volatile("cp.async.commit_group;");
    };
    issue_stage(0, 0);

    // ---- Q fragments in registers (a-frag layout, loaded once) ----
    uint32_t qf[4][4];
    {
        const int g = qbase + w * 16 + group;
#pragma unroll
        for (int kk = 0; kk < 4; kk++) {
            const size_t col = (size_t)h * DH + kk * 16 + t4 * 2;
            qf[kk][0] = *(const uint32_t*)&Q[(size_t)g * DMODEL + col];
            qf[kk][1] = *(const uint32_t*)&Q[(size_t)(g + 8) * DMODEL + col];
            qf[kk][2] = *(const uint32_t*)&Q[(size_t)g * DMODEL + col + 8];
            qf[kk][3] = *(const uint32_t*)&Q[(size_t)(g + 8) * DMODEL + col + 8];
        }
    }

    uint32_t aK[4], aV[4];
#pragma unroll
    for (int p = 0; p < 4; p++) aK[p] = smb + sw64(p * 16 + lr, kc);
#pragma unroll
    for (int p = 0; p < 4; p++) aV[p] = smb + 8192 + sw64(p * 16 + lr, kc);

    uint32_t pbOff[2];
#pragma unroll
    for (int r2 = 0; r2 < 2; r2++)
        pbOff[r2] = smb + 32768 +
                    (uint32_t)((w * 16 + group + r2 * 8) * PB_STRIDE + t4 * 8);

    float O[8][4];
    float ds[4] = {0.0f, 0.0f, 0.0f, 0.0f};   // ones-column c-frag = row sums
    float m_i[2] = {-1e30f, -1e30f};
#pragma unroll
    for (int j = 0; j < 8; j++)
#pragma unroll
        for (int r = 0; r < 4; r++) O[j][r] = 0.0f;

#pragma unroll 1
    for (int it = 0; it < 32; it++) {
        if (it < 31) issue_stage((it + 1) & 1, it + 1);

        // ---- prefetch mask bits into 2 bitmask regs ----
        uint32_t okb[2] = {0u, 0u};
#pragma unroll
        for (int r2 = 0; r2 < 2; r2++) {
            const int qrow = qbase + w * 16 + group + r2 * 8;
            const size_t mrow = (size_t)qrow * SEQ + it * 64;
#pragma unroll
            for (int j = 0; j < 8; j++) {
                const int col = j * 8 + t4 * 2;
                uint32_t ok0, ok1;
                if (mode == 0) {
                    uchar2 mv = *(const uchar2*)&m8[mrow + col];
                    ok0 = mv.x ? 1u : 0u; ok1 = mv.y ? 1u : 0u;
                } else if (mode == 1) {
                    int2 mv = *(const int2*)&m32[mrow + col];
                    ok0 = mv.x ? 1u : 0u; ok1 = mv.y ? 1u : 0u;
                } else {
                    float2 mv = *(const float2*)&mf[mrow + col];
                    ok0 = (mv.x != 0.0f) ? 1u : 0u; ok1 = (mv.y != 0.0f) ? 1u : 0u;
                }
                okb[r2] |= (ok0 << (2 * j)) | (ok1 << (2 * j + 1));
            }
        }

        if (it < 31) asm volatile("cp.async.wait_group 1;");
        else         asm volatile("cp.async.wait_group 0;");
        __syncthreads();

        const uint32_t so   = (it & 1) * 16384;
        const uint32_t sopb = (it & 1) * PB_STAGE;

        // ---- S = Q K^T  (single pass) ----
        float S[8][4];
#pragma unroll
        for (int j = 0; j < 8; j++)
#pragma unroll
            for (int r = 0; r < 4; r++) S[j][r] = 0.0f;

#pragma unroll
        for (int kk = 0; kk < 4; kk++) {
            const uint32_t kx = kk * 32;
            uint32_t khf[4][4];
#pragma unroll
            for (int p = 0; p < 4; p++) ldsm4((aK[p] ^ kx) + so, khf[p]);
#pragma unroll
            for (int j = 0; j < 8; j++)
                mma16816(S[j], qf[kk], khf[j >> 1][j & 1], khf[j >> 1][(j & 1) + 2]);
        }

        // ---- bias + mask + online softmax; P emitted as f16x2 via ex2 ----
        uint32_t aP[4][4];
#pragma unroll
        for (int r2 = 0; r2 < 2; r2++) {
            float mx = -1e30f;
#pragma unroll
            for (int j = 0; j < 8; j++) {
                float2 bv;
                asm volatile("ld.shared.v2.f32 {%0,%1}, [%2];"
                    : "=f"(bv.x), "=f"(bv.y)
                    : "r"(pbOff[r2] + sopb + (uint32_t)(j * 32)));
                float s0 = (okb[r2] >> (2 * j)     & 1u) ? S[j][r2 * 2]     + bv.x : -1e30f;
                float s1 = (okb[r2] >> (2 * j + 1) & 1u) ? S[j][r2 * 2 + 1] + bv.y : -1e30f;
                S[j][r2 * 2] = s0; S[j][r2 * 2 + 1] = s1;
                mx = fmaxf(mx, fmaxf(s0, s1));
            }
            mx = fmaxf(mx, __shfl_xor_sync(0xffffffffu, mx, 1));
            mx = fmaxf(mx, __shfl_xor_sync(0xffffffffu, mx, 2));
            float mnew = fmaxf(m_i[r2], mx);
            float corr = __expf(m_i[r2] - mnew);
            m_i[r2] = mnew;
            const float mnl = mnew * LOG2E;
#pragma unroll
            for (int j = 0; j < 8; j++) {
                float t0 = fmaf(S[j][r2 * 2],     LOG2E, -mnl);
                float t1 = fmaf(S[j][r2 * 2 + 1], LOG2E, -mnl);
                aP[j >> 1][(j & 1) * 2 + r2] = ex2_f16x2(pack_f16(t0, t1));
            }
#pragma unroll
            for (int j = 0; j < 8; j++) {
                O[j][r2 * 2]     *= corr;
                O[j][r2 * 2 + 1] *= corr;
            }
            ds[r2 * 2]     *= corr;
            ds[r2 * 2 + 1] *= corr;
        }

        // ---- O += P V, ds += P 1  (single pass) ----
#pragma unroll
        for (int kk = 0; kk < 4; kk++) {
#pragma unroll
            for (int jj = 0; jj < 4; jj++) {
                const uint32_t jx = jj * 32;
                uint32_t vh4[4];
                ldsm4t((aV[kk] ^ jx) + so, vh4);
                mma16816(O[2 * jj],     aP[kk], vh4[0], vh4[1]);
                mma16816(O[2 * jj + 1], aP[kk], vh4[2], vh4[3]);
            }
            mma16816(ds, aP[kk], 0x3C003C00u, 0x3C003C00u);
        }
        __syncthreads();
    }

    // ---- epilogue: normalize by ds (ones-column sums), single fp16 ----
#pragma unroll
    for (int r2 = 0; r2 < 2; r2++) {
        const int qrow = qbase + w * 16 + group + r2 * 8;
        const float inv = 1.0f / ds[r2 * 2];
#pragma unroll
        for (int j = 0; j < 8; j++) {
            const int col = h * DH + j * 8 + t4 * 2;
            *(uint32_t*)&O16[(size_t)qrow * DMODEL + col] =
                pack_f16(O[j][r2 * 2] * inv, O[j][r2 * 2 + 1] * inv);
        }
    }
}

// ---------------------------------------------------------------------------
extern "C" void kernel_launch(void* const* d_in, const int* in_sizes, int n_in,
                              void* d_out, int out_size)
{
    const float* hq   = (const float*)d_in[0];
    const float* hkv  = (const float*)d_in[1];
    const void*  mask = d_in[2];
    const float* pb   = (const float*)d_in[3];
    const float* wq   = (const float*)d_in[4];
    const float* bq   = (const float*)d_in[5];
    const float* wk   = (const float*)d_in[6];
    const float* bk   = (const float*)d_in[7];
    const float* wv   = (const float*)d_in[8];
    const float* bv   = (const float*)d_in[9];
    const float* wo   = (const float*)d_in[10];
    const float* bo   = (const float*)d_in[11];
    float* out = (float*)d_out;

    __half *x16, *y16, *wq16, *wk16, *wv16, *wo16, *qp, *kp, *vp, *ap;
    cudaGetSymbolAddress((void**)&x16, g_x16);
    cudaGetSymbolAddress((void**)&y16, g_y16);
    cudaGetSymbolAddress((void**)&wq16, g_wq16);
    cudaGetSymbolAddress((void**)&wk16, g_wk16);
    cudaGetSymbolAddress((void**)&wv16, g_wv16);
    cudaGetSymbolAddress((void**)&wo16, g_wo16);
    cudaGetSymbolAddress((void**)&qp, g_q);
    cudaGetSymbolAddress((void**)&kp, g_k);
    cudaGetSymbolAddress((void**)&vp, g_v);
    cudaGetSymbolAddress((void**)&ap, g_a);

    cudaFuncSetAttribute(gemm_qkv,
                         cudaFuncAttributeMaxDynamicSharedMemorySize, GEMM_SMEM);
    cudaFuncSetAttribute(gemm_out,
                         cudaFuncAttributeMaxDynamicSharedMemorySize, GEMM_SMEM);
    cudaFuncSetAttribute(attn_mma,
                         cudaFuncAttributeMaxDynamicSharedMemorySize, ATTN_SMEM);

    detect_mask_kernel<<<1, 32>>>((const unsigned char*)mask);

    conv6_f16<<<6 * 2048, 256>>>(hq, hkv, wq, wk, wv, wo,
                                 x16, y16, wq16, wk16, wv16, wo16);

    gemm_qkv<<<dim3(DMODEL / 128, SEQ / 128, 3), 256, GEMM_SMEM>>>(
        x16, y16, wq16, wk16, wv16, bq, bk, bv, qp, kp, vp);

    attn_mma<<<dim3(SEQ / 64, NH), 128, ATTN_SMEM>>>(
        qp, kp, vp, mask, pb, ap);

    gemm_out<<<dim3(DMODEL / 128, SEQ / 128), 256, GEMM_SMEM>>>(
        ap, wo16, bo, out);
}

// round 17
// speedup vs baseline: 6.3307x; 1.2356x over previous
#include <cuda_runtime.h>
#include <cuda_fp16.h>
#include <cstdint>
#include <cstddef>

#define SEQ 2048
#define DMODEL 2048
#define NH 32
#define DH 64

// ---------------------------------------------------------------------------
// Scratch (device globals: allocation-free rule).  All-fp16 data path.
// ---------------------------------------------------------------------------
__device__ __half g_x16[SEQ * DMODEL];   // hq fp16
__device__ __half g_y16[SEQ * DMODEL];   // hkv fp16
__device__ __half g_wq16[SEQ * DMODEL];
__device__ __half g_wk16[SEQ * DMODEL];
__device__ __half g_wv16[SEQ * DMODEL];
__device__ __half g_wo16[SEQ * DMODEL];
__device__ __half g_q [SEQ * DMODEL];    // Q fp16 (pre-scaled 0.125)
__device__ __half g_k [SEQ * DMODEL];    // K fp16
__device__ __half g_v [SEQ * DMODEL];    // V fp16
__device__ __half g_a [SEQ * DMODEL];    // attention out fp16
__device__ unsigned long long g_mpack[SEQ * (SEQ / 64)];  // bit-packed mask
__device__ int g_mask_mode;  // 0=uint8, 1=int32, 2=float32

// ---------------------------------------------------------------------------
__global__ void detect_mask_kernel(const unsigned char* __restrict__ m) {
    if (threadIdx.x == 0) {
        int mx = 0, off = 0;
        for (int i = 0; i < 256; i++) {
            int b = m[i];
            if (b > mx) mx = b;
            if ((i & 3) && b) off = 1;
        }
        g_mask_mode = (mx > 1) ? 2 : (off ? 0 : 1);
    }
}

// ---------------------------------------------------------------------------
// Bit-pack the mask: 64 elements -> one uint64.  65536 words total.
// grid 256 x 256 threads; one word per thread.
// ---------------------------------------------------------------------------
__global__ __launch_bounds__(256) void pack_mask(
    const void* __restrict__ mask_raw, unsigned long long* __restrict__ mp)
{
    const int idx = blockIdx.x * 256 + threadIdx.x;      // word index
    const int mode = g_mask_mode;
    unsigned long long bits = 0ull;
    if (mode == 0) {
        const uint32_t* src = (const uint32_t*)mask_raw + idx * 16;
#pragma unroll
        for (int i = 0; i < 16; i++) {
            uint32_t u = src[i];
#pragma unroll
            for (int b = 0; b < 4; b++)
                if ((u >> (8 * b)) & 0xFFu)
                    bits |= 1ull << (i * 4 + b);
        }
    } else if (mode == 1) {
        const int4* src = (const int4*)mask_raw + idx * 16;
#pragma unroll
        for (int i = 0; i < 16; i++) {
            int4 v = src[i];
            if (v.x) bits |= 1ull << (i * 4 + 0);
            if (v.y) bits |= 1ull << (i * 4 + 1);
            if (v.z) bits |= 1ull << (i * 4 + 2);
            if (v.w) bits |= 1ull << (i * 4 + 3);
        }
    } else {
        const float4* src = (const float4*)mask_raw + idx * 16;
#pragma unroll
        for (int i = 0; i < 16; i++) {
            float4 v = src[i];
            if (v.x != 0.0f) bits |= 1ull << (i * 4 + 0);
            if (v.y != 0.0f) bits |= 1ull << (i * 4 + 1);
            if (v.z != 0.0f) bits |= 1ull << (i * 4 + 2);
            if (v.w != 0.0f) bits |= 1ull << (i * 4 + 3);
        }
    }
    mp[idx] = bits;
}

// ---------------------------------------------------------------------------
// Fused fp32 -> fp16 conversion of all six fp32 sources.
// ---------------------------------------------------------------------------
__global__ __launch_bounds__(256) void conv6_f16(
    const float* __restrict__ s0, const float* __restrict__ s1,
    const float* __restrict__ s2, const float* __restrict__ s3,
    const float* __restrict__ s4, const float* __restrict__ s5,
    __half* __restrict__ d0, __half* __restrict__ d1,
    __half* __restrict__ d2, __half* __restrict__ d3,
    __half* __restrict__ d4, __half* __restrict__ d5)
{
    int sel = blockIdx.x >> 11;
    int b   = blockIdx.x & 2047;
    const float* x = (sel == 0) ? s0 : (sel == 1) ? s1 : (sel == 2) ? s2
                   : (sel == 3) ? s3 : (sel == 4) ? s4 : s5;
    __half* y      = (sel == 0) ? d0 : (sel == 1) ? d1 : (sel == 2) ? d2
                   : (sel == 3) ? d3 : (sel == 4) ? d4 : d5;
    size_t base = ((size_t)b * 256 + threadIdx.x) * 8;
    float4 a = *(const float4*)(x + base);
    float4 c = *(const float4*)(x + base + 4);
    __half2 h2[4];
    h2[0] = __floats2half2_rn(a.x, a.y);
    h2[1] = __floats2half2_rn(a.z, a.w);
    h2[2] = __floats2half2_rn(c.x, c.y);
    h2[3] = __floats2half2_rn(c.z, c.w);
    *(uint4*)(y + base) = *(uint4*)h2;
}

// ---------------------------------------------------------------------------
__device__ __forceinline__ uint32_t smem_u32(const void* p) {
    uint32_t a;
    asm("{ .reg .u64 t; cvta.to.shared.u64 t, %1; cvt.u32.u64 %0, t; }"
        : "=r"(a) : "l"(p));
    return a;
}
__device__ __forceinline__ void ldsm4(uint32_t addr, uint32_t* r) {
    asm volatile("ldmatrix.sync.aligned.m8n8.x4.shared.b16 {%0,%1,%2,%3}, [%4];"
        : "=r"(r[0]), "=r"(r[1]), "=r"(r[2]), "=r"(r[3]) : "r"(addr));
}
__device__ __forceinline__ void ldsm4t(uint32_t addr, uint32_t* r) {
    asm volatile("ldmatrix.sync.aligned.m8n8.x4.trans.shared.b16 {%0,%1,%2,%3}, [%4];"
        : "=r"(r[0]), "=r"(r[1]), "=r"(r[2]), "=r"(r[3]) : "r"(addr));
}
__device__ __forceinline__ void mma16816(float* d, const uint32_t* a,
                                         uint32_t b0, uint32_t b1) {
    asm volatile(
        "mma.sync.aligned.m16n8k16.row.col.f32.f16.f16.f32 "
        "{%0,%1,%2,%3}, {%4,%5,%6,%7}, {%8,%9}, {%0,%1,%2,%3};"
        : "+f"(d[0]), "+f"(d[1]), "+f"(d[2]), "+f"(d[3])
        : "r"(a[0]), "r"(a[1]), "r"(a[2]), "r"(a[3]), "r"(b0), "r"(b1));
}
__device__ __forceinline__ void cpa16(uint32_t s, const void* g) {
    asm volatile("cp.async.cg.shared.global [%0], [%1], 16;" :: "r"(s), "l"(g));
}
__device__ __forceinline__ uint32_t pack_f16(float a, float b) {
    __half2 h = __floats2half2_rn(a, b);
    return *(uint32_t*)&h;
}
__device__ __forceinline__ uint32_t ex2_f16x2(uint32_t t) {
    uint32_t p;
    asm("ex2.approx.f16x2 %0, %1;" : "=r"(p) : "r"(t));
    return p;
}

// 32-col f16 tile (64B rows)
__device__ __forceinline__ uint32_t sw_off(int r, int c) {
    return (uint32_t)(r * 64 + ((c ^ ((r >> 1) & 3)) * 16));
}
// 64-col f16 tile (128B rows)
__device__ __forceinline__ uint32_t sw64(int r, int c) {
    return (uint32_t)(r * 128 + ((c ^ (r & 7)) * 16));
}

// ---------------------------------------------------------------------------
// Shared GEMM body (fp16 1-pass): C = A[M,K] @ B[N,K]^T + bias, *scale.
// Stage layout (16KB): A +0 | B +8192.  3 stages.
// ---------------------------------------------------------------------------
#define GEMM_SMEM (3 * 16384)

__device__ __forceinline__ void gemm_body(
    const __half* __restrict__ A, const __half* __restrict__ B,
    const float* __restrict__ bias, float* __restrict__ Cf,
    __half* __restrict__ Ch, float scale, char* sm)
{
    const int t    = threadIdx.x;
    const int bm   = blockIdx.y * 128;
    const int bn   = blockIdx.x * 128;
    const int lane = t & 31;
    const int w    = t >> 5;
    const int wm   = (w & 1) * 64;
    const int wn   = (w >> 1) * 32;
    const int lr   = lane & 15;
    const int kc   = lane >> 4;
    const uint32_t smb = smem_u32(sm);

    float d[4][4][4];
#pragma unroll
    for (int i = 0; i < 4; i++)
#pragma unroll
        for (int j = 0; j < 4; j++)
#pragma unroll
            for (int r = 0; r < 4; r++) d[i][j][r] = 0.0f;

    const int r0 = t >> 2, c0 = t & 3;
    const int r1 = r0 + 64;
    const __half* srcs[2] = {A, B};
    const __half* sp[4];
    uint32_t dst[4];
#pragma unroll
    for (int arr = 0; arr < 2; arr++) {
        const int rb = (arr == 0) ? bm : bn;
        sp[2 * arr]     = srcs[arr] + (size_t)(rb + r0) * DMODEL + c0 * 8;
        sp[2 * arr + 1] = srcs[arr] + (size_t)(rb + r1) * DMODEL + c0 * 8;
        dst[2 * arr]     = smb + arr * 8192 + sw_off(r0, c0);
        dst[2 * arr + 1] = smb + arr * 8192 + sw_off(r1, c0);
    }
    auto issue = [&](uint32_t so2, int kt) {
#pragma unroll
        for (int i = 0; i < 4; i++) cpa16(dst[i] + so2, sp[i] + kt * 32);
        asm volatile("cp.async.commit_group;");
    };

    uint32_t aA[4], aB[2];
#pragma unroll
    for (int i = 0; i < 4; i++) aA[i] = smb + sw_off(wm + i * 16 + lr, kc);
#pragma unroll
    for (int p = 0; p < 2; p++) aB[p] = smb + 8192 + sw_off(wn + p * 16 + lr, kc);

    issue(0, 0);
    issue(16384, 1);

    uint32_t so = 0, si = 32768;
#pragma unroll 1
    for (int kt = 0; kt < 64; kt++) {
        if (kt < 63) asm volatile("cp.async.wait_group 1;");
        else         asm volatile("cp.async.wait_group 0;");
        __syncthreads();
        if (kt + 2 < 64) issue(si, kt + 2);

#pragma unroll
        for (int kk = 0; kk < 2; kk++) {
            const uint32_t kx = kk * 32;
            uint32_t af[4][4], bf[2][4];
#pragma unroll
            for (int i = 0; i < 4; i++) ldsm4((aA[i] ^ kx) + so, af[i]);
#pragma unroll
            for (int p = 0; p < 2; p++) ldsm4((aB[p] ^ kx) + so, bf[p]);
#pragma unroll
            for (int i = 0; i < 4; i++)
#pragma unroll
                for (int j = 0; j < 4; j++)
                    mma16816(d[i][j], af[i], bf[j >> 1][j & 1], bf[j >> 1][(j & 1) + 2]);
        }
        so = (so == 32768) ? 0 : so + 16384;
        si = (si == 32768) ? 0 : si + 16384;
    }

    const int tg = lane >> 2, t4 = lane & 3;
#pragma unroll
    for (int i = 0; i < 4; i++) {
        const int row = bm + wm + i * 16 + tg;
#pragma unroll
        for (int j = 0; j < 4; j++) {
            const int col = bn + wn + j * 8 + t4 * 2;
            const float b0 = bias[col], b1 = bias[col + 1];
            float v0 = (d[i][j][0] + b0) * scale, v1 = (d[i][j][1] + b1) * scale;
            float v2 = (d[i][j][2] + b0) * scale, v3 = (d[i][j][3] + b1) * scale;
            if (Cf) {
                *(float2*)&Cf[(size_t)row * DMODEL + col] = make_float2(v0, v1);
                *(float2*)&Cf[(size_t)(row + 8) * DMODEL + col] = make_float2(v2, v3);
            } else {
                *(uint32_t*)&Ch[(size_t)row * DMODEL + col] = pack_f16(v0, v1);
                *(uint32_t*)&Ch[(size_t)(row + 8) * DMODEL + col] = pack_f16(v2, v3);
            }
        }
    }
}

// Merged Q/K/V projection: grid (16,16,3); z selects operands.
__global__ __launch_bounds__(256, 2) void gemm_qkv(
    const __half* __restrict__ x16, const __half* __restrict__ y16,
    const __half* __restrict__ wq, const __half* __restrict__ wk,
    const __half* __restrict__ wv,
    const float* __restrict__ bq, const float* __restrict__ bk,
    const float* __restrict__ bv,
    __half* __restrict__ q, __half* __restrict__ k, __half* __restrict__ v)
{
    extern __shared__ __align__(1024) char sm[];
    const int z = blockIdx.z;
    const __half* A  = (z == 0) ? x16 : y16;
    const __half* B  = (z == 0) ? wq : (z == 1) ? wk : wv;
    const float* bias = (z == 0) ? bq : (z == 1) ? bk : bv;
    __half* C = (z == 0) ? q : (z == 1) ? k : v;
    const float scale = (z == 0) ? 0.125f : 1.0f;
    gemm_body(A, B, bias, nullptr, C, scale, sm);
}

// Output projection: fp32 out.
__global__ __launch_bounds__(256, 2) void gemm_out(
    const __half* __restrict__ A, const __half* __restrict__ B,
    const float* __restrict__ bias, float* __restrict__ Cf)
{
    extern __shared__ __align__(1024) char sm[];
    gemm_body(A, B, bias, Cf, nullptr, 1.0f, sm);
}

// ---------------------------------------------------------------------------
// Tensor-core flash attention.
//  - Q fp16 in registers (1-pass QK^T); P fp16 via ex2.approx.f16x2.
//  - Row sums via ones-column PV mma (c-frag ds).
//  - pb staged via cp.async (2 stages).
//  - Mask: ONE bit-packed uint64 LDG per row-half per iteration (g_mpack).
// smem: KV 2 x 16KB at +0 (K +0 | V +8192); pb 2 x 17408B at +32768.
// ---------------------------------------------------------------------------
#define PB_STRIDE 272
#define PB_STAGE  (64 * PB_STRIDE)      // 17408
#define ATTN_SMEM (32768 + 2 * PB_STAGE)
#define LOG2E 1.4426950408889634f

__global__ __launch_bounds__(128, 3) void attn_mma(
    const __half* __restrict__ Q,
    const __half* __restrict__ K, const __half* __restrict__ V,
    const unsigned long long* __restrict__ MP, const float* __restrict__ pb,
    __half* __restrict__ O16)
{
    extern __shared__ __align__(1024) char sm[];
    const int t = threadIdx.x, lane = t & 31, w = t >> 5;
    const int lr = lane & 15, kc = lane >> 4;
    const int group = lane >> 2, t4 = lane & 3;
    const int qbase = blockIdx.x * 64;
    const int h = blockIdx.y;
    const uint32_t smb = smem_u32(sm);

    const __half* kvs[2] = {K, V};
    const float* pbbase = pb + ((size_t)h * SEQ + qbase) * SEQ;

    auto issue_stage = [&](int st, int tile) {
#pragma unroll
        for (int arr = 0; arr < 2; arr++)
#pragma unroll
            for (int i = 0; i < 4; i++) {
                int idx = t + i * 128;
                int r = idx >> 3, c = idx & 7;
                cpa16(smb + st * 16384 + arr * 8192 + sw64(r, c),
                      kvs[arr] + (size_t)(tile * 64 + r) * DMODEL + h * DH + c * 8);
            }
#pragma unroll
        for (int i = 0; i < 8; i++) {
            int c = t + i * 128;
            int r = c >> 4, c16 = c & 15;
            cpa16(smb + 32768 + st * PB_STAGE + r * PB_STRIDE + c16 * 16,
                  pbbase + (size_t)r * SEQ + tile * 64 + c16 * 4);
        }
        asm volatile("cp.async.commit_group;");
    };
    issue_stage(0, 0);

    // ---- Q fragments in registers (a-frag layout, loaded once) ----
    uint32_t qf[4][4];
    {
        const int g = qbase + w * 16 + group;
#pragma unroll
        for (int kk = 0; kk < 4; kk++) {
            const size_t col = (size_t)h * DH + kk * 16 + t4 * 2;
            qf[kk][0] = *(const uint32_t*)&Q[(size_t)g * DMODEL + col];
            qf[kk][1] = *(const uint32_t*)&Q[(size_t)(g + 8) * DMODEL + col];
            qf[kk][2] = *(const uint32_t*)&Q[(size_t)g * DMODEL + col + 8];
            qf[kk][3] = *(const uint32_t*)&Q[(size_t)(g + 8) * DMODEL + col + 8];
        }
    }

    uint32_t aK[4], aV[4];
#pragma unroll
    for (int p = 0; p < 4; p++) aK[p] = smb + sw64(p * 16 + lr, kc);
#pragma unroll
    for (int p = 0; p < 4; p++) aV[p] = smb + 8192 + sw64(p * 16 + lr, kc);

    uint32_t pbOff[2];
#pragma unroll
    for (int r2 = 0; r2 < 2; r2++)
        pbOff[r2] = smb + 32768 +
                    (uint32_t)((w * 16 + group + r2 * 8) * PB_STRIDE + t4 * 8);

    // mask word pointers (row-half 0 / 1), advanced by 1 word per iteration
    const unsigned long long* mpr[2];
#pragma unroll
    for (int r2 = 0; r2 < 2; r2++)
        mpr[r2] = MP + (size_t)(qbase + w * 16 + group + r2 * 8) * (SEQ / 64);

    float O[8][4];
    float ds[4] = {0.0f, 0.0f, 0.0f, 0.0f};   // ones-column c-frag = row sums
    float m_i[2] = {-1e30f, -1e30f};
#pragma unroll
    for (int j = 0; j < 8; j++)
#pragma unroll
        for (int r = 0; r < 4; r++) O[j][r] = 0.0f;

#pragma unroll 1
    for (int it = 0; it < 32; it++) {
        if (it < 31) issue_stage((it + 1) & 1, it + 1);

        // ---- mask words for this iteration: 2 x LDG.64 ----
        const unsigned long long wb0 = mpr[0][it];
        const unsigned long long wb1 = mpr[1][it];

        if (it < 31) asm volatile("cp.async.wait_group 1;");
        else         asm volatile("cp.async.wait_group 0;");
        __syncthreads();

        const uint32_t so   = (it & 1) * 16384;
        const uint32_t sopb = (it & 1) * PB_STAGE;

        // ---- S = Q K^T  (single pass) ----
        float S[8][4];
#pragma unroll
        for (int j = 0; j < 8; j++)
#pragma unroll
            for (int r = 0; r < 4; r++) S[j][r] = 0.0f;

#pragma unroll
        for (int kk = 0; kk < 4; kk++) {
            const uint32_t kx = kk * 32;
            uint32_t khf[4][4];
#pragma unroll
            for (int p = 0; p < 4; p++) ldsm4((aK[p] ^ kx) + so, khf[p]);
#pragma unroll
            for (int j = 0; j < 8; j++)
                mma16816(S[j], qf[kk], khf[j >> 1][j & 1], khf[j >> 1][(j & 1) + 2]);
        }

        // ---- bias + mask bits + online softmax; P via ex2.f16x2 ----
        uint32_t aP[4][4];
#pragma unroll
        for (int r2 = 0; r2 < 2; r2++) {
            const unsigned long long wb = r2 ? wb1 : wb0;
            float mx = -1e30f;
#pragma unroll
            for (int j = 0; j < 8; j++) {
                float2 bv;
                asm volatile("ld.shared.v2.f32 {%0,%1}, [%2];"
                    : "=f"(bv.x), "=f"(bv.y)
                    : "r"(pbOff[r2] + sopb + (uint32_t)(j * 32)));
                const uint32_t sh = (uint32_t)(j * 8 + t4 * 2);
                float s0 = ((wb >> sh) & 1ull)       ? S[j][r2 * 2]     + bv.x : -1e30f;
                float s1 = ((wb >> (sh + 1)) & 1ull) ? S[j][r2 * 2 + 1] + bv.y : -1e30f;
                S[j][r2 * 2] = s0; S[j][r2 * 2 + 1] = s1;
                mx = fmaxf(mx, fmaxf(s0, s1));
            }
            mx = fmaxf(mx, __shfl_xor_sync(0xffffffffu, mx, 1));
            mx = fmaxf(mx, __shfl_xor_sync(0xffffffffu, mx, 2));
            float mnew = fmaxf(m_i[r2], mx);
            float corr = __expf(m_i[r2] - mnew);
            m_i[r2] = mnew;
            const float mnl = mnew * LOG2E;
#pragma unroll
            for (int j = 0; j < 8; j++) {
                float t0 = fmaf(S[j][r2 * 2],     LOG2E, -mnl);
                float t1 = fmaf(S[j][r2 * 2 + 1], LOG2E, -mnl);
                aP[j >> 1][(j & 1) * 2 + r2] = ex2_f16x2(pack_f16(t0, t1));
            }
#pragma unroll
            for (int j = 0; j < 8; j++) {
                O[j][r2 * 2]     *= corr;
                O[j][r2 * 2 + 1] *= corr;
            }
            ds[r2 * 2]     *= corr;
            ds[r2 * 2 + 1] *= corr;
        }

        // ---- O += P V, ds += P 1  (single pass) ----
#pragma unroll
        for (int kk = 0; kk < 4; kk++) {
#pragma unroll
            for (int jj = 0; jj < 4; jj++) {
                const uint32_t jx = jj * 32;
                uint32_t vh4[4];
                ldsm4t((aV[kk] ^ jx) + so, vh4);
                mma16816(O[2 * jj],     aP[kk], vh4[0], vh4[1]);
                mma16816(O[2 * jj + 1], aP[kk], vh4[2], vh4[3]);
            }
            mma16816(ds, aP[kk], 0x3C003C00u, 0x3C003C00u);
        }
        __syncthreads();
    }

    // ---- epilogue: normalize by ds, single fp16 ----
#pragma unroll
    for (int r2 = 0; r2 < 2; r2++) {
        const int qrow = qbase + w * 16 + group + r2 * 8;
        const float inv = 1.0f / ds[r2 * 2];
#pragma unroll
        for (int j = 0; j < 8; j++) {
            const int col = h * DH + j * 8 + t4 * 2;
            *(uint32_t*)&O16[(size_t)qrow * DMODEL + col] =
                pack_f16(O[j][r2 * 2] * inv, O[j][r2 * 2 + 1] * inv);
        }
    }
}

// ---------------------------------------------------------------------------
extern "C" void kernel_launch(void* const* d_in, const int* in_sizes, int n_in,
                              void* d_out, int out_size)
{
    const float* hq   = (const float*)d_in[0];
    const float* hkv  = (const float*)d_in[1];
    const void*  mask = d_in[2];
    const float* pb   = (const float*)d_in[3];
    const float* wq   = (const float*)d_in[4];
    const float* bq   = (const float*)d_in[5];
    const float* wk   = (const float*)d_in[6];
    const float* bk   = (const float*)d_in[7];
    const float* wv   = (const float*)d_in[8];
    const float* bv   = (const float*)d_in[9];
    const float* wo   = (const float*)d_in[10];
    const float* bo   = (const float*)d_in[11];
    float* out = (float*)d_out;

    __half *x16, *y16, *wq16, *wk16, *wv16, *wo16, *qp, *kp, *vp, *ap;
    unsigned long long* mp;
    cudaGetSymbolAddress((void**)&x16, g_x16);
    cudaGetSymbolAddress((void**)&y16, g_y16);
    cudaGetSymbolAddress((void**)&wq16, g_wq16);
    cudaGetSymbolAddress((void**)&wk16, g_wk16);
    cudaGetSymbolAddress((void**)&wv16, g_wv16);
    cudaGetSymbolAddress((void**)&wo16, g_wo16);
    cudaGetSymbolAddress((void**)&qp, g_q);
    cudaGetSymbolAddress((void**)&kp, g_k);
    cudaGetSymbolAddress((void**)&vp, g_v);
    cudaGetSymbolAddress((void**)&ap, g_a);
    cudaGetSymbolAddress((void**)&mp, g_mpack);

    cudaFuncSetAttribute(gemm_qkv,
                         cudaFuncAttributeMaxDynamicSharedMemorySize, GEMM_SMEM);
    cudaFuncSetAttribute(gemm_out,
                         cudaFuncAttributeMaxDynamicSharedMemorySize, GEMM_SMEM);
    cudaFuncSetAttribute(attn_mma,
                         cudaFuncAttributeMaxDynamicSharedMemorySize, ATTN_SMEM);

    detect_mask_kernel<<<1, 32>>>((const unsigned char*)mask);
    pack_mask<<<256, 256>>>(mask, mp);

    conv6_f16<<<6 * 2048, 256>>>(hq, hkv, wq, wk, wv, wo,
                                 x16, y16, wq16, wk16, wv16, wo16);

    gemm_qkv<<<dim3(DMODEL / 128, SEQ / 128, 3), 256, GEMM_SMEM>>>(
        x16, y16, wq16, wk16, wv16, bq, bk, bv, qp, kp, vp);

    attn_mma<<<dim3(SEQ / 64, NH), 128, ATTN_SMEM>>>(
        qp, kp, vp, mp, pb, ap);

    gemm_out<<<dim3(DMODEL / 128, SEQ / 128), 256, GEMM_SMEM>>>(
        ap, wo16, bo, out);
}